// round 11
// baseline (speedup 1.0000x reference)
#include <cuda_runtime.h>
#include <cuda_bf16.h>
#include <cstdint>

// ===========================================================================
// B=4, C_IN=256, C=128, H=W=64, HW=4096. out [4,128,128,128] f32.
// ALL dense ops on mma.sync bf16 HMMA, 2-term split.
// Operands stored 2-segment [hi|lo]; GEMM walks 3-segment schedule:
//   (Ahi,Bhi) + (Alo,Bhi) + (Ahi,Blo)   (err ~2^-18)
// Convs = per-tap shifted GEMMs (cp.async zfill). Split-operand production
// fused into GEMM/conv epilogues (smem transpose). 1 barrier per k-chunk.
// ===========================================================================

#define F_RES1 0LL
#define F_RES2 (F_RES1 + 2097152)
#define F_SIM  (F_RES2 + 2097152)
#define F_ABSD (F_SIM  + 16384)
#define F_SIMP (F_ABSD + 2097152)
#define F_R    (F_SIMP + 524288)
#define F_DIF  (F_R    + 2097152)
#define F_INC  (F_DIF  + 2097152)
#define F_LOG  (F_INC  + 2097152)      /* logitsT [B,4096,1024] */
#define F_FUSE (F_LOG  + 16777216)
#define F_TOTAL (F_FUSE + 2097152)

__device__ float g_scratch[F_TOTAL];

// bf16 scratch element offsets (2-segment layouts)
#define W_T1W2   0LL         /* [128,512]       */
#define W_T2W2   65536LL
#define W_RESW2  131072LL
#define W_FUW2   196608LL
#define W_DFUW2  262144LL    /* [128,256]       */
#define W_B0T    294912LL    /* [9][64][256]    */
#define W_B1T    442368LL    /* [25][64][256]   */
#define W_BR1T   851968LL    /* [9][128][256]   */
#define W_BR2T   1146880LL   /* [25][128][256]  */
#define G_ATTN2  1966080LL   /* [4,1024,256]    */
#define G_INCT2  3014656LL   /* [4,4096,256]    */
#define G_ATTNT2 7208960LL   /* [4,128,2048]    */
#define G_AT2    8257536LL   /* [4,4096,2048]   */
#define G_T3A    41811968LL  /* [4,4096,512]    */
#define G_T3B    50200576LL  /* [4,4096,512]    */
#define G_RB2    58589184LL  /* [4,4096,256]    */
#define G_DIF2   62783488LL  /* [4,4096,256]    */
#define G_BB2    66977792LL  /* [4,4096,256]    */
#define G_TOTAL  71172096LL

__device__ __align__(256) __nv_bfloat16 g_bf[G_TOTAL];

// ------------------------------ helpers ------------------------------------
__device__ __forceinline__ uint32_t smem_u32(const void* p) {
    uint32_t a;
    asm("{ .reg .u64 t; cvta.to.shared.u64 t, %1; cvt.u32.u64 %0, t; }"
        : "=r"(a) : "l"(p));
    return a;
}
__device__ __forceinline__ void bsplit(float x, __nv_bfloat16& h, __nv_bfloat16& l) {
    h = __float2bfloat16(x);
    l = __float2bfloat16(x - __bfloat162float(h));
}
#define CP_ASYNC(dst, src) asm volatile( \
    "cp.async.cg.shared.global [%0], [%1], 16;" :: "r"(dst), "l"(src))
#define CP_ASYNC_Z(dst, src, sz) asm volatile( \
    "cp.async.cg.shared.global [%0], [%1], 16, %2;" :: "r"(dst), "l"(src), "r"(sz))
#define CP_COMMIT() asm volatile("cp.async.commit_group;" ::: "memory")
#define CP_WAIT1()  asm volatile("cp.async.wait_group 1;" ::: "memory")
#define CP_WAIT0()  asm volatile("cp.async.wait_group 0;" ::: "memory")
#define LDM_X4(r0, r1, r2, r3, a) asm volatile( \
    "ldmatrix.sync.aligned.m8n8.x4.shared.b16 {%0,%1,%2,%3}, [%4];" \
    : "=r"(r0), "=r"(r1), "=r"(r2), "=r"(r3) : "r"(a))
#define MMA16816(d, a, bfr) asm volatile( \
    "mma.sync.aligned.m16n8k16.row.col.f32.bf16.bf16.f32 " \
    "{%0,%1,%2,%3}, {%4,%5,%6,%7}, {%8,%9}, {%0,%1,%2,%3};" \
    : "+f"((d)[0]), "+f"((d)[1]), "+f"((d)[2]), "+f"((d)[3]) \
    : "r"((a)[0]), "r"((a)[1]), "r"((a)[2]), "r"((a)[3]), \
      "r"((bfr)[0]), "r"((bfr)[1]))

// ===========================================================================
// hmma_gemm: 128x128 tile, 8 warps (32m x 64n), chunk k=32, 3-stage cp.async.
// A2 [Mtot, 2*Kcore], B2 [Ntot, 2*Kcore] bf16 (hi|lo); 3-segment schedule.
// Optional epilogue outputs: C (f32) and/or dsplit [pix][2*Rtot] bf16 (hi|lo)
// at channel offset choff (requires M tile == full 128-channel block, grid.y==1
// for dsplit users). dyn smem = 66048.
// ===========================================================================
__global__ void __launch_bounds__(256) hmma_gemm(
    const __nv_bfloat16* __restrict__ A2, const __nv_bfloat16* __restrict__ B2,
    float* __restrict__ C,
    const float* __restrict__ bias, const float* __restrict__ scale,
    const float* __restrict__ off, const float* __restrict__ resid,
    int Kcore, int Ncols,
    long long Abs, long long Bbs, long long Cbs, long long Rbs,
    __nv_bfloat16* __restrict__ dsplit, long long Dbs, int Rtot, int choff)
{
    extern __shared__ __align__(16) char smbuf[];
    const uint32_t sA = smem_u32(smbuf);          // 3 stages x 10240
    const uint32_t sB = sA + 30720;               // 3 stages x 10240
    const int t = threadIdx.x, lane = t & 31, wid = t >> 5;
    const int wm = wid & 3, wn = wid >> 2;
    const int b  = blockIdx.z;
    const int m0 = blockIdx.y * 128;
    const int n0 = blockIdx.x * 128;
    const int Kp = 2 * Kcore;
    const __nv_bfloat16* Ab = A2 + (long long)b * Abs + (long long)m0 * Kp;
    const __nv_bfloat16* Bb = B2 + (long long)b * Bbs + (long long)n0 * Kp;

    float acc[2][8][4];
#pragma unroll
    for (int i = 0; i < 2; i++)
#pragma unroll
        for (int j = 0; j < 8; j++)
#pragma unroll
            for (int r = 0; r < 4; r++) acc[i][j][r] = 0.f;

    const int nchseg = Kcore >> 5;
    auto ldch = [&](int gc) {
        const int seg = (gc >= nchseg) + (gc >= 2 * nchseg);
        const int cc  = gc - seg * nchseg;
        const int aco = (seg == 1 ? Kcore : 0) + cc * 32;
        const int bco = (seg == 2 ? Kcore : 0) + cc * 32;
        const uint32_t ao = sA + (gc % 3) * 10240;
        const uint32_t bo = sB + (gc % 3) * 10240;
#pragma unroll
        for (int r = 0; r < 2; r++) {
            int f = t + 256 * r, row = f >> 2, kq = f & 3;
            CP_ASYNC(ao + (uint32_t)(row * 80 + kq * 16),
                     Ab + (long long)row * Kp + aco + kq * 8);
            CP_ASYNC(bo + (uint32_t)(row * 80 + kq * 16),
                     Bb + (long long)row * Kp + bco + kq * 8);
        }
        CP_COMMIT();
    };

    const int NC = 3 * nchseg;
    ldch(0);
    ldch(1);
    for (int gc = 0; gc < NC; gc++) {
        if (gc + 1 < NC) CP_WAIT1(); else CP_WAIT0();
        __syncthreads();
        if (gc + 2 < NC) ldch(gc + 2);
        const uint32_t ao = sA + (gc % 3) * 10240;
        const uint32_t bo = sB + (gc % 3) * 10240;
#pragma unroll
        for (int ks = 0; ks < 2; ks++) {
            const int kb = ks * 16;
            uint32_t af[2][4];
#pragma unroll
            for (int i = 0; i < 2; i++) {
                int row = wm * 32 + i * 16 + (lane & 7) + ((lane >> 3) & 1) * 8;
                int col = kb + ((lane >> 4) & 1) * 8;
                LDM_X4(af[i][0], af[i][1], af[i][2], af[i][3],
                       ao + (uint32_t)(row * 80 + col * 2));
            }
            uint32_t bfr[8][2];
#pragma unroll
            for (int jp = 0; jp < 4; jp++) {
                int n = wn * 64 + jp * 16 + (lane & 7) + ((lane >> 4) & 1) * 8;
                int k = kb + ((lane >> 3) & 1) * 8;
                LDM_X4(bfr[2 * jp][0], bfr[2 * jp][1],
                       bfr[2 * jp + 1][0], bfr[2 * jp + 1][1],
                       bo + (uint32_t)(n * 80 + k * 2));
            }
#pragma unroll
            for (int i = 0; i < 2; i++)
#pragma unroll
                for (int j = 0; j < 8; j++)
                    MMA16816(acc[i][j], af[i], bfr[j]);
        }
        // no trailing barrier: next iter's top barrier orders stage reuse
    }

    float* Cb = C ? C + (long long)b * Cbs : nullptr;
    const float* Rb = resid ? resid + (long long)b * Rbs : nullptr;
    float* tr = (float*)smbuf;   // [128][129] f32, reuses stages
    if (dsplit) __syncthreads();
#pragma unroll
    for (int i = 0; i < 2; i++)
#pragma unroll
        for (int h = 0; h < 2; h++) {
            int ml = wm * 32 + i * 16 + (lane >> 2) + h * 8;
            int m = m0 + ml;
            float bi = bias  ? bias[m]  : 0.f;
            float sc = scale ? scale[m] : 1.f;
            float ofv = off  ? off[m]   : 0.f;
            float* crow = Cb ? Cb + (long long)m * Ncols : nullptr;
            const float* rrow = Rb ? Rb + (long long)m * Ncols : nullptr;
#pragma unroll
            for (int j = 0; j < 8; j++) {
                int cl = wn * 64 + j * 8 + (lane & 3) * 2;
                int col = n0 + cl;
                float2 v = make_float2(acc[i][j][h * 2 + 0] + bi,
                                       acc[i][j][h * 2 + 1] + bi);
                if (scale) {
                    v.x = fmaxf(v.x, 0.f) * sc + ofv;
                    v.y = fmaxf(v.y, 0.f) * sc + ofv;
                }
                if (rrow) {
                    float2 rv = *(const float2*)(rrow + col);
                    v.x += rv.x; v.y += rv.y;
                }
                if (crow) *(float2*)(crow + col) = v;
                if (dsplit) {
                    tr[ml * 129 + cl]     = v.x;
                    tr[ml * 129 + cl + 1] = v.y;
                }
            }
        }
    if (dsplit) {
        __syncthreads();
        const int p = t >> 1, side = t & 1;
        __nv_bfloat16* drow = dsplit + (long long)b * Dbs
                            + (long long)(n0 + p) * (2 * Rtot) + choff;
#pragma unroll 8
        for (int q = 0; q < 64; q++) {
            int ch = side * 64 + q;
            float x = tr[ch * 129 + p];
            __nv_bfloat16 hh, ll; bsplit(x, hh, ll);
            drow[ch] = hh; drow[Rtot + ch] = ll;
        }
    }
}

// ===========================================================================
// hconv_tap: conv KSxKS (pad KS/2) as per-tap shifted GEMMs, Kcore=128/tap.
// W2t [tap][MT][256] (hi|lo); Bsplit [B][4096][256] (hi|lo).
// Optional epilogue outputs: out (f32, [b][ch][4096]) and/or dsplit.
// ===========================================================================
template <int KS, int MT>
__global__ void __launch_bounds__(256) hconv_tap(
    const __nv_bfloat16* __restrict__ W2t, const __nv_bfloat16* __restrict__ Bsplit,
    float* __restrict__ out,
    const float* __restrict__ bias, const float* __restrict__ scale,
    const float* __restrict__ off, long long out_bstride,
    __nv_bfloat16* __restrict__ dsplit, long long Dbs, int Rtot, int choff)
{
    constexpr int P    = KS / 2;
    constexpr int TAPS = KS * KS;
    constexpr int NC   = TAPS * 12;
    constexpr int WM_N = MT / 32;
    constexpr int WN_N = 8 / WM_N;
    constexpr int NJ   = 128 / (WN_N * 8);
    constexpr int ASTG = MT * 80;
    constexpr int CHT  = MT / 2;      // channels per thread in split writer
    extern __shared__ __align__(16) char smbuf[];
    const uint32_t sA = smem_u32(smbuf);
    const uint32_t sB = sA + 3 * ASTG;
    const int t = threadIdx.x, lane = t & 31, wid = t >> 5;
    const int wm = wid % WM_N, wn = wid / WM_N;
    const int b  = blockIdx.z;
    const int n0 = blockIdx.x * 128;
    const __nv_bfloat16* Bb = Bsplit + (long long)b * (4096LL * 256);

    float acc[2][NJ][4];
#pragma unroll
    for (int i = 0; i < 2; i++)
#pragma unroll
        for (int j = 0; j < NJ; j++)
#pragma unroll
            for (int r = 0; r < 4; r++) acc[i][j][r] = 0.f;

    auto ldch = [&](int gc) {
        const int tap = gc / 12;
        const int r12 = gc - tap * 12;
        const int seg = r12 >> 2;
        const int cc  = r12 & 3;
        const int aco = (seg == 1 ? 128 : 0) + cc * 32;
        const int bco = (seg == 2 ? 128 : 0) + cc * 32;
        const int dy  = tap / KS - P, dx = tap - (tap / KS) * KS - P;
        const int shift = dy * 64 + dx;
        const uint32_t ao = sA + (gc % 3) * ASTG;
        const uint32_t bo = sB + (gc % 3) * 10240;
#pragma unroll
        for (int r = 0; r < MT / 64; r++) {
            int f = t + 256 * r, row = f >> 2, kq = f & 3;
            CP_ASYNC(ao + (uint32_t)(row * 80 + kq * 16),
                     W2t + (long long)tap * (MT * 256) + (long long)row * 256
                         + aco + kq * 8);
        }
#pragma unroll
        for (int r = 0; r < 2; r++) {
            int f = t + 256 * r, row = f >> 2, kq = f & 3;
            int gpix = n0 + row;
            int y = gpix >> 6, x = gpix & 63;
            bool ok = ((unsigned)(y + dy) < 64u) && ((unsigned)(x + dx) < 64u);
            int spix = ok ? (gpix + shift) : 0;
            uint32_t sz = ok ? 16u : 0u;
            CP_ASYNC_Z(bo + (uint32_t)(row * 80 + kq * 16),
                       Bb + (long long)spix * 256 + bco + kq * 8, sz);
        }
        CP_COMMIT();
    };

    ldch(0);
    ldch(1);
    for (int gc = 0; gc < NC; gc++) {
        if (gc + 1 < NC) CP_WAIT1(); else CP_WAIT0();
        __syncthreads();
        if (gc + 2 < NC) ldch(gc + 2);
        const uint32_t ao = sA + (gc % 3) * ASTG;
        const uint32_t bo = sB + (gc % 3) * 10240;
#pragma unroll
        for (int ks = 0; ks < 2; ks++) {
            const int kb = ks * 16;
            uint32_t af[2][4];
#pragma unroll
            for (int i = 0; i < 2; i++) {
                int row = wm * 32 + i * 16 + (lane & 7) + ((lane >> 3) & 1) * 8;
                int col = kb + ((lane >> 4) & 1) * 8;
                LDM_X4(af[i][0], af[i][1], af[i][2], af[i][3],
                       ao + (uint32_t)(row * 80 + col * 2));
            }
            uint32_t bfr[NJ][2];
#pragma unroll
            for (int jp = 0; jp < NJ / 2; jp++) {
                int n = wn * (NJ * 8) + jp * 16 + (lane & 7) + ((lane >> 4) & 1) * 8;
                int k = kb + ((lane >> 3) & 1) * 8;
                LDM_X4(bfr[2 * jp][0], bfr[2 * jp][1],
                       bfr[2 * jp + 1][0], bfr[2 * jp + 1][1],
                       bo + (uint32_t)(n * 80 + k * 2));
            }
#pragma unroll
            for (int i = 0; i < 2; i++)
#pragma unroll
                for (int j = 0; j < NJ; j++)
                    MMA16816(acc[i][j], af[i], bfr[j]);
        }
    }

    float* Ob = out ? out + (long long)b * out_bstride : nullptr;
    float* tr = (float*)smbuf;   // [MT][129]
    if (dsplit) __syncthreads();
#pragma unroll
    for (int i = 0; i < 2; i++)
#pragma unroll
        for (int h = 0; h < 2; h++) {
            int ml = wm * 32 + i * 16 + (lane >> 2) + h * 8;
            float bi = bias[ml];
            float sc = scale ? scale[ml] : 1.f;
            float ofv = off ? off[ml] : 0.f;
            float* crow = Ob ? Ob + (long long)ml * 4096 : nullptr;
#pragma unroll
            for (int j = 0; j < NJ; j++) {
                int cl = wn * (NJ * 8) + j * 8 + (lane & 3) * 2;
                int col = n0 + cl;
                float2 v = make_float2(acc[i][j][h * 2 + 0] + bi,
                                       acc[i][j][h * 2 + 1] + bi);
                if (scale) {
                    v.x = fmaxf(v.x, 0.f) * sc + ofv;
                    v.y = fmaxf(v.y, 0.f) * sc + ofv;
                }
                if (crow) *(float2*)(crow + col) = v;
                if (dsplit) {
                    tr[ml * 129 + cl]     = v.x;
                    tr[ml * 129 + cl + 1] = v.y;
                }
            }
        }
    if (dsplit) {
        __syncthreads();
        const int p = t >> 1, side = t & 1;
        __nv_bfloat16* drow = dsplit + (long long)b * Dbs
                            + (long long)(n0 + p) * (2 * Rtot) + choff;
#pragma unroll 8
        for (int q = 0; q < CHT; q++) {
            int ch = side * CHT + q;
            float x = tr[ch * 129 + p];
            __nv_bfloat16 hh, ll; bsplit(x, hh, ll);
            drow[ch] = hh; drow[Rtot + ch] = ll;
        }
    }
}

// ===========================================================================
// prep kernels (all 2-segment [hi|lo])
// ===========================================================================
__global__ void wsplit5_k(const float* s0, const float* s1, const float* s2,
                          const float* s3, const float* s4,
                          __nv_bfloat16* d0, __nv_bfloat16* d1, __nv_bfloat16* d2,
                          __nv_bfloat16* d3, __nv_bfloat16* d4)
{
    const int seg = blockIdx.y;
    const float* src; __nv_bfloat16* dst; int K, total;
    switch (seg) {
        case 0: src = s0; dst = d0; K = 256; total = 32768; break;
        case 1: src = s1; dst = d1; K = 256; total = 32768; break;
        case 2: src = s2; dst = d2; K = 256; total = 32768; break;
        case 3: src = s3; dst = d3; K = 256; total = 32768; break;
        default: src = s4; dst = d4; K = 128; total = 16384; break;
    }
    int i = blockIdx.x * 256 + threadIdx.x;
    if (i >= total) return;
    int m = i / K, k = i - m * K;
    __nv_bfloat16 h, l; bsplit(src[i], h, l);
    __nv_bfloat16* o = dst + (long long)m * 2 * K + k;
    o[0] = h; o[K] = l;
}

__global__ void wsplit_tap_k(const float* __restrict__ src, __nv_bfloat16* __restrict__ dst,
                             int Cout, int KS2, int total)
{
    int i = blockIdx.x * 256 + threadIdx.x;
    if (i >= total) return;
    int co = i / (128 * KS2);
    int rem = i - co * 128 * KS2;
    int ci = rem / KS2;
    int tap = rem - ci * KS2;
    __nv_bfloat16 h, l; bsplit(src[i], h, l);
    __nv_bfloat16* o = dst + (long long)tap * Cout * 256 + (long long)co * 256 + ci;
    o[0] = h; o[128] = l;
}

// transpose+split: in [B,R,Ncol] f32 -> out [B,Ncol,2R] bf16 (hi|lo)
__global__ void tsplit2_k(const float* __restrict__ in, __nv_bfloat16* __restrict__ out,
                          int R, int Ncol)
{
    __shared__ float tile[32][33];
    const int b = blockIdx.z, r0 = blockIdx.y * 32, n0 = blockIdx.x * 32;
    const int tx = threadIdx.x & 31, ty = threadIdx.x >> 5;
    const float* ib = in + (long long)b * R * Ncol;
#pragma unroll
    for (int p = 0; p < 4; p++)
        tile[ty + 8 * p][tx] = ib[(long long)(r0 + ty + 8 * p) * Ncol + n0 + tx];
    __syncthreads();
    __nv_bfloat16* ob = out + (long long)b * Ncol * 2 * R;
#pragma unroll
    for (int p = 0; p < 4; p++) {
        int n = n0 + ty + 8 * p, r = r0 + tx;
        float x = tile[tx][ty + 8 * p];
        __nv_bfloat16 h, l; bsplit(x, h, l);
        __nv_bfloat16* o = ob + (long long)n * 2 * R;
        o[r] = h; o[R + r] = l;
    }
}

__global__ void split2row_k(const float* __restrict__ in, __nv_bfloat16* __restrict__ out)
{
    int i = blockIdx.x * 256 + threadIdx.x;
    float x = in[i];
    __nv_bfloat16 h, l; bsplit(x, h, l);
    long long row = i >> 7; int c = i & 127;
    __nv_bfloat16* o = out + row * 256 + c;
    o[0] = h; o[128] = l;
}

// fused difsim: absd f32 AND difcat split operand [B,4096,512] (hi(256)|lo(256))
__global__ void difsim_split_k(const float* __restrict__ r1, const float* __restrict__ r2,
                               const float* __restrict__ sim,
                               __nv_bfloat16* __restrict__ dsplit,
                               float* __restrict__ absd)
{
    __shared__ float f1s[32][33], f2s[32][33], d1s[32][33], d2s[32][33], ss[32];
    const int b  = blockIdx.z;
    const int c0 = blockIdx.y * 32;
    const int n0 = blockIdx.x * 32;
    const int t  = threadIdx.x;
    const int tx = t & 31, ty = t >> 5;
    const long long BS = 524288;
    const float* r1b = r1 + (long long)b * BS;
    const float* r2b = r2 + (long long)b * BS;
#pragma unroll
    for (int r = 0; r < 4; r++) {
        int n = ty + 8 * r;
        f1s[n][tx] = r1b[(long long)(n0 + n) * 128 + c0 + tx];
        f2s[n][tx] = r2b[(long long)(n0 + n) * 128 + c0 + tx];
    }
    if (t < 32) ss[t] = sim[b * 4096 + n0 + t];
    __syncthreads();
#pragma unroll
    for (int r = 0; r < 4; r++) {
        int cl = ty + 8 * r;
        int c = c0 + cl;
        int n = n0 + tx;
        float rv1 = r1b[(long long)c * 4096 + n];
        float rv2 = r2b[(long long)c * 4096 + n];
        float s  = ss[tx];
        float f1 = f1s[tx][cl];
        float f2 = f2s[tx][cl];
        float omns = 1.f - s;
        d1s[cl][tx] = f1 * omns + rv1;
        d2s[cl][tx] = f2 * omns + rv2;
        absd[(long long)b * BS + (long long)c * 4096 + n] =
            fabsf((f1 - f2) * s + rv1 - rv2);
    }
    __syncthreads();
#pragma unroll
    for (int p = 0; p < 4; p++) {
        int nl = ty + 8 * p;
        float d1 = d1s[tx][nl];
        float d2 = d2s[tx][nl];
        __nv_bfloat16 h1, l1, h2, l2;
        bsplit(d1, h1, l1);
        bsplit(d2, h2, l2);
        __nv_bfloat16* orow = dsplit + (long long)b * (4096LL * 512)
                            + (long long)(n0 + nl) * 512;
        orow[c0 + tx]       = h1;
        orow[128 + c0 + tx] = h2;
        orow[256 + c0 + tx] = l1;
        orow[384 + c0 + tx] = l2;
    }
}

// fused column softmax: stats + normalize + split -> aT2 [B,4096,2048] (hi|lo)
__global__ void colsoftmax_k(const float* __restrict__ lt,
                             __nv_bfloat16* __restrict__ out)
{
    __shared__ float smx[16][65], ssm[16][65];
    __shared__ float cmx[64], csi[64];
    const int b = blockIdx.y;
    const int c = threadIdx.x & 63, g = threadIdx.x >> 6;
    const int col = blockIdx.x * 64 + c;
    const float* p = lt + (long long)b * 4194304 + col;
    float mx = -1e30f, sm = 0.f;
    for (int m = g; m < 4096; m += 16) {
        float x = p[(long long)m * 1024];
        float nm = fmaxf(mx, x);
        sm = sm * __expf(mx - nm) + __expf(x - nm);
        mx = nm;
    }
    smx[g][c] = mx; ssm[g][c] = sm;
    __syncthreads();
    if (g == 0) {
        float MX = smx[0][c], SM = ssm[0][c];
#pragma unroll
        for (int k = 1; k < 16; k++) {
            float m2 = smx[k][c], s2 = ssm[k][c];
            float nm = fmaxf(MX, m2);
            SM = SM * __expf(MX - nm) + s2 * __expf(m2 - nm);
            MX = nm;
        }
        cmx[c] = MX;
        csi[c] = 1.f / SM;
    }
    __syncthreads();
    const float MX = cmx[c], SI = csi[c];
    __nv_bfloat16* ob = out + (long long)b * (4096LL * 2048) + col;
    for (int m = g; m < 4096; m += 16) {
        float e = __expf(p[(long long)m * 1024] - MX) * SI;
        __nv_bfloat16 h, l; bsplit(e, h, l);
        ob[(long long)m * 2048]        = h;
        ob[(long long)m * 2048 + 1024] = l;
    }
}

// ===========================================================================
// scalar auxiliary kernels
// ===========================================================================
__global__ void cos_k(const float* __restrict__ r1, const float* __restrict__ r2,
                      float* __restrict__ sim)
{
    int gid  = blockIdx.x * blockDim.x + threadIdx.x;
    int wid  = gid >> 5;
    int lane = gid & 31;
    if (wid >= 4 * 4096) return;
    const float* a = r1 + (long long)wid * 128;
    const float* c = r2 + (long long)wid * 128;
    float dot = 0.f, na = 0.f, nb = 0.f;
#pragma unroll
    for (int i = 0; i < 4; i++) {
        float x = a[lane + 32 * i], y = c[lane + 32 * i];
        dot += x * y; na += x * x; nb += y * y;
    }
#pragma unroll
    for (int o = 16; o; o >>= 1) {
        dot += __shfl_xor_sync(0xffffffffu, dot, o);
        na  += __shfl_xor_sync(0xffffffffu, na,  o);
        nb  += __shfl_xor_sync(0xffffffffu, nb,  o);
    }
    if (lane == 0)
        sim[wid] = dot / fmaxf(sqrtf(na) * sqrtf(nb), 1e-8f);
}

__global__ void pool_k(const float* __restrict__ absd, float* __restrict__ simp)
{
    int i = blockIdx.x * 256 + threadIdx.x;
    if (i >= 524288) return;
    int wp = i & 31, hp = (i >> 5) & 31, bc = i >> 10;
    const float* a = absd + (long long)bc * 4096 + (hp * 2) * 64 + wp * 2;
    simp[i] = 0.25f * (a[0] + a[1] + a[64] + a[65]);
}

__global__ void resize_k(const float* __restrict__ in, float* __restrict__ out)
{
    long long i = (long long)blockIdx.x * 256 + threadIdx.x;
    if (i >= 8388608LL) return;
    int x = (int)(i & 127), y = (int)((i >> 7) & 127);
    long long bc = i >> 14;
    float sx = (x + 0.5f) * 0.5f - 0.5f;
    float sy = (y + 0.5f) * 0.5f - 0.5f;
    int x0 = (int)floorf(sx), y0 = (int)floorf(sy);
    float fx = sx - x0, fy = sy - y0;
    int x1 = min(x0 + 1, 63), y1 = min(y0 + 1, 63);
    x0 = max(x0, 0); y0 = max(y0, 0);
    const float* p = in + bc * 4096;
    float v = (1.f - fy) * ((1.f - fx) * p[y0 * 64 + x0] + fx * p[y0 * 64 + x1])
            +        fy  * ((1.f - fx) * p[y1 * 64 + x0] + fx * p[y1 * 64 + x1]);
    out[i] = v;
}

// ---------------------------------------------------------------------------
extern "C" void kernel_launch(void* const* d_in, const int* in_sizes, int n_in,
                              void* d_out, int out_size)
{
    (void)in_sizes; (void)n_in; (void)out_size;
    const float* t1      = (const float*)d_in[0];
    const float* t2      = (const float*)d_in[1];
    const float* t1_w    = (const float*)d_in[2];
    const float* t1_b    = (const float*)d_in[3];
    const float* t2_w    = (const float*)d_in[4];
    const float* t2_b    = (const float*)d_in[5];
    const float* df_res_w = (const float*)d_in[6];
    const float* df_res_b = (const float*)d_in[7];
    const float* df_res_s = (const float*)d_in[8];
    const float* df_res_o = (const float*)d_in[9];
    const float* df_b0_w = (const float*)d_in[10];
    const float* df_b0_b = (const float*)d_in[11];
    const float* df_b0_s = (const float*)d_in[12];
    const float* df_b0_o = (const float*)d_in[13];
    const float* df_b1_w = (const float*)d_in[14];
    const float* df_b1_b = (const float*)d_in[15];
    const float* df_b1_s = (const float*)d_in[16];
    const float* df_b1_o = (const float*)d_in[17];
    const float* df_fu_w = (const float*)d_in[18];
    const float* df_fu_b = (const float*)d_in[19];
    const float* df_fu_s = (const float*)d_in[20];
    const float* df_fu_o = (const float*)d_in[21];
    const float* br1_w   = (const float*)d_in[22];
    const float* br1_b   = (const float*)d_in[23];
    const float* br2_w   = (const float*)d_in[24];
    const float* br2_b   = (const float*)d_in[25];
    const float* fu_w    = (const float*)d_in[26];
    const float* fu_b    = (const float*)d_in[27];
    const float* fu_s    = (const float*)d_in[28];
    const float* fu_o    = (const float*)d_in[29];
    float* out = (float*)d_out;

    float* S;
    cudaGetSymbolAddress((void**)&S, g_scratch);
    __nv_bfloat16* G;
    cudaGetSymbolAddress((void**)&G, g_bf);

    cudaFuncSetAttribute(hmma_gemm, cudaFuncAttributeMaxDynamicSharedMemorySize, 66560);
    cudaFuncSetAttribute(hconv_tap<3, 64>,  cudaFuncAttributeMaxDynamicSharedMemorySize, 46080);
    cudaFuncSetAttribute(hconv_tap<5, 64>,  cudaFuncAttributeMaxDynamicSharedMemorySize, 46080);
    cudaFuncSetAttribute(hconv_tap<3, 128>, cudaFuncAttributeMaxDynamicSharedMemorySize, 66560);
    cudaFuncSetAttribute(hconv_tap<5, 128>, cudaFuncAttributeMaxDynamicSharedMemorySize, 66560);

    float* res1    = S + F_RES1;
    float* res2    = S + F_RES2;
    float* sim     = S + F_SIM;
    float* absd    = S + F_ABSD;
    float* simp    = S + F_SIMP;
    float* rbuf    = S + F_R;
    float* dif     = S + F_DIF;
    float* inc     = S + F_INC;
    float* logitsT = S + F_LOG;
    float* fuse    = S + F_FUSE;

    const long long S128 = 128LL * 4096;
    const long long D256 = 4096LL * 256;   // dsplit batch stride, Rtot=128
    const long long D512 = 4096LL * 512;   // dsplit batch stride, Rtot=256

    // weight splits
    wsplit5_k<<<dim3(128, 5), 256>>>(t1_w, t2_w, df_res_w, fu_w, df_fu_w,
                                     G + W_T1W2, G + W_T2W2, G + W_RESW2,
                                     G + W_FUW2, G + W_DFUW2);
    wsplit_tap_k<<<288,  256>>>(df_b0_w, G + W_B0T,  64,  9,  73728);
    wsplit_tap_k<<<800,  256>>>(df_b1_w, G + W_B1T,  64,  25, 204800);
    wsplit_tap_k<<<576,  256>>>(br1_w,   G + W_BR1T, 128, 9,  147456);
    wsplit_tap_k<<<1600, 256>>>(br2_w,   G + W_BR2T, 128, 25, 409600);
    // input splits
    tsplit2_k<<<dim3(128, 8, 4), 256>>>(t1, G + G_T3A, 256, 4096);
    tsplit2_k<<<dim3(128, 8, 4), 256>>>(t2, G + G_T3B, 256, 4096);
    // 1. res1/res2 = 1x1 (256->128) + bias
    hmma_gemm<<<dim3(32, 1, 4), 256, 66560>>>(G + W_T1W2, G + G_T3A, res1,
                                              t1_b, nullptr, nullptr, nullptr,
                                              256, 4096, 0, 4096LL * 512, S128, 0,
                                              nullptr, 0, 0, 0);
    hmma_gemm<<<dim3(32, 1, 4), 256, 66560>>>(G + W_T2W2, G + G_T3B, res2,
                                              t2_b, nullptr, nullptr, nullptr,
                                              256, 4096, 0, 4096LL * 512, S128, 0,
                                              nullptr, 0, 0, 0);
    // 2-4. cosine, fused dif-split (into G_T3A), avgpool, attn operands
    cos_k<<<2048, 256>>>(res1, res2, sim);
    difsim_split_k<<<dim3(128, 4, 4), 256>>>(res1, res2, sim, G + G_T3A, absd);
    pool_k<<<2048, 256>>>(absd, simp);
    split2row_k<<<2048, 256>>>(simp, G + G_ATTN2);
    tsplit2_k<<<dim3(4, 32, 4), 256>>>(simp, G + G_ATTNT2, 1024, 128);
    // 5. r = stdconv 1x1 (256->128); epilogue emits rbuf f32 + G_RB2 split
    hmma_gemm<<<dim3(32, 1, 4), 256, 66560>>>(G + W_RESW2, G + G_T3A, rbuf,
                                              df_res_b, df_res_s, df_res_o, nullptr,
                                              256, 4096, 0, 4096LL * 512, S128, 0,
                                              G + G_RB2, D256, 128, 0);
    // 6/7. inception branches: split-only outputs into G_BB2 (cat via choff)
    hconv_tap<3, 64><<<dim3(32, 1, 4), 256, 46080>>>(
        G + W_B0T, G + G_RB2, nullptr, df_b0_b, df_b0_s, df_b0_o, 0,
        G + G_BB2, D256, 128, 0);
    hconv_tap<5, 64><<<dim3(32, 1, 4), 256, 46080>>>(
        G + W_B1T, G + G_RB2, nullptr, df_b1_b, df_b1_s, df_b1_o, 0,
        G + G_BB2, D256, 128, 64);
    // 8. dif = stdconv 1x1 (128->128) + r; emits dif f32 + G_DIF2 split
    hmma_gemm<<<dim3(32, 1, 4), 256, 66560>>>(G + W_DFUW2, G + G_BB2, dif,
                                              df_fu_b, df_fu_s, df_fu_o, rbuf,
                                              128, 4096, 0, 4096LL * 256, S128, S128,
                                              G + G_DIF2, D256, 128, 0);
    // --- attention branches ---
    for (int br = 0; br < 2; br++) {
        if (br == 0)
            hconv_tap<3, 128><<<dim3(32, 1, 4), 256, 66560>>>(
                G + W_BR1T, G + G_DIF2, inc, br1_b, nullptr, nullptr, S128,
                G + G_INCT2, D256, 128, 0);
        else
            hconv_tap<5, 128><<<dim3(32, 1, 4), 256, 66560>>>(
                G + W_BR2T, G + G_DIF2, inc, br2_b, nullptr, nullptr, S128,
                G + G_INCT2, D256, 128, 0);
        // logitsT[b, pix, tok] = incT . attn
        hmma_gemm<<<dim3(8, 32, 4), 256, 66560>>>(G + G_INCT2, G + G_ATTN2, logitsT,
                                                  nullptr, nullptr, nullptr, nullptr,
                                                  128, 1024,
                                                  4096LL * 256, 1024LL * 256,
                                                  4096LL * 1024, 0,
                                                  nullptr, 0, 0, 0);
        colsoftmax_k<<<dim3(16, 4), 1024>>>(logitsT, G + G_AT2);
        // av: split-only output into acat-split (G_T3A) at choff=br*128
        hmma_gemm<<<dim3(32, 1, 4), 256, 66560>>>(G + G_ATTNT2, G + G_AT2,
                                                  nullptr,
                                                  nullptr, nullptr, nullptr, inc,
                                                  1024, 4096,
                                                  128LL * 2048, 4096LL * 2048,
                                                  0, S128,
                                                  G + G_T3A, D512, 256, br * 128);
    }
    // 14. fused = stdconv 1x1 (256->128) + dif
    hmma_gemm<<<dim3(32, 1, 4), 256, 66560>>>(G + W_FUW2, G + G_T3A, fuse,
                                              fu_b, fu_s, fu_o, dif,
                                              256, 4096, 0, 4096LL * 512, S128, S128,
                                              nullptr, 0, 0, 0);
    // 15. bilinear x2 upsample
    resize_k<<<32768, 256>>>(fuse, out);
}

// round 12
// speedup vs baseline: 1.2125x; 1.2125x over previous
#include <cuda_runtime.h>
#include <cuda_bf16.h>
#include <cstdint>

// ===========================================================================
// B=4, C_IN=256, C=128, H=W=64, HW=4096. out [4,128,128,128] f32.
// ALL dense ops on mma.sync bf16 HMMA, 2-term split.
// Split operands stored 2-segment [hi|lo]; GEMM walks a 3-segment schedule:
//   (Ahi,Bhi) + (Alo,Bhi) + (Ahi,Blo)   (err ~2^-18)
// Convs = per-tap shifted GEMMs over L2-resident split input (cp.async zfill).
// Softmax stats+normalize fused. One barrier per k-chunk (3-stage pipeline).
// ===========================================================================

#define F_RES1 0LL
#define F_RES2 (F_RES1 + 2097152)
#define F_SIM  (F_RES2 + 2097152)
#define F_ABSD (F_SIM  + 16384)
#define F_SIMP (F_ABSD + 2097152)
#define F_R    (F_SIMP + 524288)
#define F_B0B1 (F_R    + 2097152)
#define F_DIF  (F_B0B1 + 2097152)
#define F_INC  (F_DIF  + 2097152)
#define F_LOG  (F_INC  + 2097152)      /* logitsT [B,4096,1024] */
#define F_ACAT (F_LOG  + 16777216)
#define F_FUSE (F_ACAT + 4194304)
#define F_TOTAL (F_FUSE + 2097152)

__device__ float g_scratch[F_TOTAL];

// bf16 scratch element offsets (2-segment layouts)
#define W_T1W2   0LL         /* [128,512]       */
#define W_T2W2   65536LL
#define W_RESW2  131072LL
#define W_FUW2   196608LL
#define W_DFUW2  262144LL    /* [128,256]       */
#define W_B0T    294912LL    /* [9][64][256]    */
#define W_B1T    442368LL    /* [25][64][256]   */
#define W_BR1T   851968LL    /* [9][128][256]   */
#define W_BR2T   1146880LL   /* [25][128][256]  */
#define G_ATTN2  1966080LL   /* [4,1024,256]    */
#define G_INCT2  3014656LL   /* [4,4096,256]    */
#define G_ATTNT2 7208960LL   /* [4,128,2048]    */
#define G_AT2    8257536LL   /* [4,4096,2048]   */
#define G_T3A    41811968LL  /* [4,4096,512]    */
#define G_T3B    50200576LL  /* [4,4096,512]    */
#define G_RB2    58589184LL  /* [4,4096,256]    */
#define G_DIF2   62783488LL  /* [4,4096,256]    */
#define G_BB2    66977792LL  /* [4,4096,256]    */
#define G_TOTAL  71172096LL

__device__ __align__(256) __nv_bfloat16 g_bf[G_TOTAL];

// ------------------------------ helpers ------------------------------------
__device__ __forceinline__ uint32_t smem_u32(const void* p) {
    uint32_t a;
    asm("{ .reg .u64 t; cvta.to.shared.u64 t, %1; cvt.u32.u64 %0, t; }"
        : "=r"(a) : "l"(p));
    return a;
}
__device__ __forceinline__ void bsplit(float x, __nv_bfloat16& h, __nv_bfloat16& l) {
    h = __float2bfloat16(x);
    l = __float2bfloat16(x - __bfloat162float(h));
}
#define CP_ASYNC(dst, src) asm volatile( \
    "cp.async.cg.shared.global [%0], [%1], 16;" :: "r"(dst), "l"(src))
#define CP_ASYNC_Z(dst, src, sz) asm volatile( \
    "cp.async.cg.shared.global [%0], [%1], 16, %2;" :: "r"(dst), "l"(src), "r"(sz))
#define CP_COMMIT() asm volatile("cp.async.commit_group;" ::: "memory")
#define CP_WAIT1()  asm volatile("cp.async.wait_group 1;" ::: "memory")
#define CP_WAIT0()  asm volatile("cp.async.wait_group 0;" ::: "memory")
#define LDM_X4(r0, r1, r2, r3, a) asm volatile( \
    "ldmatrix.sync.aligned.m8n8.x4.shared.b16 {%0,%1,%2,%3}, [%4];" \
    : "=r"(r0), "=r"(r1), "=r"(r2), "=r"(r3) : "r"(a))
#define MMA16816(d, a, bfr) asm volatile( \
    "mma.sync.aligned.m16n8k16.row.col.f32.bf16.bf16.f32 " \
    "{%0,%1,%2,%3}, {%4,%5,%6,%7}, {%8,%9}, {%0,%1,%2,%3};" \
    : "+f"((d)[0]), "+f"((d)[1]), "+f"((d)[2]), "+f"((d)[3]) \
    : "r"((a)[0]), "r"((a)[1]), "r"((a)[2]), "r"((a)[3]), \
      "r"((bfr)[0]), "r"((bfr)[1]))

// ===========================================================================
// hmma_gemm: 128x128 tile, 8 warps (32m x 64n), chunk k=32, 3-stage cp.async.
// A2 [Mtot, 2*Kcore], B2 [Ntot, 2*Kcore] bf16 (hi|lo).
// 3-segment schedule: (0,0), (Kcore,0), (0,Kcore). Kcore % 32 == 0.
// ===========================================================================
__global__ void __launch_bounds__(256) hmma_gemm(
    const __nv_bfloat16* __restrict__ A2, const __nv_bfloat16* __restrict__ B2,
    float* __restrict__ C,
    const float* __restrict__ bias, const float* __restrict__ scale,
    const float* __restrict__ off, const float* __restrict__ resid,
    int Kcore, int Ncols,
    long long Abs, long long Bbs, long long Cbs, long long Rbs)
{
    extern __shared__ __align__(16) char smbuf[];
    const uint32_t sA = smem_u32(smbuf);          // 3 stages x 10240
    const uint32_t sB = sA + 30720;               // 3 stages x 10240
    const int t = threadIdx.x, lane = t & 31, wid = t >> 5;
    const int wm = wid & 3, wn = wid >> 2;
    const int b  = blockIdx.z;
    const int m0 = blockIdx.y * 128;
    const int n0 = blockIdx.x * 128;
    const int Kp = 2 * Kcore;
    const __nv_bfloat16* Ab = A2 + (long long)b * Abs + (long long)m0 * Kp;
    const __nv_bfloat16* Bb = B2 + (long long)b * Bbs + (long long)n0 * Kp;

    float acc[2][8][4];
#pragma unroll
    for (int i = 0; i < 2; i++)
#pragma unroll
        for (int j = 0; j < 8; j++)
#pragma unroll
            for (int r = 0; r < 4; r++) acc[i][j][r] = 0.f;

    const int nchseg = Kcore >> 5;
    auto ldch = [&](int gc) {
        const int seg = (gc >= nchseg) + (gc >= 2 * nchseg);
        const int cc  = gc - seg * nchseg;
        const int aco = (seg == 1 ? Kcore : 0) + cc * 32;
        const int bco = (seg == 2 ? Kcore : 0) + cc * 32;
        const uint32_t ao = sA + (gc % 3) * 10240;
        const uint32_t bo = sB + (gc % 3) * 10240;
#pragma unroll
        for (int r = 0; r < 2; r++) {
            int f = t + 256 * r, row = f >> 2, kq = f & 3;
            CP_ASYNC(ao + (uint32_t)(row * 80 + kq * 16),
                     Ab + (long long)row * Kp + aco + kq * 8);
            CP_ASYNC(bo + (uint32_t)(row * 80 + kq * 16),
                     Bb + (long long)row * Kp + bco + kq * 8);
        }
        CP_COMMIT();
    };

    const int NC = 3 * nchseg;
    ldch(0);
    ldch(1);
    for (int gc = 0; gc < NC; gc++) {
        if (gc + 1 < NC) CP_WAIT1(); else CP_WAIT0();
        __syncthreads();
        if (gc + 2 < NC) ldch(gc + 2);
        const uint32_t ao = sA + (gc % 3) * 10240;
        const uint32_t bo = sB + (gc % 3) * 10240;
#pragma unroll
        for (int ks = 0; ks < 2; ks++) {
            const int kb = ks * 16;
            uint32_t af[2][4];
#pragma unroll
            for (int i = 0; i < 2; i++) {
                int row = wm * 32 + i * 16 + (lane & 7) + ((lane >> 3) & 1) * 8;
                int col = kb + ((lane >> 4) & 1) * 8;
                LDM_X4(af[i][0], af[i][1], af[i][2], af[i][3],
                       ao + (uint32_t)(row * 80 + col * 2));
            }
            uint32_t bfr[8][2];
#pragma unroll
            for (int jp = 0; jp < 4; jp++) {
                int n = wn * 64 + jp * 16 + (lane & 7) + ((lane >> 4) & 1) * 8;
                int k = kb + ((lane >> 3) & 1) * 8;
                LDM_X4(bfr[2 * jp][0], bfr[2 * jp][1],
                       bfr[2 * jp + 1][0], bfr[2 * jp + 1][1],
                       bo + (uint32_t)(n * 80 + k * 2));
            }
#pragma unroll
            for (int i = 0; i < 2; i++)
#pragma unroll
                for (int j = 0; j < 8; j++)
                    MMA16816(acc[i][j], af[i], bfr[j]);
        }
        // single barrier per chunk: next iteration's top barrier orders reuse
    }

    float* Cb = C + (long long)b * Cbs;
    const float* Rb = resid ? resid + (long long)b * Rbs : nullptr;
#pragma unroll
    for (int i = 0; i < 2; i++)
#pragma unroll
        for (int h = 0; h < 2; h++) {
            int m = m0 + wm * 32 + i * 16 + (lane >> 2) + h * 8;
            float bi = bias  ? bias[m]  : 0.f;
            float sc = scale ? scale[m] : 1.f;
            float ofv = off  ? off[m]   : 0.f;
            float* crow = Cb + (long long)m * Ncols;
            const float* rrow = Rb ? Rb + (long long)m * Ncols : nullptr;
#pragma unroll
            for (int j = 0; j < 8; j++) {
                int col = n0 + wn * 64 + j * 8 + (lane & 3) * 2;
                float2 v = make_float2(acc[i][j][h * 2 + 0] + bi,
                                       acc[i][j][h * 2 + 1] + bi);
                if (scale) {
                    v.x = fmaxf(v.x, 0.f) * sc + ofv;
                    v.y = fmaxf(v.y, 0.f) * sc + ofv;
                }
                if (rrow) {
                    float2 rv = *(const float2*)(rrow + col);
                    v.x += rv.x; v.y += rv.y;
                }
                *(float2*)(crow + col) = v;
            }
        }
}

// ===========================================================================
// hconv_tap: conv KSxKS (pad KS/2) as per-tap shifted GEMMs, Kcore=128/tap.
// W2t [tap][MT][256] (hi|lo); Bsplit [B][4096][256] (hi|lo).
// ===========================================================================
template <int KS, int MT>
__global__ void __launch_bounds__(256) hconv_tap(
    const __nv_bfloat16* __restrict__ W2t, const __nv_bfloat16* __restrict__ Bsplit,
    float* __restrict__ out,
    const float* __restrict__ bias, const float* __restrict__ scale,
    const float* __restrict__ off, long long out_bstride)
{
    constexpr int P    = KS / 2;
    constexpr int TAPS = KS * KS;
    constexpr int NC   = TAPS * 12;          // 3 segs x 4 chunks per tap
    constexpr int WM_N = MT / 32;
    constexpr int WN_N = 8 / WM_N;
    constexpr int NJ   = 128 / (WN_N * 8);
    constexpr int ASTG = MT * 80;
    extern __shared__ __align__(16) char smbuf[];
    const uint32_t sA = smem_u32(smbuf);
    const uint32_t sB = sA + 3 * ASTG;
    const int t = threadIdx.x, lane = t & 31, wid = t >> 5;
    const int wm = wid % WM_N, wn = wid / WM_N;
    const int b  = blockIdx.z;
    const int n0 = blockIdx.x * 128;
    const __nv_bfloat16* Bb = Bsplit + (long long)b * (4096LL * 256);

    float acc[2][NJ][4];
#pragma unroll
    for (int i = 0; i < 2; i++)
#pragma unroll
        for (int j = 0; j < NJ; j++)
#pragma unroll
            for (int r = 0; r < 4; r++) acc[i][j][r] = 0.f;

    auto ldch = [&](int gc) {
        const int tap = gc / 12;
        const int r12 = gc - tap * 12;
        const int seg = r12 >> 2;
        const int cc  = r12 & 3;
        const int aco = (seg == 1 ? 128 : 0) + cc * 32;
        const int bco = (seg == 2 ? 128 : 0) + cc * 32;
        const int dy  = tap / KS - P, dx = tap - (tap / KS) * KS - P;
        const int shift = dy * 64 + dx;
        const uint32_t ao = sA + (gc % 3) * ASTG;
        const uint32_t bo = sB + (gc % 3) * 10240;
#pragma unroll
        for (int r = 0; r < MT / 64; r++) {
            int f = t + 256 * r, row = f >> 2, kq = f & 3;
            CP_ASYNC(ao + (uint32_t)(row * 80 + kq * 16),
                     W2t + (long long)tap * (MT * 256) + (long long)row * 256
                         + aco + kq * 8);
        }
#pragma unroll
        for (int r = 0; r < 2; r++) {
            int f = t + 256 * r, row = f >> 2, kq = f & 3;
            int gpix = n0 + row;
            int y = gpix >> 6, x = gpix & 63;
            bool ok = ((unsigned)(y + dy) < 64u) && ((unsigned)(x + dx) < 64u);
            int spix = ok ? (gpix + shift) : 0;
            uint32_t sz = ok ? 16u : 0u;
            CP_ASYNC_Z(bo + (uint32_t)(row * 80 + kq * 16),
                       Bb + (long long)spix * 256 + bco + kq * 8, sz);
        }
        CP_COMMIT();
    };

    ldch(0);
    ldch(1);
    for (int gc = 0; gc < NC; gc++) {
        if (gc + 1 < NC) CP_WAIT1(); else CP_WAIT0();
        __syncthreads();
        if (gc + 2 < NC) ldch(gc + 2);
        const uint32_t ao = sA + (gc % 3) * ASTG;
        const uint32_t bo = sB + (gc % 3) * 10240;
#pragma unroll
        for (int ks = 0; ks < 2; ks++) {
            const int kb = ks * 16;
            uint32_t af[2][4];
#pragma unroll
            for (int i = 0; i < 2; i++) {
                int row = wm * 32 + i * 16 + (lane & 7) + ((lane >> 3) & 1) * 8;
                int col = kb + ((lane >> 4) & 1) * 8;
                LDM_X4(af[i][0], af[i][1], af[i][2], af[i][3],
                       ao + (uint32_t)(row * 80 + col * 2));
            }
            uint32_t bfr[NJ][2];
#pragma unroll
            for (int jp = 0; jp < NJ / 2; jp++) {
                int n = wn * (NJ * 8) + jp * 16 + (lane & 7) + ((lane >> 4) & 1) * 8;
                int k = kb + ((lane >> 3) & 1) * 8;
                LDM_X4(bfr[2 * jp][0], bfr[2 * jp][1],
                       bfr[2 * jp + 1][0], bfr[2 * jp + 1][1],
                       bo + (uint32_t)(n * 80 + k * 2));
            }
#pragma unroll
            for (int i = 0; i < 2; i++)
#pragma unroll
                for (int j = 0; j < NJ; j++)
                    MMA16816(acc[i][j], af[i], bfr[j]);
        }
        // single barrier per chunk
    }

    float* Ob = out + (long long)b * out_bstride;
#pragma unroll
    for (int i = 0; i < 2; i++)
#pragma unroll
        for (int h = 0; h < 2; h++) {
            int m = wm * 32 + i * 16 + (lane >> 2) + h * 8;
            float bi = bias[m];
            float sc = scale ? scale[m] : 1.f;
            float ofv = off ? off[m] : 0.f;
            float* crow = Ob + (long long)m * 4096;
#pragma unroll
            for (int j = 0; j < NJ; j++) {
                int col = n0 + wn * (NJ * 8) + j * 8 + (lane & 3) * 2;
                float2 v = make_float2(acc[i][j][h * 2 + 0] + bi,
                                       acc[i][j][h * 2 + 1] + bi);
                if (scale) {
                    v.x = fmaxf(v.x, 0.f) * sc + ofv;
                    v.y = fmaxf(v.y, 0.f) * sc + ofv;
                }
                *(float2*)(crow + col) = v;
            }
        }
}

// ===========================================================================
// prep kernels (all 2-segment [hi|lo])
// ===========================================================================
__global__ void wsplit5_k(const float* s0, const float* s1, const float* s2,
                          const float* s3, const float* s4,
                          __nv_bfloat16* d0, __nv_bfloat16* d1, __nv_bfloat16* d2,
                          __nv_bfloat16* d3, __nv_bfloat16* d4)
{
    const int seg = blockIdx.y;
    const float* src; __nv_bfloat16* dst; int K, total;
    switch (seg) {
        case 0: src = s0; dst = d0; K = 256; total = 32768; break;
        case 1: src = s1; dst = d1; K = 256; total = 32768; break;
        case 2: src = s2; dst = d2; K = 256; total = 32768; break;
        case 3: src = s3; dst = d3; K = 256; total = 32768; break;
        default: src = s4; dst = d4; K = 128; total = 16384; break;
    }
    int i = blockIdx.x * 256 + threadIdx.x;
    if (i >= total) return;
    int m = i / K, k = i - m * K;
    __nv_bfloat16 h, l; bsplit(src[i], h, l);
    __nv_bfloat16* o = dst + (long long)m * 2 * K + k;
    o[0] = h; o[K] = l;
}

// conv weight split: src OIHW f32 [Cout,128,KS2] -> dst [tap][Cout][256] (hi|lo)
__global__ void wsplit_tap_k(const float* __restrict__ src, __nv_bfloat16* __restrict__ dst,
                             int Cout, int KS2, int total)
{
    int i = blockIdx.x * 256 + threadIdx.x;
    if (i >= total) return;
    int co = i / (128 * KS2);
    int rem = i - co * 128 * KS2;
    int ci = rem / KS2;
    int tap = rem - ci * KS2;
    __nv_bfloat16 h, l; bsplit(src[i], h, l);
    __nv_bfloat16* o = dst + (long long)tap * Cout * 256 + (long long)co * 256 + ci;
    o[0] = h; o[128] = l;
}

// transpose+split: in [B,R,Ncol] f32 -> out [B,Ncol,2R] bf16 (hi|lo)
__global__ void tsplit2_k(const float* __restrict__ in, __nv_bfloat16* __restrict__ out,
                          int R, int Ncol)
{
    __shared__ float tile[32][33];
    const int b = blockIdx.z, r0 = blockIdx.y * 32, n0 = blockIdx.x * 32;
    const int tx = threadIdx.x & 31, ty = threadIdx.x >> 5;
    const float* ib = in + (long long)b * R * Ncol;
#pragma unroll
    for (int p = 0; p < 4; p++)
        tile[ty + 8 * p][tx] = ib[(long long)(r0 + ty + 8 * p) * Ncol + n0 + tx];
    __syncthreads();
    __nv_bfloat16* ob = out + (long long)b * Ncol * 2 * R;
#pragma unroll
    for (int p = 0; p < 4; p++) {
        int n = n0 + ty + 8 * p, r = r0 + tx;
        float x = tile[tx][ty + 8 * p];
        __nv_bfloat16 h, l; bsplit(x, h, l);
        __nv_bfloat16* o = ob + (long long)n * 2 * R;
        o[r] = h; o[R + r] = l;
    }
}

// attn2: simp [B*1024,128] f32 -> [B,1024,256] bf16 (hi|lo)
__global__ void split2row_k(const float* __restrict__ in, __nv_bfloat16* __restrict__ out)
{
    int i = blockIdx.x * 256 + threadIdx.x;
    float x = in[i];
    __nv_bfloat16 h, l; bsplit(x, h, l);
    long long row = i >> 7; int c = i & 127;
    __nv_bfloat16* o = out + row * 256 + c;
    o[0] = h; o[128] = l;
}

// fused difsim: absd f32 AND difcat split operand [B,4096,512] (hi(256)|lo(256))
__global__ void difsim_split_k(const float* __restrict__ r1, const float* __restrict__ r2,
                               const float* __restrict__ sim,
                               __nv_bfloat16* __restrict__ dsplit,
                               float* __restrict__ absd)
{
    __shared__ float f1s[32][33], f2s[32][33], d1s[32][33], d2s[32][33], ss[32];
    const int b  = blockIdx.z;
    const int c0 = blockIdx.y * 32;
    const int n0 = blockIdx.x * 32;
    const int t  = threadIdx.x;
    const int tx = t & 31, ty = t >> 5;
    const long long BS = 524288;
    const float* r1b = r1 + (long long)b * BS;
    const float* r2b = r2 + (long long)b * BS;
#pragma unroll
    for (int r = 0; r < 4; r++) {
        int n = ty + 8 * r;
        f1s[n][tx] = r1b[(long long)(n0 + n) * 128 + c0 + tx];
        f2s[n][tx] = r2b[(long long)(n0 + n) * 128 + c0 + tx];
    }
    if (t < 32) ss[t] = sim[b * 4096 + n0 + t];
    __syncthreads();
#pragma unroll
    for (int r = 0; r < 4; r++) {
        int cl = ty + 8 * r;
        int c = c0 + cl;
        int n = n0 + tx;
        float rv1 = r1b[(long long)c * 4096 + n];
        float rv2 = r2b[(long long)c * 4096 + n];
        float s  = ss[tx];
        float f1 = f1s[tx][cl];
        float f2 = f2s[tx][cl];
        float omns = 1.f - s;
        d1s[cl][tx] = f1 * omns + rv1;
        d2s[cl][tx] = f2 * omns + rv2;
        absd[(long long)b * BS + (long long)c * 4096 + n] =
            fabsf((f1 - f2) * s + rv1 - rv2);
    }
    __syncthreads();
#pragma unroll
    for (int p = 0; p < 4; p++) {
        int nl = ty + 8 * p;
        float d1 = d1s[tx][nl];
        float d2 = d2s[tx][nl];
        __nv_bfloat16 h1, l1, h2, l2;
        bsplit(d1, h1, l1);
        bsplit(d2, h2, l2);
        __nv_bfloat16* orow = dsplit + (long long)b * (4096LL * 512)
                            + (long long)(n0 + nl) * 512;
        orow[c0 + tx]       = h1;
        orow[128 + c0 + tx] = h2;
        orow[256 + c0 + tx] = l1;
        orow[384 + c0 + tx] = l2;
    }
}

// fused column softmax: stats + normalize + split -> aT2 [B,4096,2048] (hi|lo)
__global__ void colsoftmax_k(const float* __restrict__ lt,
                             __nv_bfloat16* __restrict__ out)
{
    __shared__ float smx[16][65], ssm[16][65];
    __shared__ float cmx[64], csi[64];
    const int b = blockIdx.y;
    const int c = threadIdx.x & 63, g = threadIdx.x >> 6;
    const int col = blockIdx.x * 64 + c;
    const float* p = lt + (long long)b * 4194304 + col;
    float mx = -1e30f, sm = 0.f;
    for (int m = g; m < 4096; m += 16) {
        float x = p[(long long)m * 1024];
        float nm = fmaxf(mx, x);
        sm = sm * __expf(mx - nm) + __expf(x - nm);
        mx = nm;
    }
    smx[g][c] = mx; ssm[g][c] = sm;
    __syncthreads();
    if (g == 0) {
        float MX = smx[0][c], SM = ssm[0][c];
#pragma unroll
        for (int k = 1; k < 16; k++) {
            float m2 = smx[k][c], s2 = ssm[k][c];
            float nm = fmaxf(MX, m2);
            SM = SM * __expf(MX - nm) + s2 * __expf(m2 - nm);
            MX = nm;
        }
        cmx[c] = MX;
        csi[c] = 1.f / SM;
    }
    __syncthreads();
    const float MX = cmx[c], SI = csi[c];
    __nv_bfloat16* ob = out + (long long)b * (4096LL * 2048) + col;
    for (int m = g; m < 4096; m += 16) {
        float e = __expf(p[(long long)m * 1024] - MX) * SI;
        __nv_bfloat16 h, l; bsplit(e, h, l);
        ob[(long long)m * 2048]        = h;
        ob[(long long)m * 2048 + 1024] = l;
    }
}

// ===========================================================================
// scalar auxiliary kernels
// ===========================================================================
__global__ void cos_k(const float* __restrict__ r1, const float* __restrict__ r2,
                      float* __restrict__ sim)
{
    int gid  = blockIdx.x * blockDim.x + threadIdx.x;
    int wid  = gid >> 5;
    int lane = gid & 31;
    if (wid >= 4 * 4096) return;
    const float* a = r1 + (long long)wid * 128;
    const float* c = r2 + (long long)wid * 128;
    float dot = 0.f, na = 0.f, nb = 0.f;
#pragma unroll
    for (int i = 0; i < 4; i++) {
        float x = a[lane + 32 * i], y = c[lane + 32 * i];
        dot += x * y; na += x * x; nb += y * y;
    }
#pragma unroll
    for (int o = 16; o; o >>= 1) {
        dot += __shfl_xor_sync(0xffffffffu, dot, o);
        na  += __shfl_xor_sync(0xffffffffu, na,  o);
        nb  += __shfl_xor_sync(0xffffffffu, nb,  o);
    }
    if (lane == 0)
        sim[wid] = dot / fmaxf(sqrtf(na) * sqrtf(nb), 1e-8f);
}

__global__ void pool_k(const float* __restrict__ absd, float* __restrict__ simp)
{
    int i = blockIdx.x * 256 + threadIdx.x;
    if (i >= 524288) return;
    int wp = i & 31, hp = (i >> 5) & 31, bc = i >> 10;
    const float* a = absd + (long long)bc * 4096 + (hp * 2) * 64 + wp * 2;
    simp[i] = 0.25f * (a[0] + a[1] + a[64] + a[65]);
}

__global__ void resize_k(const float* __restrict__ in, float* __restrict__ out)
{
    long long i = (long long)blockIdx.x * 256 + threadIdx.x;
    if (i >= 8388608LL) return;
    int x = (int)(i & 127), y = (int)((i >> 7) & 127);
    long long bc = i >> 14;
    float sx = (x + 0.5f) * 0.5f - 0.5f;
    float sy = (y + 0.5f) * 0.5f - 0.5f;
    int x0 = (int)floorf(sx), y0 = (int)floorf(sy);
    float fx = sx - x0, fy = sy - y0;
    int x1 = min(x0 + 1, 63), y1 = min(y0 + 1, 63);
    x0 = max(x0, 0); y0 = max(y0, 0);
    const float* p = in + bc * 4096;
    float v = (1.f - fy) * ((1.f - fx) * p[y0 * 64 + x0] + fx * p[y0 * 64 + x1])
            +        fy  * ((1.f - fx) * p[y1 * 64 + x0] + fx * p[y1 * 64 + x1]);
    out[i] = v;
}

// ---------------------------------------------------------------------------
extern "C" void kernel_launch(void* const* d_in, const int* in_sizes, int n_in,
                              void* d_out, int out_size)
{
    (void)in_sizes; (void)n_in; (void)out_size;
    const float* t1      = (const float*)d_in[0];
    const float* t2      = (const float*)d_in[1];
    const float* t1_w    = (const float*)d_in[2];
    const float* t1_b    = (const float*)d_in[3];
    const float* t2_w    = (const float*)d_in[4];
    const float* t2_b    = (const float*)d_in[5];
    const float* df_res_w = (const float*)d_in[6];
    const float* df_res_b = (const float*)d_in[7];
    const float* df_res_s = (const float*)d_in[8];
    const float* df_res_o = (const float*)d_in[9];
    const float* df_b0_w = (const float*)d_in[10];
    const float* df_b0_b = (const float*)d_in[11];
    const float* df_b0_s = (const float*)d_in[12];
    const float* df_b0_o = (const float*)d_in[13];
    const float* df_b1_w = (const float*)d_in[14];
    const float* df_b1_b = (const float*)d_in[15];
    const float* df_b1_s = (const float*)d_in[16];
    const float* df_b1_o = (const float*)d_in[17];
    const float* df_fu_w = (const float*)d_in[18];
    const float* df_fu_b = (const float*)d_in[19];
    const float* df_fu_s = (const float*)d_in[20];
    const float* df_fu_o = (const float*)d_in[21];
    const float* br1_w   = (const float*)d_in[22];
    const float* br1_b   = (const float*)d_in[23];
    const float* br2_w   = (const float*)d_in[24];
    const float* br2_b   = (const float*)d_in[25];
    const float* fu_w    = (const float*)d_in[26];
    const float* fu_b    = (const float*)d_in[27];
    const float* fu_s    = (const float*)d_in[28];
    const float* fu_o    = (const float*)d_in[29];
    float* out = (float*)d_out;

    float* S;
    cudaGetSymbolAddress((void**)&S, g_scratch);
    __nv_bfloat16* G;
    cudaGetSymbolAddress((void**)&G, g_bf);

    cudaFuncSetAttribute(hmma_gemm, cudaFuncAttributeMaxDynamicSharedMemorySize, 61440);
    cudaFuncSetAttribute(hconv_tap<3, 64>,  cudaFuncAttributeMaxDynamicSharedMemorySize, 46080);
    cudaFuncSetAttribute(hconv_tap<5, 64>,  cudaFuncAttributeMaxDynamicSharedMemorySize, 46080);
    cudaFuncSetAttribute(hconv_tap<3, 128>, cudaFuncAttributeMaxDynamicSharedMemorySize, 61440);
    cudaFuncSetAttribute(hconv_tap<5, 128>, cudaFuncAttributeMaxDynamicSharedMemorySize, 61440);

    float* res1    = S + F_RES1;
    float* res2    = S + F_RES2;
    float* sim     = S + F_SIM;
    float* absd    = S + F_ABSD;
    float* simp    = S + F_SIMP;
    float* rbuf    = S + F_R;
    float* b0b1    = S + F_B0B1;
    float* dif     = S + F_DIF;
    float* inc     = S + F_INC;
    float* logitsT = S + F_LOG;
    float* acat    = S + F_ACAT;
    float* fuse    = S + F_FUSE;

    const long long S128 = 128LL * 4096;
    const long long S256 = 256LL * 4096;

    // weight splits
    wsplit5_k<<<dim3(128, 5), 256>>>(t1_w, t2_w, df_res_w, fu_w, df_fu_w,
                                     G + W_T1W2, G + W_T2W2, G + W_RESW2,
                                     G + W_FUW2, G + W_DFUW2);
    wsplit_tap_k<<<288,  256>>>(df_b0_w, G + W_B0T,  64,  9,  73728);
    wsplit_tap_k<<<800,  256>>>(df_b1_w, G + W_B1T,  64,  25, 204800);
    wsplit_tap_k<<<576,  256>>>(br1_w,   G + W_BR1T, 128, 9,  147456);
    wsplit_tap_k<<<1600, 256>>>(br2_w,   G + W_BR2T, 128, 25, 409600);
    // input splits
    tsplit2_k<<<dim3(128, 8, 4), 256>>>(t1, G + G_T3A, 256, 4096);
    tsplit2_k<<<dim3(128, 8, 4), 256>>>(t2, G + G_T3B, 256, 4096);
    // 1. res1/res2 = 1x1 (256->128) + bias
    hmma_gemm<<<dim3(32, 1, 4), 256, 61440>>>(G + W_T1W2, G + G_T3A, res1,
                                              t1_b, nullptr, nullptr, nullptr,
                                              256, 4096, 0, 4096LL * 512, S128, 0);
    hmma_gemm<<<dim3(32, 1, 4), 256, 61440>>>(G + W_T2W2, G + G_T3B, res2,
                                              t2_b, nullptr, nullptr, nullptr,
                                              256, 4096, 0, 4096LL * 512, S128, 0);
    // 2-4. cosine, fused dif-split (into G_T3A), avgpool, attn operands
    cos_k<<<2048, 256>>>(res1, res2, sim);
    difsim_split_k<<<dim3(128, 4, 4), 256>>>(res1, res2, sim, G + G_T3A, absd);
    pool_k<<<2048, 256>>>(absd, simp);
    split2row_k<<<2048, 256>>>(simp, G + G_ATTN2);
    tsplit2_k<<<dim3(4, 32, 4), 256>>>(simp, G + G_ATTNT2, 1024, 128);
    // 5. r = stdconv 1x1 (256->128)
    hmma_gemm<<<dim3(32, 1, 4), 256, 61440>>>(G + W_RESW2, G + G_T3A, rbuf,
                                              df_res_b, df_res_s, df_res_o, nullptr,
                                              256, 4096, 0, 4096LL * 512, S128, 0);
    // 6/7. inception branches over shared rbuf-split
    tsplit2_k<<<dim3(128, 4, 4), 256>>>(rbuf, G + G_RB2, 128, 4096);
    hconv_tap<3, 64><<<dim3(32, 1, 4), 256, 46080>>>(
        G + W_B0T, G + G_RB2, b0b1, df_b0_b, df_b0_s, df_b0_o, S128);
    hconv_tap<5, 64><<<dim3(32, 1, 4), 256, 46080>>>(
        G + W_B1T, G + G_RB2, b0b1 + 64LL * 4096, df_b1_b, df_b1_s, df_b1_o, S128);
    // 8. dif = stdconv 1x1 (128->128) + r
    tsplit2_k<<<dim3(128, 4, 4), 256>>>(b0b1, G + G_BB2, 128, 4096);
    hmma_gemm<<<dim3(32, 1, 4), 256, 61440>>>(G + W_DFUW2, G + G_BB2, dif,
                                              df_fu_b, df_fu_s, df_fu_o, rbuf,
                                              128, 4096, 0, 4096LL * 256, S128, S128);
    tsplit2_k<<<dim3(128, 4, 4), 256>>>(dif, G + G_DIF2, 128, 4096);
    // --- attention branches ---
    for (int br = 0; br < 2; br++) {
        if (br == 0)
            hconv_tap<3, 128><<<dim3(32, 1, 4), 256, 61440>>>(
                G + W_BR1T, G + G_DIF2, inc, br1_b, nullptr, nullptr, S128);
        else
            hconv_tap<5, 128><<<dim3(32, 1, 4), 256, 61440>>>(
                G + W_BR2T, G + G_DIF2, inc, br2_b, nullptr, nullptr, S128);
        tsplit2_k<<<dim3(128, 4, 4), 256>>>(inc, G + G_INCT2, 128, 4096);
        // logitsT[b, pix, tok] = incT . attn
        hmma_gemm<<<dim3(8, 32, 4), 256, 61440>>>(G + G_INCT2, G + G_ATTN2, logitsT,
                                                  nullptr, nullptr, nullptr, nullptr,
                                                  128, 1024,
                                                  4096LL * 256, 1024LL * 256,
                                                  4096LL * 1024, 0);
        colsoftmax_k<<<dim3(16, 4), 1024>>>(logitsT, G + G_AT2);
        // out[b, c, pix] = attnT . aT + inc  -> acat half
        hmma_gemm<<<dim3(32, 1, 4), 256, 61440>>>(G + G_ATTNT2, G + G_AT2,
                                                  acat + (long long)br * S128,
                                                  nullptr, nullptr, nullptr, inc,
                                                  1024, 4096,
                                                  128LL * 2048, 4096LL * 2048,
                                                  S256, S128);
    }
    // 14. fused = stdconv 1x1 (256->128) + dif
    tsplit2_k<<<dim3(128, 8, 4), 256>>>(acat, G + G_T3A, 256, 4096);
    hmma_gemm<<<dim3(32, 1, 4), 256, 61440>>>(G + W_FUW2, G + G_T3A, fuse,
                                              fu_b, fu_s, fu_o, dif,
                                              256, 4096, 0, 4096LL * 512, S128, S128);
    // 15. bilinear x2 upsample
    resize_k<<<32768, 256>>>(fuse, out);
}

// round 13
// speedup vs baseline: 1.4028x; 1.1569x over previous
#include <cuda_runtime.h>
#include <cuda_bf16.h>
#include <cstdint>

// ===========================================================================
// B=4, C_IN=256, C=128, H=W=64, HW=4096. out [4,128,128,128] f32.
// ALL dense ops on mma.sync bf16 HMMA, 2-term split.
// Split operands stored 2-segment [hi|lo]; GEMM walks a 3-segment schedule:
//   (Ahi,Bhi) + (Alo,Bhi) + (Ahi,Blo)   (err ~2^-18)
// Convs = per-tap shifted GEMMs over L2-resident split input (cp.async zfill).
// Round 13: k-chunk 64 (3-stage, row stride 144B), halving barrier count.
// ===========================================================================

#define F_RES1 0LL
#define F_RES2 (F_RES1 + 2097152)
#define F_SIM  (F_RES2 + 2097152)
#define F_ABSD (F_SIM  + 16384)
#define F_SIMP (F_ABSD + 2097152)
#define F_R    (F_SIMP + 524288)
#define F_B0B1 (F_R    + 2097152)
#define F_DIF  (F_B0B1 + 2097152)
#define F_INC  (F_DIF  + 2097152)
#define F_LOG  (F_INC  + 2097152)      /* logitsT [B,4096,1024] */
#define F_ACAT (F_LOG  + 16777216)
#define F_FUSE (F_ACAT + 4194304)
#define F_TOTAL (F_FUSE + 2097152)

__device__ float g_scratch[F_TOTAL];

// bf16 scratch element offsets (2-segment layouts)
#define W_T1W2   0LL         /* [128,512]       */
#define W_T2W2   65536LL
#define W_RESW2  131072LL
#define W_FUW2   196608LL
#define W_DFUW2  262144LL    /* [128,256]       */
#define W_B0T    294912LL    /* [9][64][256]    */
#define W_B1T    442368LL    /* [25][64][256]   */
#define W_BR1T   851968LL    /* [9][128][256]   */
#define W_BR2T   1146880LL   /* [25][128][256]  */
#define G_ATTN2  1966080LL   /* [4,1024,256]    */
#define G_INCT2  3014656LL   /* [4,4096,256]    */
#define G_ATTNT2 7208960LL   /* [4,128,2048]    */
#define G_AT2    8257536LL   /* [4,4096,2048]   */
#define G_T3A    41811968LL  /* [4,4096,512]    */
#define G_T3B    50200576LL  /* [4,4096,512]    */
#define G_RB2    58589184LL  /* [4,4096,256]    */
#define G_DIF2   62783488LL  /* [4,4096,256]    */
#define G_BB2    66977792LL  /* [4,4096,256]    */
#define G_TOTAL  71172096LL

__device__ __align__(256) __nv_bfloat16 g_bf[G_TOTAL];

// ------------------------------ helpers ------------------------------------
__device__ __forceinline__ uint32_t smem_u32(const void* p) {
    uint32_t a;
    asm("{ .reg .u64 t; cvta.to.shared.u64 t, %1; cvt.u32.u64 %0, t; }"
        : "=r"(a) : "l"(p));
    return a;
}
__device__ __forceinline__ void bsplit(float x, __nv_bfloat16& h, __nv_bfloat16& l) {
    h = __float2bfloat16(x);
    l = __float2bfloat16(x - __bfloat162float(h));
}
#define CP_ASYNC(dst, src) asm volatile( \
    "cp.async.cg.shared.global [%0], [%1], 16;" :: "r"(dst), "l"(src))
#define CP_ASYNC_Z(dst, src, sz) asm volatile( \
    "cp.async.cg.shared.global [%0], [%1], 16, %2;" :: "r"(dst), "l"(src), "r"(sz))
#define CP_COMMIT() asm volatile("cp.async.commit_group;" ::: "memory")
#define CP_WAIT1()  asm volatile("cp.async.wait_group 1;" ::: "memory")
#define CP_WAIT0()  asm volatile("cp.async.wait_group 0;" ::: "memory")
#define LDM_X4(r0, r1, r2, r3, a) asm volatile( \
    "ldmatrix.sync.aligned.m8n8.x4.shared.b16 {%0,%1,%2,%3}, [%4];" \
    : "=r"(r0), "=r"(r1), "=r"(r2), "=r"(r3) : "r"(a))
#define MMA16816(d, a, bfr) asm volatile( \
    "mma.sync.aligned.m16n8k16.row.col.f32.bf16.bf16.f32 " \
    "{%0,%1,%2,%3}, {%4,%5,%6,%7}, {%8,%9}, {%0,%1,%2,%3};" \
    : "+f"((d)[0]), "+f"((d)[1]), "+f"((d)[2]), "+f"((d)[3]) \
    : "r"((a)[0]), "r"((a)[1]), "r"((a)[2]), "r"((a)[3]), \
      "r"((bfr)[0]), "r"((bfr)[1]))

// ===========================================================================
// hmma_gemm: 128x128 tile, 8 warps (32m x 64n), chunk k=64, 3-stage cp.async.
// A2 [Mtot, 2*Kcore], B2 [Ntot, 2*Kcore] bf16 (hi|lo).
// 3-segment schedule: (0,0), (Kcore,0), (0,Kcore). Kcore % 64 == 0.
// Row stride in smem = 144B (9 x 16B units -> conflict-free ldmatrix).
// dyn smem = 110592.
// ===========================================================================
__global__ void __launch_bounds__(256) hmma_gemm(
    const __nv_bfloat16* __restrict__ A2, const __nv_bfloat16* __restrict__ B2,
    float* __restrict__ C,
    const float* __restrict__ bias, const float* __restrict__ scale,
    const float* __restrict__ off, const float* __restrict__ resid,
    int Kcore, int Ncols,
    long long Abs, long long Bbs, long long Cbs, long long Rbs)
{
    extern __shared__ __align__(16) char smbuf[];
    const uint32_t sA = smem_u32(smbuf);          // 3 stages x 18432
    const uint32_t sB = sA + 55296;               // 3 stages x 18432
    const int t = threadIdx.x, lane = t & 31, wid = t >> 5;
    const int wm = wid & 3, wn = wid >> 2;
    const int b  = blockIdx.z;
    const int m0 = blockIdx.y * 128;
    const int n0 = blockIdx.x * 128;
    const int Kp = 2 * Kcore;
    const __nv_bfloat16* Ab = A2 + (long long)b * Abs + (long long)m0 * Kp;
    const __nv_bfloat16* Bb = B2 + (long long)b * Bbs + (long long)n0 * Kp;

    float acc[2][8][4];
#pragma unroll
    for (int i = 0; i < 2; i++)
#pragma unroll
        for (int j = 0; j < 8; j++)
#pragma unroll
            for (int r = 0; r < 4; r++) acc[i][j][r] = 0.f;

    const int nchseg = Kcore >> 6;
    auto ldch = [&](int gc) {
        const int seg = (gc >= nchseg) + (gc >= 2 * nchseg);
        const int cc  = gc - seg * nchseg;
        const int aco = (seg == 1 ? Kcore : 0) + cc * 64;
        const int bco = (seg == 2 ? Kcore : 0) + cc * 64;
        const uint32_t ao = sA + (gc % 3) * 18432;
        const uint32_t bo = sB + (gc % 3) * 18432;
#pragma unroll
        for (int r = 0; r < 4; r++) {
            int f = t + 256 * r, row = f >> 3, kq = f & 7;
            CP_ASYNC(ao + (uint32_t)(row * 144 + kq * 16),
                     Ab + (long long)row * Kp + aco + kq * 8);
            CP_ASYNC(bo + (uint32_t)(row * 144 + kq * 16),
                     Bb + (long long)row * Kp + bco + kq * 8);
        }
        CP_COMMIT();
    };

    const int NC = 3 * nchseg;
    ldch(0);
    ldch(1);
    for (int gc = 0; gc < NC; gc++) {
        if (gc + 1 < NC) CP_WAIT1(); else CP_WAIT0();
        __syncthreads();
        if (gc + 2 < NC) ldch(gc + 2);
        const uint32_t ao = sA + (gc % 3) * 18432;
        const uint32_t bo = sB + (gc % 3) * 18432;
#pragma unroll
        for (int ks = 0; ks < 4; ks++) {
            const int kb = ks * 16;
            uint32_t af[2][4];
#pragma unroll
            for (int i = 0; i < 2; i++) {
                int row = wm * 32 + i * 16 + (lane & 7) + ((lane >> 3) & 1) * 8;
                int col = kb + ((lane >> 4) & 1) * 8;
                LDM_X4(af[i][0], af[i][1], af[i][2], af[i][3],
                       ao + (uint32_t)(row * 144 + col * 2));
            }
            uint32_t bfr[8][2];
#pragma unroll
            for (int jp = 0; jp < 4; jp++) {
                int n = wn * 64 + jp * 16 + (lane & 7) + ((lane >> 4) & 1) * 8;
                int k = kb + ((lane >> 3) & 1) * 8;
                LDM_X4(bfr[2 * jp][0], bfr[2 * jp][1],
                       bfr[2 * jp + 1][0], bfr[2 * jp + 1][1],
                       bo + (uint32_t)(n * 144 + k * 2));
            }
#pragma unroll
            for (int i = 0; i < 2; i++)
#pragma unroll
                for (int j = 0; j < 8; j++)
                    MMA16816(acc[i][j], af[i], bfr[j]);
        }
        // single barrier per chunk: next iteration's top barrier orders reuse
    }

    float* Cb = C + (long long)b * Cbs;
    const float* Rb = resid ? resid + (long long)b * Rbs : nullptr;
#pragma unroll
    for (int i = 0; i < 2; i++)
#pragma unroll
        for (int h = 0; h < 2; h++) {
            int m = m0 + wm * 32 + i * 16 + (lane >> 2) + h * 8;
            float bi = bias  ? bias[m]  : 0.f;
            float sc = scale ? scale[m] : 1.f;
            float ofv = off  ? off[m]   : 0.f;
            float* crow = Cb + (long long)m * Ncols;
            const float* rrow = Rb ? Rb + (long long)m * Ncols : nullptr;
#pragma unroll
            for (int j = 0; j < 8; j++) {
                int col = n0 + wn * 64 + j * 8 + (lane & 3) * 2;
                float2 v = make_float2(acc[i][j][h * 2 + 0] + bi,
                                       acc[i][j][h * 2 + 1] + bi);
                if (scale) {
                    v.x = fmaxf(v.x, 0.f) * sc + ofv;
                    v.y = fmaxf(v.y, 0.f) * sc + ofv;
                }
                if (rrow) {
                    float2 rv = *(const float2*)(rrow + col);
                    v.x += rv.x; v.y += rv.y;
                }
                *(float2*)(crow + col) = v;
            }
        }
}

// ===========================================================================
// hconv_tap: conv KSxKS (pad KS/2) as per-tap shifted GEMMs, Kcore=128/tap.
// W2t [tap][MT][256] (hi|lo); Bsplit [B][4096][256] (hi|lo).
// k-chunk 64: per tap 3 segs x 2 chunks. Row stride 144B.
// dyn smem = 3*(MT*144) + 55296.
// ===========================================================================
template <int KS, int MT>
__global__ void __launch_bounds__(256) hconv_tap(
    const __nv_bfloat16* __restrict__ W2t, const __nv_bfloat16* __restrict__ Bsplit,
    float* __restrict__ out,
    const float* __restrict__ bias, const float* __restrict__ scale,
    const float* __restrict__ off, long long out_bstride)
{
    constexpr int P    = KS / 2;
    constexpr int TAPS = KS * KS;
    constexpr int NC   = TAPS * 6;           // 3 segs x 2 chunks per tap
    constexpr int WM_N = MT / 32;
    constexpr int WN_N = 8 / WM_N;
    constexpr int NJ   = 128 / (WN_N * 8);
    constexpr int ASTG = MT * 144;
    extern __shared__ __align__(16) char smbuf[];
    const uint32_t sA = smem_u32(smbuf);
    const uint32_t sB = sA + 3 * ASTG;
    const int t = threadIdx.x, lane = t & 31, wid = t >> 5;
    const int wm = wid % WM_N, wn = wid / WM_N;
    const int b  = blockIdx.z;
    const int n0 = blockIdx.x * 128;
    const __nv_bfloat16* Bb = Bsplit + (long long)b * (4096LL * 256);

    float acc[2][NJ][4];
#pragma unroll
    for (int i = 0; i < 2; i++)
#pragma unroll
        for (int j = 0; j < NJ; j++)
#pragma unroll
            for (int r = 0; r < 4; r++) acc[i][j][r] = 0.f;

    auto ldch = [&](int gc) {
        const int tap = gc / 6;
        const int r6  = gc - tap * 6;
        const int seg = r6 >> 1;
        const int cc  = r6 & 1;
        const int aco = (seg == 1 ? 128 : 0) + cc * 64;
        const int bco = (seg == 2 ? 128 : 0) + cc * 64;
        const int dy  = tap / KS - P, dx = tap - (tap / KS) * KS - P;
        const int shift = dy * 64 + dx;
        const uint32_t ao = sA + (gc % 3) * ASTG;
        const uint32_t bo = sB + (gc % 3) * 18432;
#pragma unroll
        for (int r = 0; r < MT / 32; r++) {
            int f = t + 256 * r, row = f >> 3, kq = f & 7;
            CP_ASYNC(ao + (uint32_t)(row * 144 + kq * 16),
                     W2t + (long long)tap * (MT * 256) + (long long)row * 256
                         + aco + kq * 8);
        }
#pragma unroll
        for (int r = 0; r < 4; r++) {
            int f = t + 256 * r, row = f >> 3, kq = f & 7;
            int gpix = n0 + row;
            int y = gpix >> 6, x = gpix & 63;
            bool ok = ((unsigned)(y + dy) < 64u) && ((unsigned)(x + dx) < 64u);
            int spix = ok ? (gpix + shift) : 0;
            uint32_t sz = ok ? 16u : 0u;
            CP_ASYNC_Z(bo + (uint32_t)(row * 144 + kq * 16),
                       Bb + (long long)spix * 256 + bco + kq * 8, sz);
        }
        CP_COMMIT();
    };

    ldch(0);
    ldch(1);
    for (int gc = 0; gc < NC; gc++) {
        if (gc + 1 < NC) CP_WAIT1(); else CP_WAIT0();
        __syncthreads();
        if (gc + 2 < NC) ldch(gc + 2);
        const uint32_t ao = sA + (gc % 3) * ASTG;
        const uint32_t bo = sB + (gc % 3) * 18432;
#pragma unroll
        for (int ks = 0; ks < 4; ks++) {
            const int kb = ks * 16;
            uint32_t af[2][4];
#pragma unroll
            for (int i = 0; i < 2; i++) {
                int row = wm * 32 + i * 16 + (lane & 7) + ((lane >> 3) & 1) * 8;
                int col = kb + ((lane >> 4) & 1) * 8;
                LDM_X4(af[i][0], af[i][1], af[i][2], af[i][3],
                       ao + (uint32_t)(row * 144 + col * 2));
            }
            uint32_t bfr[NJ][2];
#pragma unroll
            for (int jp = 0; jp < NJ / 2; jp++) {
                int n = wn * (NJ * 8) + jp * 16 + (lane & 7) + ((lane >> 4) & 1) * 8;
                int k = kb + ((lane >> 3) & 1) * 8;
                LDM_X4(bfr[2 * jp][0], bfr[2 * jp][1],
                       bfr[2 * jp + 1][0], bfr[2 * jp + 1][1],
                       bo + (uint32_t)(n * 144 + k * 2));
            }
#pragma unroll
            for (int i = 0; i < 2; i++)
#pragma unroll
                for (int j = 0; j < NJ; j++)
                    MMA16816(acc[i][j], af[i], bfr[j]);
        }
        // single barrier per chunk
    }

    float* Ob = out + (long long)b * out_bstride;
#pragma unroll
    for (int i = 0; i < 2; i++)
#pragma unroll
        for (int h = 0; h < 2; h++) {
            int m = wm * 32 + i * 16 + (lane >> 2) + h * 8;
            float bi = bias[m];
            float sc = scale ? scale[m] : 1.f;
            float ofv = off ? off[m] : 0.f;
            float* crow = Ob + (long long)m * 4096;
#pragma unroll
            for (int j = 0; j < NJ; j++) {
                int col = n0 + wn * (NJ * 8) + j * 8 + (lane & 3) * 2;
                float2 v = make_float2(acc[i][j][h * 2 + 0] + bi,
                                       acc[i][j][h * 2 + 1] + bi);
                if (scale) {
                    v.x = fmaxf(v.x, 0.f) * sc + ofv;
                    v.y = fmaxf(v.y, 0.f) * sc + ofv;
                }
                *(float2*)(crow + col) = v;
            }
        }
}

// ===========================================================================
// prep kernels (all 2-segment [hi|lo])
// ===========================================================================
__global__ void wsplit5_k(const float* s0, const float* s1, const float* s2,
                          const float* s3, const float* s4,
                          __nv_bfloat16* d0, __nv_bfloat16* d1, __nv_bfloat16* d2,
                          __nv_bfloat16* d3, __nv_bfloat16* d4)
{
    const int seg = blockIdx.y;
    const float* src; __nv_bfloat16* dst; int K, total;
    switch (seg) {
        case 0: src = s0; dst = d0; K = 256; total = 32768; break;
        case 1: src = s1; dst = d1; K = 256; total = 32768; break;
        case 2: src = s2; dst = d2; K = 256; total = 32768; break;
        case 3: src = s3; dst = d3; K = 256; total = 32768; break;
        default: src = s4; dst = d4; K = 128; total = 16384; break;
    }
    int i = blockIdx.x * 256 + threadIdx.x;
    if (i >= total) return;
    int m = i / K, k = i - m * K;
    __nv_bfloat16 h, l; bsplit(src[i], h, l);
    __nv_bfloat16* o = dst + (long long)m * 2 * K + k;
    o[0] = h; o[K] = l;
}

// conv weight split: src OIHW f32 [Cout,128,KS2] -> dst [tap][Cout][256] (hi|lo)
__global__ void wsplit_tap_k(const float* __restrict__ src, __nv_bfloat16* __restrict__ dst,
                             int Cout, int KS2, int total)
{
    int i = blockIdx.x * 256 + threadIdx.x;
    if (i >= total) return;
    int co = i / (128 * KS2);
    int rem = i - co * 128 * KS2;
    int ci = rem / KS2;
    int tap = rem - ci * KS2;
    __nv_bfloat16 h, l; bsplit(src[i], h, l);
    __nv_bfloat16* o = dst + (long long)tap * Cout * 256 + (long long)co * 256 + ci;
    o[0] = h; o[128] = l;
}

// transpose+split: in [B,R,Ncol] f32 -> out [B,Ncol,2R] bf16 (hi|lo)
__global__ void tsplit2_k(const float* __restrict__ in, __nv_bfloat16* __restrict__ out,
                          int R, int Ncol)
{
    __shared__ float tile[32][33];
    const int b = blockIdx.z, r0 = blockIdx.y * 32, n0 = blockIdx.x * 32;
    const int tx = threadIdx.x & 31, ty = threadIdx.x >> 5;
    const float* ib = in + (long long)b * R * Ncol;
#pragma unroll
    for (int p = 0; p < 4; p++)
        tile[ty + 8 * p][tx] = ib[(long long)(r0 + ty + 8 * p) * Ncol + n0 + tx];
    __syncthreads();
    __nv_bfloat16* ob = out + (long long)b * Ncol * 2 * R;
#pragma unroll
    for (int p = 0; p < 4; p++) {
        int n = n0 + ty + 8 * p, r = r0 + tx;
        float x = tile[tx][ty + 8 * p];
        __nv_bfloat16 h, l; bsplit(x, h, l);
        __nv_bfloat16* o = ob + (long long)n * 2 * R;
        o[r] = h; o[R + r] = l;
    }
}

// attn2: simp [B*1024,128] f32 -> [B,1024,256] bf16 (hi|lo)
__global__ void split2row_k(const float* __restrict__ in, __nv_bfloat16* __restrict__ out)
{
    int i = blockIdx.x * 256 + threadIdx.x;
    float x = in[i];
    __nv_bfloat16 h, l; bsplit(x, h, l);
    long long row = i >> 7; int c = i & 127;
    __nv_bfloat16* o = out + row * 256 + c;
    o[0] = h; o[128] = l;
}

// fused difsim: absd f32 AND difcat split operand [B,4096,512] (hi(256)|lo(256))
__global__ void difsim_split_k(const float* __restrict__ r1, const float* __restrict__ r2,
                               const float* __restrict__ sim,
                               __nv_bfloat16* __restrict__ dsplit,
                               float* __restrict__ absd)
{
    __shared__ float f1s[32][33], f2s[32][33], d1s[32][33], d2s[32][33], ss[32];
    const int b  = blockIdx.z;
    const int c0 = blockIdx.y * 32;
    const int n0 = blockIdx.x * 32;
    const int t  = threadIdx.x;
    const int tx = t & 31, ty = t >> 5;
    const long long BS = 524288;
    const float* r1b = r1 + (long long)b * BS;
    const float* r2b = r2 + (long long)b * BS;
#pragma unroll
    for (int r = 0; r < 4; r++) {
        int n = ty + 8 * r;
        f1s[n][tx] = r1b[(long long)(n0 + n) * 128 + c0 + tx];
        f2s[n][tx] = r2b[(long long)(n0 + n) * 128 + c0 + tx];
    }
    if (t < 32) ss[t] = sim[b * 4096 + n0 + t];
    __syncthreads();
#pragma unroll
    for (int r = 0; r < 4; r++) {
        int cl = ty + 8 * r;
        int c = c0 + cl;
        int n = n0 + tx;
        float rv1 = r1b[(long long)c * 4096 + n];
        float rv2 = r2b[(long long)c * 4096 + n];
        float s  = ss[tx];
        float f1 = f1s[tx][cl];
        float f2 = f2s[tx][cl];
        float omns = 1.f - s;
        d1s[cl][tx] = f1 * omns + rv1;
        d2s[cl][tx] = f2 * omns + rv2;
        absd[(long long)b * BS + (long long)c * 4096 + n] =
            fabsf((f1 - f2) * s + rv1 - rv2);
    }
    __syncthreads();
#pragma unroll
    for (int p = 0; p < 4; p++) {
        int nl = ty + 8 * p;
        float d1 = d1s[tx][nl];
        float d2 = d2s[tx][nl];
        __nv_bfloat16 h1, l1, h2, l2;
        bsplit(d1, h1, l1);
        bsplit(d2, h2, l2);
        __nv_bfloat16* orow = dsplit + (long long)b * (4096LL * 512)
                            + (long long)(n0 + nl) * 512;
        orow[c0 + tx]       = h1;
        orow[128 + c0 + tx] = h2;
        orow[256 + c0 + tx] = l1;
        orow[384 + c0 + tx] = l2;
    }
}

// fused column softmax: stats + normalize + split -> aT2 [B,4096,2048] (hi|lo)
__global__ void colsoftmax_k(const float* __restrict__ lt,
                             __nv_bfloat16* __restrict__ out)
{
    __shared__ float smx[16][65], ssm[16][65];
    __shared__ float cmx[64], csi[64];
    const int b = blockIdx.y;
    const int c = threadIdx.x & 63, g = threadIdx.x >> 6;
    const int col = blockIdx.x * 64 + c;
    const float* p = lt + (long long)b * 4194304 + col;
    float mx = -1e30f, sm = 0.f;
    for (int m = g; m < 4096; m += 16) {
        float x = p[(long long)m * 1024];
        float nm = fmaxf(mx, x);
        sm = sm * __expf(mx - nm) + __expf(x - nm);
        mx = nm;
    }
    smx[g][c] = mx; ssm[g][c] = sm;
    __syncthreads();
    if (g == 0) {
        float MX = smx[0][c], SM = ssm[0][c];
#pragma unroll
        for (int k = 1; k < 16; k++) {
            float m2 = smx[k][c], s2 = ssm[k][c];
            float nm = fmaxf(MX, m2);
            SM = SM * __expf(MX - nm) + s2 * __expf(m2 - nm);
            MX = nm;
        }
        cmx[c] = MX;
        csi[c] = 1.f / SM;
    }
    __syncthreads();
    const float MX = cmx[c], SI = csi[c];
    __nv_bfloat16* ob = out + (long long)b * (4096LL * 2048) + col;
    for (int m = g; m < 4096; m += 16) {
        float e = __expf(p[(long long)m * 1024] - MX) * SI;
        __nv_bfloat16 h, l; bsplit(e, h, l);
        ob[(long long)m * 2048]        = h;
        ob[(long long)m * 2048 + 1024] = l;
    }
}

// ===========================================================================
// scalar auxiliary kernels
// ===========================================================================
__global__ void cos_k(const float* __restrict__ r1, const float* __restrict__ r2,
                      float* __restrict__ sim)
{
    int gid  = blockIdx.x * blockDim.x + threadIdx.x;
    int wid  = gid >> 5;
    int lane = gid & 31;
    if (wid >= 4 * 4096) return;
    const float* a = r1 + (long long)wid * 128;
    const float* c = r2 + (long long)wid * 128;
    float dot = 0.f, na = 0.f, nb = 0.f;
#pragma unroll
    for (int i = 0; i < 4; i++) {
        float x = a[lane + 32 * i], y = c[lane + 32 * i];
        dot += x * y; na += x * x; nb += y * y;
    }
#pragma unroll
    for (int o = 16; o; o >>= 1) {
        dot += __shfl_xor_sync(0xffffffffu, dot, o);
        na  += __shfl_xor_sync(0xffffffffu, na,  o);
        nb  += __shfl_xor_sync(0xffffffffu, nb,  o);
    }
    if (lane == 0)
        sim[wid] = dot / fmaxf(sqrtf(na) * sqrtf(nb), 1e-8f);
}

__global__ void pool_k(const float* __restrict__ absd, float* __restrict__ simp)
{
    int i = blockIdx.x * 256 + threadIdx.x;
    if (i >= 524288) return;
    int wp = i & 31, hp = (i >> 5) & 31, bc = i >> 10;
    const float* a = absd + (long long)bc * 4096 + (hp * 2) * 64 + wp * 2;
    simp[i] = 0.25f * (a[0] + a[1] + a[64] + a[65]);
}

__global__ void resize_k(const float* __restrict__ in, float* __restrict__ out)
{
    long long i = (long long)blockIdx.x * 256 + threadIdx.x;
    if (i >= 8388608LL) return;
    int x = (int)(i & 127), y = (int)((i >> 7) & 127);
    long long bc = i >> 14;
    float sx = (x + 0.5f) * 0.5f - 0.5f;
    float sy = (y + 0.5f) * 0.5f - 0.5f;
    int x0 = (int)floorf(sx), y0 = (int)floorf(sy);
    float fx = sx - x0, fy = sy - y0;
    int x1 = min(x0 + 1, 63), y1 = min(y0 + 1, 63);
    x0 = max(x0, 0); y0 = max(y0, 0);
    const float* p = in + bc * 4096;
    float v = (1.f - fy) * ((1.f - fx) * p[y0 * 64 + x0] + fx * p[y0 * 64 + x1])
            +        fy  * ((1.f - fx) * p[y1 * 64 + x0] + fx * p[y1 * 64 + x1]);
    out[i] = v;
}

// ---------------------------------------------------------------------------
extern "C" void kernel_launch(void* const* d_in, const int* in_sizes, int n_in,
                              void* d_out, int out_size)
{
    (void)in_sizes; (void)n_in; (void)out_size;
    const float* t1      = (const float*)d_in[0];
    const float* t2      = (const float*)d_in[1];
    const float* t1_w    = (const float*)d_in[2];
    const float* t1_b    = (const float*)d_in[3];
    const float* t2_w    = (const float*)d_in[4];
    const float* t2_b    = (const float*)d_in[5];
    const float* df_res_w = (const float*)d_in[6];
    const float* df_res_b = (const float*)d_in[7];
    const float* df_res_s = (const float*)d_in[8];
    const float* df_res_o = (const float*)d_in[9];
    const float* df_b0_w = (const float*)d_in[10];
    const float* df_b0_b = (const float*)d_in[11];
    const float* df_b0_s = (const float*)d_in[12];
    const float* df_b0_o = (const float*)d_in[13];
    const float* df_b1_w = (const float*)d_in[14];
    const float* df_b1_b = (const float*)d_in[15];
    const float* df_b1_s = (const float*)d_in[16];
    const float* df_b1_o = (const float*)d_in[17];
    const float* df_fu_w = (const float*)d_in[18];
    const float* df_fu_b = (const float*)d_in[19];
    const float* df_fu_s = (const float*)d_in[20];
    const float* df_fu_o = (const float*)d_in[21];
    const float* br1_w   = (const float*)d_in[22];
    const float* br1_b   = (const float*)d_in[23];
    const float* br2_w   = (const float*)d_in[24];
    const float* br2_b   = (const float*)d_in[25];
    const float* fu_w    = (const float*)d_in[26];
    const float* fu_b    = (const float*)d_in[27];
    const float* fu_s    = (const float*)d_in[28];
    const float* fu_o    = (const float*)d_in[29];
    float* out = (float*)d_out;

    float* S;
    cudaGetSymbolAddress((void**)&S, g_scratch);
    __nv_bfloat16* G;
    cudaGetSymbolAddress((void**)&G, g_bf);

    cudaFuncSetAttribute(hmma_gemm, cudaFuncAttributeMaxDynamicSharedMemorySize, 110592);
    cudaFuncSetAttribute(hconv_tap<3, 64>,  cudaFuncAttributeMaxDynamicSharedMemorySize, 82944);
    cudaFuncSetAttribute(hconv_tap<5, 64>,  cudaFuncAttributeMaxDynamicSharedMemorySize, 82944);
    cudaFuncSetAttribute(hconv_tap<3, 128>, cudaFuncAttributeMaxDynamicSharedMemorySize, 110592);
    cudaFuncSetAttribute(hconv_tap<5, 128>, cudaFuncAttributeMaxDynamicSharedMemorySize, 110592);

    float* res1    = S + F_RES1;
    float* res2    = S + F_RES2;
    float* sim     = S + F_SIM;
    float* absd    = S + F_ABSD;
    float* simp    = S + F_SIMP;
    float* rbuf    = S + F_R;
    float* b0b1    = S + F_B0B1;
    float* dif     = S + F_DIF;
    float* inc     = S + F_INC;
    float* logitsT = S + F_LOG;
    float* acat    = S + F_ACAT;
    float* fuse    = S + F_FUSE;

    const long long S128 = 128LL * 4096;
    const long long S256 = 256LL * 4096;

    // weight splits
    wsplit5_k<<<dim3(128, 5), 256>>>(t1_w, t2_w, df_res_w, fu_w, df_fu_w,
                                     G + W_T1W2, G + W_T2W2, G + W_RESW2,
                                     G + W_FUW2, G + W_DFUW2);
    wsplit_tap_k<<<288,  256>>>(df_b0_w, G + W_B0T,  64,  9,  73728);
    wsplit_tap_k<<<800,  256>>>(df_b1_w, G + W_B1T,  64,  25, 204800);
    wsplit_tap_k<<<576,  256>>>(br1_w,   G + W_BR1T, 128, 9,  147456);
    wsplit_tap_k<<<1600, 256>>>(br2_w,   G + W_BR2T, 128, 25, 409600);
    // input splits
    tsplit2_k<<<dim3(128, 8, 4), 256>>>(t1, G + G_T3A, 256, 4096);
    tsplit2_k<<<dim3(128, 8, 4), 256>>>(t2, G + G_T3B, 256, 4096);
    // 1. res1/res2 = 1x1 (256->128) + bias
    hmma_gemm<<<dim3(32, 1, 4), 256, 110592>>>(G + W_T1W2, G + G_T3A, res1,
                                               t1_b, nullptr, nullptr, nullptr,
                                               256, 4096, 0, 4096LL * 512, S128, 0);
    hmma_gemm<<<dim3(32, 1, 4), 256, 110592>>>(G + W_T2W2, G + G_T3B, res2,
                                               t2_b, nullptr, nullptr, nullptr,
                                               256, 4096, 0, 4096LL * 512, S128, 0);
    // 2-4. cosine, fused dif-split (into G_T3A), avgpool, attn operands
    cos_k<<<2048, 256>>>(res1, res2, sim);
    difsim_split_k<<<dim3(128, 4, 4), 256>>>(res1, res2, sim, G + G_T3A, absd);
    pool_k<<<2048, 256>>>(absd, simp);
    split2row_k<<<2048, 256>>>(simp, G + G_ATTN2);
    tsplit2_k<<<dim3(4, 32, 4), 256>>>(simp, G + G_ATTNT2, 1024, 128);
    // 5. r = stdconv 1x1 (256->128)
    hmma_gemm<<<dim3(32, 1, 4), 256, 110592>>>(G + W_RESW2, G + G_T3A, rbuf,
                                               df_res_b, df_res_s, df_res_o, nullptr,
                                               256, 4096, 0, 4096LL * 512, S128, 0);
    // 6/7. inception branches over shared rbuf-split
    tsplit2_k<<<dim3(128, 4, 4), 256>>>(rbuf, G + G_RB2, 128, 4096);
    hconv_tap<3, 64><<<dim3(32, 1, 4), 256, 82944>>>(
        G + W_B0T, G + G_RB2, b0b1, df_b0_b, df_b0_s, df_b0_o, S128);
    hconv_tap<5, 64><<<dim3(32, 1, 4), 256, 82944>>>(
        G + W_B1T, G + G_RB2, b0b1 + 64LL * 4096, df_b1_b, df_b1_s, df_b1_o, S128);
    // 8. dif = stdconv 1x1 (128->128) + r
    tsplit2_k<<<dim3(128, 4, 4), 256>>>(b0b1, G + G_BB2, 128, 4096);
    hmma_gemm<<<dim3(32, 1, 4), 256, 110592>>>(G + W_DFUW2, G + G_BB2, dif,
                                               df_fu_b, df_fu_s, df_fu_o, rbuf,
                                               128, 4096, 0, 4096LL * 256, S128, S128);
    tsplit2_k<<<dim3(128, 4, 4), 256>>>(dif, G + G_DIF2, 128, 4096);
    // --- attention branches ---
    for (int br = 0; br < 2; br++) {
        if (br == 0)
            hconv_tap<3, 128><<<dim3(32, 1, 4), 256, 110592>>>(
                G + W_BR1T, G + G_DIF2, inc, br1_b, nullptr, nullptr, S128);
        else
            hconv_tap<5, 128><<<dim3(32, 1, 4), 256, 110592>>>(
                G + W_BR2T, G + G_DIF2, inc, br2_b, nullptr, nullptr, S128);
        tsplit2_k<<<dim3(128, 4, 4), 256>>>(inc, G + G_INCT2, 128, 4096);
        // logitsT[b, pix, tok] = incT . attn
        hmma_gemm<<<dim3(8, 32, 4), 256, 110592>>>(G + G_INCT2, G + G_ATTN2, logitsT,
                                                   nullptr, nullptr, nullptr, nullptr,
                                                   128, 1024,
                                                   4096LL * 256, 1024LL * 256,
                                                   4096LL * 1024, 0);
        colsoftmax_k<<<dim3(16, 4), 1024>>>(logitsT, G + G_AT2);
        // out[b, c, pix] = attnT . aT + inc  -> acat half
        hmma_gemm<<<dim3(32, 1, 4), 256, 110592>>>(G + G_ATTNT2, G + G_AT2,
                                                   acat + (long long)br * S128,
                                                   nullptr, nullptr, nullptr, inc,
                                                   1024, 4096,
                                                   128LL * 2048, 4096LL * 2048,
                                                   S256, S128);
    }
    // 14. fused = stdconv 1x1 (256->128) + dif
    tsplit2_k<<<dim3(128, 8, 4), 256>>>(acat, G + G_T3A, 256, 4096);
    hmma_gemm<<<dim3(32, 1, 4), 256, 110592>>>(G + W_FUW2, G + G_T3A, fuse,
                                               fu_b, fu_s, fu_o, dif,
                                               256, 4096, 0, 4096LL * 512, S128, S128);
    // 15. bilinear x2 upsample
    resize_k<<<32768, 256>>>(fuse, out);
}

// round 14
// speedup vs baseline: 1.4805x; 1.0553x over previous
#include <cuda_runtime.h>
#include <cuda_bf16.h>
#include <cstdint>

// ===========================================================================
// B=4, C_IN=256, C=128, H=W=64, HW=4096. out [4,128,128,128] f32.
// ALL dense ops on mma.sync bf16 HMMA, 2-term split.
// Split operands stored 2-segment [hi|lo]; GEMM walks a 3-segment schedule:
//   (Ahi,Bhi) + (Alo,Bhi) + (Ahi,Blo)   (err ~2^-18)
// Convs = per-tap shifted GEMMs (cp.async zfill), k-chunk 128 (2-stage).
// 1x1/attention GEMM: k-chunk 64, 3-stage (keeps 2 CTA/SM for logit GEMM).
// ===========================================================================

#define F_RES1 0LL
#define F_RES2 (F_RES1 + 2097152)
#define F_SIM  (F_RES2 + 2097152)
#define F_ABSD (F_SIM  + 16384)
#define F_SIMP (F_ABSD + 2097152)
#define F_R    (F_SIMP + 524288)
#define F_B0B1 (F_R    + 2097152)
#define F_DIF  (F_B0B1 + 2097152)
#define F_INC  (F_DIF  + 2097152)
#define F_LOG  (F_INC  + 2097152)      /* logitsT [B,4096,1024] */
#define F_ACAT (F_LOG  + 16777216)
#define F_FUSE (F_ACAT + 4194304)
#define F_TOTAL (F_FUSE + 2097152)

__device__ float g_scratch[F_TOTAL];

// bf16 scratch element offsets (2-segment layouts)
#define W_T1W2   0LL         /* [128,512]       */
#define W_T2W2   65536LL
#define W_RESW2  131072LL
#define W_FUW2   196608LL
#define W_DFUW2  262144LL    /* [128,256]       */
#define W_B0T    294912LL    /* [9][64][256]    */
#define W_B1T    442368LL    /* [25][64][256]   */
#define W_BR1T   851968LL    /* [9][128][256]   */
#define W_BR2T   1146880LL   /* [25][128][256]  */
#define G_ATTN2  1966080LL   /* [4,1024,256]    */
#define G_INCT2  3014656LL   /* [4,4096,256]    */
#define G_ATTNT2 7208960LL   /* [4,128,2048]    */
#define G_AT2    8257536LL   /* [4,4096,2048]   */
#define G_T3A    41811968LL  /* [4,4096,512]    */
#define G_T3B    50200576LL  /* [4,4096,512]    */
#define G_RB2    58589184LL  /* [4,4096,256]    */
#define G_DIF2   62783488LL  /* [4,4096,256]    */
#define G_BB2    66977792LL  /* [4,4096,256]    */
#define G_TOTAL  71172096LL

__device__ __align__(256) __nv_bfloat16 g_bf[G_TOTAL];

// ------------------------------ helpers ------------------------------------
__device__ __forceinline__ uint32_t smem_u32(const void* p) {
    uint32_t a;
    asm("{ .reg .u64 t; cvta.to.shared.u64 t, %1; cvt.u32.u64 %0, t; }"
        : "=r"(a) : "l"(p));
    return a;
}
__device__ __forceinline__ void bsplit(float x, __nv_bfloat16& h, __nv_bfloat16& l) {
    h = __float2bfloat16(x);
    l = __float2bfloat16(x - __bfloat162float(h));
}
#define CP_ASYNC(dst, src) asm volatile( \
    "cp.async.cg.shared.global [%0], [%1], 16;" :: "r"(dst), "l"(src))
#define CP_ASYNC_Z(dst, src, sz) asm volatile( \
    "cp.async.cg.shared.global [%0], [%1], 16, %2;" :: "r"(dst), "l"(src), "r"(sz))
#define CP_COMMIT() asm volatile("cp.async.commit_group;" ::: "memory")
#define CP_WAIT1()  asm volatile("cp.async.wait_group 1;" ::: "memory")
#define CP_WAIT0()  asm volatile("cp.async.wait_group 0;" ::: "memory")
#define LDM_X4(r0, r1, r2, r3, a) asm volatile( \
    "ldmatrix.sync.aligned.m8n8.x4.shared.b16 {%0,%1,%2,%3}, [%4];" \
    : "=r"(r0), "=r"(r1), "=r"(r2), "=r"(r3) : "r"(a))
#define MMA16816(d, a, bfr) asm volatile( \
    "mma.sync.aligned.m16n8k16.row.col.f32.bf16.bf16.f32 " \
    "{%0,%1,%2,%3}, {%4,%5,%6,%7}, {%8,%9}, {%0,%1,%2,%3};" \
    : "+f"((d)[0]), "+f"((d)[1]), "+f"((d)[2]), "+f"((d)[3]) \
    : "r"((a)[0]), "r"((a)[1]), "r"((a)[2]), "r"((a)[3]), \
      "r"((bfr)[0]), "r"((bfr)[1]))

// ===========================================================================
// hmma_gemm: 128x128 tile, 8 warps (32m x 64n), chunk k=64, 3-stage cp.async.
// A2 [Mtot, 2*Kcore], B2 [Ntot, 2*Kcore] bf16 (hi|lo).
// 3-segment schedule: (0,0), (Kcore,0), (0,Kcore). Kcore % 64 == 0.
// Row stride 144B (9x16B -> conflict-free ldmatrix). dyn smem = 110592.
// ===========================================================================
__global__ void __launch_bounds__(256) hmma_gemm(
    const __nv_bfloat16* __restrict__ A2, const __nv_bfloat16* __restrict__ B2,
    float* __restrict__ C,
    const float* __restrict__ bias, const float* __restrict__ scale,
    const float* __restrict__ off, const float* __restrict__ resid,
    int Kcore, int Ncols,
    long long Abs, long long Bbs, long long Cbs, long long Rbs)
{
    extern __shared__ __align__(16) char smbuf[];
    const uint32_t sA = smem_u32(smbuf);          // 3 stages x 18432
    const uint32_t sB = sA + 55296;               // 3 stages x 18432
    const int t = threadIdx.x, lane = t & 31, wid = t >> 5;
    const int wm = wid & 3, wn = wid >> 2;
    const int b  = blockIdx.z;
    const int m0 = blockIdx.y * 128;
    const int n0 = blockIdx.x * 128;
    const int Kp = 2 * Kcore;
    const __nv_bfloat16* Ab = A2 + (long long)b * Abs + (long long)m0 * Kp;
    const __nv_bfloat16* Bb = B2 + (long long)b * Bbs + (long long)n0 * Kp;

    float acc[2][8][4];
#pragma unroll
    for (int i = 0; i < 2; i++)
#pragma unroll
        for (int j = 0; j < 8; j++)
#pragma unroll
            for (int r = 0; r < 4; r++) acc[i][j][r] = 0.f;

    const int nchseg = Kcore >> 6;
    auto ldch = [&](int gc) {
        const int seg = (gc >= nchseg) + (gc >= 2 * nchseg);
        const int cc  = gc - seg * nchseg;
        const int aco = (seg == 1 ? Kcore : 0) + cc * 64;
        const int bco = (seg == 2 ? Kcore : 0) + cc * 64;
        const uint32_t ao = sA + (gc % 3) * 18432;
        const uint32_t bo = sB + (gc % 3) * 18432;
#pragma unroll
        for (int r = 0; r < 4; r++) {
            int f = t + 256 * r, row = f >> 3, kq = f & 7;
            CP_ASYNC(ao + (uint32_t)(row * 144 + kq * 16),
                     Ab + (long long)row * Kp + aco + kq * 8);
            CP_ASYNC(bo + (uint32_t)(row * 144 + kq * 16),
                     Bb + (long long)row * Kp + bco + kq * 8);
        }
        CP_COMMIT();
    };

    const int NC = 3 * nchseg;
    ldch(0);
    ldch(1);
    for (int gc = 0; gc < NC; gc++) {
        if (gc + 1 < NC) CP_WAIT1(); else CP_WAIT0();
        __syncthreads();
        if (gc + 2 < NC) ldch(gc + 2);
        const uint32_t ao = sA + (gc % 3) * 18432;
        const uint32_t bo = sB + (gc % 3) * 18432;
#pragma unroll
        for (int ks = 0; ks < 4; ks++) {
            const int kb = ks * 16;
            uint32_t af[2][4];
#pragma unroll
            for (int i = 0; i < 2; i++) {
                int row = wm * 32 + i * 16 + (lane & 7) + ((lane >> 3) & 1) * 8;
                int col = kb + ((lane >> 4) & 1) * 8;
                LDM_X4(af[i][0], af[i][1], af[i][2], af[i][3],
                       ao + (uint32_t)(row * 144 + col * 2));
            }
            uint32_t bfr[8][2];
#pragma unroll
            for (int jp = 0; jp < 4; jp++) {
                int n = wn * 64 + jp * 16 + (lane & 7) + ((lane >> 4) & 1) * 8;
                int k = kb + ((lane >> 3) & 1) * 8;
                LDM_X4(bfr[2 * jp][0], bfr[2 * jp][1],
                       bfr[2 * jp + 1][0], bfr[2 * jp + 1][1],
                       bo + (uint32_t)(n * 144 + k * 2));
            }
#pragma unroll
            for (int i = 0; i < 2; i++)
#pragma unroll
                for (int j = 0; j < 8; j++)
                    MMA16816(acc[i][j], af[i], bfr[j]);
        }
    }

    float* Cb = C + (long long)b * Cbs;
    const float* Rb = resid ? resid + (long long)b * Rbs : nullptr;
#pragma unroll
    for (int i = 0; i < 2; i++)
#pragma unroll
        for (int h = 0; h < 2; h++) {
            int m = m0 + wm * 32 + i * 16 + (lane >> 2) + h * 8;
            float bi = bias  ? bias[m]  : 0.f;
            float sc = scale ? scale[m] : 1.f;
            float ofv = off  ? off[m]   : 0.f;
            float* crow = Cb + (long long)m * Ncols;
            const float* rrow = Rb ? Rb + (long long)m * Ncols : nullptr;
#pragma unroll
            for (int j = 0; j < 8; j++) {
                int col = n0 + wn * 64 + j * 8 + (lane & 3) * 2;
                float2 v = make_float2(acc[i][j][h * 2 + 0] + bi,
                                       acc[i][j][h * 2 + 1] + bi);
                if (scale) {
                    v.x = fmaxf(v.x, 0.f) * sc + ofv;
                    v.y = fmaxf(v.y, 0.f) * sc + ofv;
                }
                if (rrow) {
                    float2 rv = *(const float2*)(rrow + col);
                    v.x += rv.x; v.y += rv.y;
                }
                *(float2*)(crow + col) = v;
            }
        }
}

// ===========================================================================
// hconv_tap: conv KSxKS (pad KS/2) as per-tap shifted GEMMs, Kcore=128/tap.
// W2t [tap][MT][256] (hi|lo); Bsplit [B][4096][256] (hi|lo).
// k-chunk 128 (one segment per chunk): NC = TAPS*3. 2-stage pipeline.
// Row stride 272B (17x16B -> conflict-free). dyn smem = 2*(MT+128)*272.
// ===========================================================================
template <int KS, int MT>
__global__ void __launch_bounds__(256) hconv_tap(
    const __nv_bfloat16* __restrict__ W2t, const __nv_bfloat16* __restrict__ Bsplit,
    float* __restrict__ out,
    const float* __restrict__ bias, const float* __restrict__ scale,
    const float* __restrict__ off, long long out_bstride)
{
    constexpr int P    = KS / 2;
    constexpr int TAPS = KS * KS;
    constexpr int NC   = TAPS * 3;           // 3 segs x 1 chunk per tap
    constexpr int WM_N = MT / 32;
    constexpr int WN_N = 8 / WM_N;
    constexpr int NJ   = 128 / (WN_N * 8);
    constexpr int ASTG = MT * 272;
    extern __shared__ __align__(16) char smbuf[];
    const uint32_t sA = smem_u32(smbuf);     // 2 stages x ASTG
    const uint32_t sB = sA + 2 * ASTG;       // 2 stages x 34816
    const int t = threadIdx.x, lane = t & 31, wid = t >> 5;
    const int wm = wid % WM_N, wn = wid / WM_N;
    const int b  = blockIdx.z;
    const int n0 = blockIdx.x * 128;
    const __nv_bfloat16* Bb = Bsplit + (long long)b * (4096LL * 256);

    float acc[2][NJ][4];
#pragma unroll
    for (int i = 0; i < 2; i++)
#pragma unroll
        for (int j = 0; j < NJ; j++)
#pragma unroll
            for (int r = 0; r < 4; r++) acc[i][j][r] = 0.f;

    auto ldch = [&](int gc) {
        const int tap = gc / 3;
        const int seg = gc - tap * 3;
        const int aco = (seg == 1 ? 128 : 0);
        const int bco = (seg == 2 ? 128 : 0);
        const int dy  = tap / KS - P, dx = tap - (tap / KS) * KS - P;
        const int shift = dy * 64 + dx;
        const uint32_t ao = sA + (gc & 1) * ASTG;
        const uint32_t bo = sB + (gc & 1) * 34816;
#pragma unroll
        for (int r = 0; r < MT / 16; r++) {
            int f = t + 256 * r, row = f >> 4, kq = f & 15;
            CP_ASYNC(ao + (uint32_t)(row * 272 + kq * 16),
                     W2t + (long long)tap * (MT * 256) + (long long)row * 256
                         + aco + kq * 8);
        }
#pragma unroll
        for (int r = 0; r < 8; r++) {
            int f = t + 256 * r, row = f >> 4, kq = f & 15;
            int gpix = n0 + row;
            int y = gpix >> 6, x = gpix & 63;
            bool ok = ((unsigned)(y + dy) < 64u) && ((unsigned)(x + dx) < 64u);
            int spix = ok ? (gpix + shift) : 0;
            uint32_t sz = ok ? 16u : 0u;
            CP_ASYNC_Z(bo + (uint32_t)(row * 272 + kq * 16),
                       Bb + (long long)spix * 256 + bco + kq * 8, sz);
        }
        CP_COMMIT();
    };

    ldch(0);
    for (int gc = 0; gc < NC; gc++) {
        CP_WAIT0();
        __syncthreads();
        if (gc + 1 < NC) ldch(gc + 1);
        const uint32_t ao = sA + (gc & 1) * ASTG;
        const uint32_t bo = sB + (gc & 1) * 34816;
#pragma unroll
        for (int ks = 0; ks < 8; ks++) {
            const int kb = ks * 16;
            uint32_t af[2][4];
#pragma unroll
            for (int i = 0; i < 2; i++) {
                int row = wm * 32 + i * 16 + (lane & 7) + ((lane >> 3) & 1) * 8;
                int col = kb + ((lane >> 4) & 1) * 8;
                LDM_X4(af[i][0], af[i][1], af[i][2], af[i][3],
                       ao + (uint32_t)(row * 272 + col * 2));
            }
            uint32_t bfr[NJ][2];
#pragma unroll
            for (int jp = 0; jp < NJ / 2; jp++) {
                int n = wn * (NJ * 8) + jp * 16 + (lane & 7) + ((lane >> 4) & 1) * 8;
                int k = kb + ((lane >> 3) & 1) * 8;
                LDM_X4(bfr[2 * jp][0], bfr[2 * jp][1],
                       bfr[2 * jp + 1][0], bfr[2 * jp + 1][1],
                       bo + (uint32_t)(n * 272 + k * 2));
            }
#pragma unroll
            for (int i = 0; i < 2; i++)
#pragma unroll
                for (int j = 0; j < NJ; j++)
                    MMA16816(acc[i][j], af[i], bfr[j]);
        }
    }

    float* Ob = out + (long long)b * out_bstride;
#pragma unroll
    for (int i = 0; i < 2; i++)
#pragma unroll
        for (int h = 0; h < 2; h++) {
            int m = wm * 32 + i * 16 + (lane >> 2) + h * 8;
            float bi = bias[m];
            float sc = scale ? scale[m] : 1.f;
            float ofv = off ? off[m] : 0.f;
            float* crow = Ob + (long long)m * 4096;
#pragma unroll
            for (int j = 0; j < NJ; j++) {
                int col = n0 + wn * (NJ * 8) + j * 8 + (lane & 3) * 2;
                float2 v = make_float2(acc[i][j][h * 2 + 0] + bi,
                                       acc[i][j][h * 2 + 1] + bi);
                if (scale) {
                    v.x = fmaxf(v.x, 0.f) * sc + ofv;
                    v.y = fmaxf(v.y, 0.f) * sc + ofv;
                }
                *(float2*)(crow + col) = v;
            }
        }
}

// ===========================================================================
// prep kernels (all 2-segment [hi|lo])
// ===========================================================================
__global__ void wsplit5_k(const float* s0, const float* s1, const float* s2,
                          const float* s3, const float* s4,
                          __nv_bfloat16* d0, __nv_bfloat16* d1, __nv_bfloat16* d2,
                          __nv_bfloat16* d3, __nv_bfloat16* d4)
{
    const int seg = blockIdx.y;
    const float* src; __nv_bfloat16* dst; int K, total;
    switch (seg) {
        case 0: src = s0; dst = d0; K = 256; total = 32768; break;
        case 1: src = s1; dst = d1; K = 256; total = 32768; break;
        case 2: src = s2; dst = d2; K = 256; total = 32768; break;
        case 3: src = s3; dst = d3; K = 256; total = 32768; break;
        default: src = s4; dst = d4; K = 128; total = 16384; break;
    }
    int i = blockIdx.x * 256 + threadIdx.x;
    if (i >= total) return;
    int m = i / K, k = i - m * K;
    __nv_bfloat16 h, l; bsplit(src[i], h, l);
    __nv_bfloat16* o = dst + (long long)m * 2 * K + k;
    o[0] = h; o[K] = l;
}

// all four conv weight splits in one launch. grid (1600, 4).
__global__ void wsplit_tap4_k(const float* w0, const float* w1,
                              const float* w2, const float* w3,
                              __nv_bfloat16* d0, __nv_bfloat16* d1,
                              __nv_bfloat16* d2, __nv_bfloat16* d3)
{
    const int seg = blockIdx.y;
    const float* src; __nv_bfloat16* dst; int Cout, KS2, total;
    switch (seg) {
        case 0: src = w0; dst = d0; Cout = 64;  KS2 = 9;  total = 73728;  break;
        case 1: src = w1; dst = d1; Cout = 64;  KS2 = 25; total = 204800; break;
        case 2: src = w2; dst = d2; Cout = 128; KS2 = 9;  total = 147456; break;
        default: src = w3; dst = d3; Cout = 128; KS2 = 25; total = 409600; break;
    }
    int i = blockIdx.x * 256 + threadIdx.x;
    if (i >= total) return;
    int co = i / (128 * KS2);
    int rem = i - co * 128 * KS2;
    int ci = rem / KS2;
    int tap = rem - ci * KS2;
    __nv_bfloat16 h, l; bsplit(src[i], h, l);
    __nv_bfloat16* o = dst + (long long)tap * Cout * 256 + (long long)co * 256 + ci;
    o[0] = h; o[128] = l;
}

// transpose+split: in [B,R,Ncol] f32 -> out [B,Ncol,2R] bf16 (hi|lo)
__global__ void tsplit2_k(const float* __restrict__ in, __nv_bfloat16* __restrict__ out,
                          int R, int Ncol)
{
    __shared__ float tile[32][33];
    const int b = blockIdx.z, r0 = blockIdx.y * 32, n0 = blockIdx.x * 32;
    const int tx = threadIdx.x & 31, ty = threadIdx.x >> 5;
    const float* ib = in + (long long)b * R * Ncol;
#pragma unroll
    for (int p = 0; p < 4; p++)
        tile[ty + 8 * p][tx] = ib[(long long)(r0 + ty + 8 * p) * Ncol + n0 + tx];
    __syncthreads();
    __nv_bfloat16* ob = out + (long long)b * Ncol * 2 * R;
#pragma unroll
    for (int p = 0; p < 4; p++) {
        int n = n0 + ty + 8 * p, r = r0 + tx;
        float x = tile[tx][ty + 8 * p];
        __nv_bfloat16 h, l; bsplit(x, h, l);
        __nv_bfloat16* o = ob + (long long)n * 2 * R;
        o[r] = h; o[R + r] = l;
    }
}

// attn2: simp [B*1024,128] f32 -> [B,1024,256] bf16 (hi|lo)
__global__ void split2row_k(const float* __restrict__ in, __nv_bfloat16* __restrict__ out)
{
    int i = blockIdx.x * 256 + threadIdx.x;
    float x = in[i];
    __nv_bfloat16 h, l; bsplit(x, h, l);
    long long row = i >> 7; int c = i & 127;
    __nv_bfloat16* o = out + row * 256 + c;
    o[0] = h; o[128] = l;
}

// fused difsim: absd f32 AND difcat split operand [B,4096,512] (hi(256)|lo(256))
__global__ void difsim_split_k(const float* __restrict__ r1, const float* __restrict__ r2,
                               const float* __restrict__ sim,
                               __nv_bfloat16* __restrict__ dsplit,
                               float* __restrict__ absd)
{
    __shared__ float f1s[32][33], f2s[32][33], d1s[32][33], d2s[32][33], ss[32];
    const int b  = blockIdx.z;
    const int c0 = blockIdx.y * 32;
    const int n0 = blockIdx.x * 32;
    const int t  = threadIdx.x;
    const int tx = t & 31, ty = t >> 5;
    const long long BS = 524288;
    const float* r1b = r1 + (long long)b * BS;
    const float* r2b = r2 + (long long)b * BS;
#pragma unroll
    for (int r = 0; r < 4; r++) {
        int n = ty + 8 * r;
        f1s[n][tx] = r1b[(long long)(n0 + n) * 128 + c0 + tx];
        f2s[n][tx] = r2b[(long long)(n0 + n) * 128 + c0 + tx];
    }
    if (t < 32) ss[t] = sim[b * 4096 + n0 + t];
    __syncthreads();
#pragma unroll
    for (int r = 0; r < 4; r++) {
        int cl = ty + 8 * r;
        int c = c0 + cl;
        int n = n0 + tx;
        float rv1 = r1b[(long long)c * 4096 + n];
        float rv2 = r2b[(long long)c * 4096 + n];
        float s  = ss[tx];
        float f1 = f1s[tx][cl];
        float f2 = f2s[tx][cl];
        float omns = 1.f - s;
        d1s[cl][tx] = f1 * omns + rv1;
        d2s[cl][tx] = f2 * omns + rv2;
        absd[(long long)b * BS + (long long)c * 4096 + n] =
            fabsf((f1 - f2) * s + rv1 - rv2);
    }
    __syncthreads();
#pragma unroll
    for (int p = 0; p < 4; p++) {
        int nl = ty + 8 * p;
        float d1 = d1s[tx][nl];
        float d2 = d2s[tx][nl];
        __nv_bfloat16 h1, l1, h2, l2;
        bsplit(d1, h1, l1);
        bsplit(d2, h2, l2);
        __nv_bfloat16* orow = dsplit + (long long)b * (4096LL * 512)
                            + (long long)(n0 + nl) * 512;
        orow[c0 + tx]       = h1;
        orow[128 + c0 + tx] = h2;
        orow[256 + c0 + tx] = l1;
        orow[384 + c0 + tx] = l2;
    }
}

// fused column softmax: stats + normalize + split -> aT2 [B,4096,2048] (hi|lo)
__global__ void colsoftmax_k(const float* __restrict__ lt,
                             __nv_bfloat16* __restrict__ out)
{
    __shared__ float smx[16][65], ssm[16][65];
    __shared__ float cmx[64], csi[64];
    const int b = blockIdx.y;
    const int c = threadIdx.x & 63, g = threadIdx.x >> 6;
    const int col = blockIdx.x * 64 + c;
    const float* p = lt + (long long)b * 4194304 + col;
    float mx = -1e30f, sm = 0.f;
    for (int m = g; m < 4096; m += 16) {
        float x = p[(long long)m * 1024];
        float nm = fmaxf(mx, x);
        sm = sm * __expf(mx - nm) + __expf(x - nm);
        mx = nm;
    }
    smx[g][c] = mx; ssm[g][c] = sm;
    __syncthreads();
    if (g == 0) {
        float MX = smx[0][c], SM = ssm[0][c];
#pragma unroll
        for (int k = 1; k < 16; k++) {
            float m2 = smx[k][c], s2 = ssm[k][c];
            float nm = fmaxf(MX, m2);
            SM = SM * __expf(MX - nm) + s2 * __expf(m2 - nm);
            MX = nm;
        }
        cmx[c] = MX;
        csi[c] = 1.f / SM;
    }
    __syncthreads();
    const float MX = cmx[c], SI = csi[c];
    __nv_bfloat16* ob = out + (long long)b * (4096LL * 2048) + col;
    for (int m = g; m < 4096; m += 16) {
        float e = __expf(p[(long long)m * 1024] - MX) * SI;
        __nv_bfloat16 h, l; bsplit(e, h, l);
        ob[(long long)m * 2048]        = h;
        ob[(long long)m * 2048 + 1024] = l;
    }
}

// ===========================================================================
// scalar auxiliary kernels
// ===========================================================================
__global__ void cos_k(const float* __restrict__ r1, const float* __restrict__ r2,
                      float* __restrict__ sim)
{
    int gid  = blockIdx.x * blockDim.x + threadIdx.x;
    int wid  = gid >> 5;
    int lane = gid & 31;
    if (wid >= 4 * 4096) return;
    const float* a = r1 + (long long)wid * 128;
    const float* c = r2 + (long long)wid * 128;
    float dot = 0.f, na = 0.f, nb = 0.f;
#pragma unroll
    for (int i = 0; i < 4; i++) {
        float x = a[lane + 32 * i], y = c[lane + 32 * i];
        dot += x * y; na += x * x; nb += y * y;
    }
#pragma unroll
    for (int o = 16; o; o >>= 1) {
        dot += __shfl_xor_sync(0xffffffffu, dot, o);
        na  += __shfl_xor_sync(0xffffffffu, na,  o);
        nb  += __shfl_xor_sync(0xffffffffu, nb,  o);
    }
    if (lane == 0)
        sim[wid] = dot / fmaxf(sqrtf(na) * sqrtf(nb), 1e-8f);
}

__global__ void pool_k(const float* __restrict__ absd, float* __restrict__ simp)
{
    int i = blockIdx.x * 256 + threadIdx.x;
    if (i >= 524288) return;
    int wp = i & 31, hp = (i >> 5) & 31, bc = i >> 10;
    const float* a = absd + (long long)bc * 4096 + (hp * 2) * 64 + wp * 2;
    simp[i] = 0.25f * (a[0] + a[1] + a[64] + a[65]);
}

__global__ void resize_k(const float* __restrict__ in, float* __restrict__ out)
{
    long long i = (long long)blockIdx.x * 256 + threadIdx.x;
    if (i >= 8388608LL) return;
    int x = (int)(i & 127), y = (int)((i >> 7) & 127);
    long long bc = i >> 14;
    float sx = (x + 0.5f) * 0.5f - 0.5f;
    float sy = (y + 0.5f) * 0.5f - 0.5f;
    int x0 = (int)floorf(sx), y0 = (int)floorf(sy);
    float fx = sx - x0, fy = sy - y0;
    int x1 = min(x0 + 1, 63), y1 = min(y0 + 1, 63);
    x0 = max(x0, 0); y0 = max(y0, 0);
    const float* p = in + bc * 4096;
    float v = (1.f - fy) * ((1.f - fx) * p[y0 * 64 + x0] + fx * p[y0 * 64 + x1])
            +        fy  * ((1.f - fx) * p[y1 * 64 + x0] + fx * p[y1 * 64 + x1]);
    out[i] = v;
}

// ---------------------------------------------------------------------------
extern "C" void kernel_launch(void* const* d_in, const int* in_sizes, int n_in,
                              void* d_out, int out_size)
{
    (void)in_sizes; (void)n_in; (void)out_size;
    const float* t1      = (const float*)d_in[0];
    const float* t2      = (const float*)d_in[1];
    const float* t1_w    = (const float*)d_in[2];
    const float* t1_b    = (const float*)d_in[3];
    const float* t2_w    = (const float*)d_in[4];
    const float* t2_b    = (const float*)d_in[5];
    const float* df_res_w = (const float*)d_in[6];
    const float* df_res_b = (const float*)d_in[7];
    const float* df_res_s = (const float*)d_in[8];
    const float* df_res_o = (const float*)d_in[9];
    const float* df_b0_w = (const float*)d_in[10];
    const float* df_b0_b = (const float*)d_in[11];
    const float* df_b0_s = (const float*)d_in[12];
    const float* df_b0_o = (const float*)d_in[13];
    const float* df_b1_w = (const float*)d_in[14];
    const float* df_b1_b = (const float*)d_in[15];
    const float* df_b1_s = (const float*)d_in[16];
    const float* df_b1_o = (const float*)d_in[17];
    const float* df_fu_w = (const float*)d_in[18];
    const float* df_fu_b = (const float*)d_in[19];
    const float* df_fu_s = (const float*)d_in[20];
    const float* df_fu_o = (const float*)d_in[21];
    const float* br1_w   = (const float*)d_in[22];
    const float* br1_b   = (const float*)d_in[23];
    const float* br2_w   = (const float*)d_in[24];
    const float* br2_b   = (const float*)d_in[25];
    const float* fu_w    = (const float*)d_in[26];
    const float* fu_b    = (const float*)d_in[27];
    const float* fu_s    = (const float*)d_in[28];
    const float* fu_o    = (const float*)d_in[29];
    float* out = (float*)d_out;

    float* S;
    cudaGetSymbolAddress((void**)&S, g_scratch);
    __nv_bfloat16* G;
    cudaGetSymbolAddress((void**)&G, g_bf);

    cudaFuncSetAttribute(hmma_gemm, cudaFuncAttributeMaxDynamicSharedMemorySize, 110592);
    cudaFuncSetAttribute(hconv_tap<3, 64>,  cudaFuncAttributeMaxDynamicSharedMemorySize, 104448);
    cudaFuncSetAttribute(hconv_tap<5, 64>,  cudaFuncAttributeMaxDynamicSharedMemorySize, 104448);
    cudaFuncSetAttribute(hconv_tap<3, 128>, cudaFuncAttributeMaxDynamicSharedMemorySize, 139264);
    cudaFuncSetAttribute(hconv_tap<5, 128>, cudaFuncAttributeMaxDynamicSharedMemorySize, 139264);

    float* res1    = S + F_RES1;
    float* res2    = S + F_RES2;
    float* sim     = S + F_SIM;
    float* absd    = S + F_ABSD;
    float* simp    = S + F_SIMP;
    float* rbuf    = S + F_R;
    float* b0b1    = S + F_B0B1;
    float* dif     = S + F_DIF;
    float* inc     = S + F_INC;
    float* logitsT = S + F_LOG;
    float* acat    = S + F_ACAT;
    float* fuse    = S + F_FUSE;

    const long long S128 = 128LL * 4096;
    const long long S256 = 256LL * 4096;

    // weight splits (merged)
    wsplit5_k<<<dim3(128, 5), 256>>>(t1_w, t2_w, df_res_w, fu_w, df_fu_w,
                                     G + W_T1W2, G + W_T2W2, G + W_RESW2,
                                     G + W_FUW2, G + W_DFUW2);
    wsplit_tap4_k<<<dim3(1600, 4), 256>>>(df_b0_w, df_b1_w, br1_w, br2_w,
                                          G + W_B0T, G + W_B1T,
                                          G + W_BR1T, G + W_BR2T);
    // input splits
    tsplit2_k<<<dim3(128, 8, 4), 256>>>(t1, G + G_T3A, 256, 4096);
    tsplit2_k<<<dim3(128, 8, 4), 256>>>(t2, G + G_T3B, 256, 4096);
    // 1. res1/res2 = 1x1 (256->128) + bias
    hmma_gemm<<<dim3(32, 1, 4), 256, 110592>>>(G + W_T1W2, G + G_T3A, res1,
                                               t1_b, nullptr, nullptr, nullptr,
                                               256, 4096, 0, 4096LL * 512, S128, 0);
    hmma_gemm<<<dim3(32, 1, 4), 256, 110592>>>(G + W_T2W2, G + G_T3B, res2,
                                               t2_b, nullptr, nullptr, nullptr,
                                               256, 4096, 0, 4096LL * 512, S128, 0);
    // 2-4. cosine, fused dif-split (into G_T3A), avgpool, attn operands
    cos_k<<<2048, 256>>>(res1, res2, sim);
    difsim_split_k<<<dim3(128, 4, 4), 256>>>(res1, res2, sim, G + G_T3A, absd);
    pool_k<<<2048, 256>>>(absd, simp);
    split2row_k<<<2048, 256>>>(simp, G + G_ATTN2);
    tsplit2_k<<<dim3(4, 32, 4), 256>>>(simp, G + G_ATTNT2, 1024, 128);
    // 5. r = stdconv 1x1 (256->128)
    hmma_gemm<<<dim3(32, 1, 4), 256, 110592>>>(G + W_RESW2, G + G_T3A, rbuf,
                                               df_res_b, df_res_s, df_res_o, nullptr,
                                               256, 4096, 0, 4096LL * 512, S128, 0);
    // 6/7. inception branches over shared rbuf-split
    tsplit2_k<<<dim3(128, 4, 4), 256>>>(rbuf, G + G_RB2, 128, 4096);
    hconv_tap<3, 64><<<dim3(32, 1, 4), 256, 104448>>>(
        G + W_B0T, G + G_RB2, b0b1, df_b0_b, df_b0_s, df_b0_o, S128);
    hconv_tap<5, 64><<<dim3(32, 1, 4), 256, 104448>>>(
        G + W_B1T, G + G_RB2, b0b1 + 64LL * 4096, df_b1_b, df_b1_s, df_b1_o, S128);
    // 8. dif = stdconv 1x1 (128->128) + r
    tsplit2_k<<<dim3(128, 4, 4), 256>>>(b0b1, G + G_BB2, 128, 4096);
    hmma_gemm<<<dim3(32, 1, 4), 256, 110592>>>(G + W_DFUW2, G + G_BB2, dif,
                                               df_fu_b, df_fu_s, df_fu_o, rbuf,
                                               128, 4096, 0, 4096LL * 256, S128, S128);
    tsplit2_k<<<dim3(128, 4, 4), 256>>>(dif, G + G_DIF2, 128, 4096);
    // --- attention branches ---
    for (int br = 0; br < 2; br++) {
        if (br == 0)
            hconv_tap<3, 128><<<dim3(32, 1, 4), 256, 139264>>>(
                G + W_BR1T, G + G_DIF2, inc, br1_b, nullptr, nullptr, S128);
        else
            hconv_tap<5, 128><<<dim3(32, 1, 4), 256, 139264>>>(
                G + W_BR2T, G + G_DIF2, inc, br2_b, nullptr, nullptr, S128);
        tsplit2_k<<<dim3(128, 4, 4), 256>>>(inc, G + G_INCT2, 128, 4096);
        // logitsT[b, pix, tok] = incT . attn
        hmma_gemm<<<dim3(8, 32, 4), 256, 110592>>>(G + G_INCT2, G + G_ATTN2, logitsT,
                                                   nullptr, nullptr, nullptr, nullptr,
                                                   128, 1024,
                                                   4096LL * 256, 1024LL * 256,
                                                   4096LL * 1024, 0);
        colsoftmax_k<<<dim3(16, 4), 1024>>>(logitsT, G + G_AT2);
        // out[b, c, pix] = attnT . aT + inc  -> acat half
        hmma_gemm<<<dim3(32, 1, 4), 256, 110592>>>(G + G_ATTNT2, G + G_AT2,
                                                   acat + (long long)br * S128,
                                                   nullptr, nullptr, nullptr, inc,
                                                   1024, 4096,
                                                   128LL * 2048, 4096LL * 2048,
                                                   S256, S128);
    }
    // 14. fused = stdconv 1x1 (256->128) + dif
    tsplit2_k<<<dim3(128, 8, 4), 256>>>(acat, G + G_T3A, 256, 4096);
    hmma_gemm<<<dim3(32, 1, 4), 256, 110592>>>(G + W_FUW2, G + G_T3A, fuse,
                                               fu_b, fu_s, fu_o, dif,
                                               256, 4096, 0, 4096LL * 512, S128, S128);
    // 15. bilinear x2 upsample
    resize_k<<<32768, 256>>>(fuse, out);
}

// round 15
// speedup vs baseline: 1.5317x; 1.0346x over previous
#include <cuda_runtime.h>
#include <cuda_bf16.h>
#include <cstdint>

// ===========================================================================
// B=4, C_IN=256, C=128, H=W=64, HW=4096. out [4,128,128,128] f32.
// ALL dense ops on mma.sync bf16 HMMA, 2-term split (storage [hi|lo],
// 3-segment schedule). Convs = per-tap shifted GEMMs, k-chunk 128, 2-stage.
// Round 15: attention branches merged over z = batch*2 + branch.
// ===========================================================================

#define F_RES1 0LL
#define F_RES2 (F_RES1 + 2097152)
#define F_SIM  (F_RES2 + 2097152)
#define F_ABSD (F_SIM  + 16384)
#define F_SIMP (F_ABSD + 2097152)
#define F_R    (F_SIMP + 524288)
#define F_B0B1 (F_R    + 2097152)
#define F_DIF  (F_B0B1 + 2097152)
#define F_INC  (F_DIF  + 2097152)      /* [8][128*4096] z = b*2+br */
#define F_LOG  (F_INC  + 4194304)      /* [8][4096][1024]          */
#define F_ACAT (F_LOG  + 33554432)
#define F_FUSE (F_ACAT + 4194304)
#define F_TOTAL (F_FUSE + 2097152)

__device__ float g_scratch[F_TOTAL];

// bf16 scratch element offsets (2-segment layouts)
#define W_T1W2   0LL          /* [128,512]        */
#define W_T2W2   65536LL
#define W_RESW2  131072LL
#define W_FUW2   196608LL
#define W_DFUW2  262144LL     /* [128,256]        */
#define W_B0T    294912LL     /* [9][64][256]     */
#define W_B1T    442368LL     /* [25][64][256]    */
#define W_BR1T   851968LL     /* [9][128][256]    */
#define W_BR2T   1146880LL    /* [25][128][256]   */
#define G_ATTN2  1966080LL    /* [4,1024,256]     */
#define G_INCT2  3014656LL    /* [8,4096,256]     */
#define G_ATTNT2 11403264LL   /* [4,128,2048]     */
#define G_AT2    12451840LL   /* [8,4096,2048]    */
#define G_T3A    79560704LL   /* [4,4096,512]     */
#define G_T3B    87949312LL   /* [4,4096,512]     */
#define G_RB2    96337920LL   /* [4,4096,256]     */
#define G_DIF2   100532224LL  /* [4,4096,256]     */
#define G_BB2    104726528LL  /* [4,4096,256]     */
#define G_TOTAL  108920832LL

__device__ __align__(256) __nv_bfloat16 g_bf[G_TOTAL];

// ------------------------------ helpers ------------------------------------
__device__ __forceinline__ uint32_t smem_u32(const void* p) {
    uint32_t a;
    asm("{ .reg .u64 t; cvta.to.shared.u64 t, %1; cvt.u32.u64 %0, t; }"
        : "=r"(a) : "l"(p));
    return a;
}
__device__ __forceinline__ void bsplit(float x, __nv_bfloat16& h, __nv_bfloat16& l) {
    h = __float2bfloat16(x);
    l = __float2bfloat16(x - __bfloat162float(h));
}
#define CP_ASYNC(dst, src) asm volatile( \
    "cp.async.cg.shared.global [%0], [%1], 16;" :: "r"(dst), "l"(src))
#define CP_ASYNC_Z(dst, src, sz) asm volatile( \
    "cp.async.cg.shared.global [%0], [%1], 16, %2;" :: "r"(dst), "l"(src), "r"(sz))
#define CP_COMMIT() asm volatile("cp.async.commit_group;" ::: "memory")
#define CP_WAIT1()  asm volatile("cp.async.wait_group 1;" ::: "memory")
#define CP_WAIT0()  asm volatile("cp.async.wait_group 0;" ::: "memory")
#define LDM_X4(r0, r1, r2, r3, a) asm volatile( \
    "ldmatrix.sync.aligned.m8n8.x4.shared.b16 {%0,%1,%2,%3}, [%4];" \
    : "=r"(r0), "=r"(r1), "=r"(r2), "=r"(r3) : "r"(a))
#define MMA16816(d, a, bfr) asm volatile( \
    "mma.sync.aligned.m16n8k16.row.col.f32.bf16.bf16.f32 " \
    "{%0,%1,%2,%3}, {%4,%5,%6,%7}, {%8,%9}, {%0,%1,%2,%3};" \
    : "+f"((d)[0]), "+f"((d)[1]), "+f"((d)[2]), "+f"((d)[3]) \
    : "r"((a)[0]), "r"((a)[1]), "r"((a)[2]), "r"((a)[3]), \
      "r"((bfr)[0]), "r"((bfr)[1]))

// ===========================================================================
// hmma_gemm: 128x128 tile, 8 warps (32m x 64n), chunk k=64, 3-stage cp.async.
// A2 [.., 2*Kcore], B2 [.., 2*Kcore] bf16 (hi|lo); 3-segment schedule.
// A batch index = z >> azshift; B batch index = z >> bzshift; C/resid use z.
// Row stride 144B. dyn smem = 110592.
// ===========================================================================
__global__ void __launch_bounds__(256) hmma_gemm(
    const __nv_bfloat16* __restrict__ A2, const __nv_bfloat16* __restrict__ B2,
    float* __restrict__ C,
    const float* __restrict__ bias, const float* __restrict__ scale,
    const float* __restrict__ off, const float* __restrict__ resid,
    int Kcore, int Ncols,
    long long Abs, long long Bbs, long long Cbs, long long Rbs,
    int azshift, int bzshift)
{
    extern __shared__ __align__(16) char smbuf[];
    const uint32_t sA = smem_u32(smbuf);          // 3 stages x 18432
    const uint32_t sB = sA + 55296;               // 3 stages x 18432
    const int t = threadIdx.x, lane = t & 31, wid = t >> 5;
    const int wm = wid & 3, wn = wid >> 2;
    const int z  = blockIdx.z;
    const int m0 = blockIdx.y * 128;
    const int n0 = blockIdx.x * 128;
    const int Kp = 2 * Kcore;
    const __nv_bfloat16* Ab = A2 + (long long)(z >> azshift) * Abs + (long long)m0 * Kp;
    const __nv_bfloat16* Bb = B2 + (long long)(z >> bzshift) * Bbs + (long long)n0 * Kp;

    float acc[2][8][4];
#pragma unroll
    for (int i = 0; i < 2; i++)
#pragma unroll
        for (int j = 0; j < 8; j++)
#pragma unroll
            for (int r = 0; r < 4; r++) acc[i][j][r] = 0.f;

    const int nchseg = Kcore >> 6;
    auto ldch = [&](int gc) {
        const int seg = (gc >= nchseg) + (gc >= 2 * nchseg);
        const int cc  = gc - seg * nchseg;
        const int aco = (seg == 1 ? Kcore : 0) + cc * 64;
        const int bco = (seg == 2 ? Kcore : 0) + cc * 64;
        const uint32_t ao = sA + (gc % 3) * 18432;
        const uint32_t bo = sB + (gc % 3) * 18432;
#pragma unroll
        for (int r = 0; r < 4; r++) {
            int f = t + 256 * r, row = f >> 3, kq = f & 7;
            CP_ASYNC(ao + (uint32_t)(row * 144 + kq * 16),
                     Ab + (long long)row * Kp + aco + kq * 8);
            CP_ASYNC(bo + (uint32_t)(row * 144 + kq * 16),
                     Bb + (long long)row * Kp + bco + kq * 8);
        }
        CP_COMMIT();
    };

    const int NC = 3 * nchseg;
    ldch(0);
    ldch(1);
    for (int gc = 0; gc < NC; gc++) {
        if (gc + 1 < NC) CP_WAIT1(); else CP_WAIT0();
        __syncthreads();
        if (gc + 2 < NC) ldch(gc + 2);
        const uint32_t ao = sA + (gc % 3) * 18432;
        const uint32_t bo = sB + (gc % 3) * 18432;
#pragma unroll
        for (int ks = 0; ks < 4; ks++) {
            const int kb = ks * 16;
            uint32_t af[2][4];
#pragma unroll
            for (int i = 0; i < 2; i++) {
                int row = wm * 32 + i * 16 + (lane & 7) + ((lane >> 3) & 1) * 8;
                int col = kb + ((lane >> 4) & 1) * 8;
                LDM_X4(af[i][0], af[i][1], af[i][2], af[i][3],
                       ao + (uint32_t)(row * 144 + col * 2));
            }
            uint32_t bfr[8][2];
#pragma unroll
            for (int jp = 0; jp < 4; jp++) {
                int n = wn * 64 + jp * 16 + (lane & 7) + ((lane >> 4) & 1) * 8;
                int k = kb + ((lane >> 3) & 1) * 8;
                LDM_X4(bfr[2 * jp][0], bfr[2 * jp][1],
                       bfr[2 * jp + 1][0], bfr[2 * jp + 1][1],
                       bo + (uint32_t)(n * 144 + k * 2));
            }
#pragma unroll
            for (int i = 0; i < 2; i++)
#pragma unroll
                for (int j = 0; j < 8; j++)
                    MMA16816(acc[i][j], af[i], bfr[j]);
        }
    }

    float* Cb = C + (long long)z * Cbs;
    const float* Rb = resid ? resid + (long long)z * Rbs : nullptr;
#pragma unroll
    for (int i = 0; i < 2; i++)
#pragma unroll
        for (int h = 0; h < 2; h++) {
            int m = m0 + wm * 32 + i * 16 + (lane >> 2) + h * 8;
            float bi = bias  ? bias[m]  : 0.f;
            float sc = scale ? scale[m] : 1.f;
            float ofv = off  ? off[m]   : 0.f;
            float* crow = Cb + (long long)m * Ncols;
            const float* rrow = Rb ? Rb + (long long)m * Ncols : nullptr;
#pragma unroll
            for (int j = 0; j < 8; j++) {
                int col = n0 + wn * 64 + j * 8 + (lane & 3) * 2;
                float2 v = make_float2(acc[i][j][h * 2 + 0] + bi,
                                       acc[i][j][h * 2 + 1] + bi);
                if (scale) {
                    v.x = fmaxf(v.x, 0.f) * sc + ofv;
                    v.y = fmaxf(v.y, 0.f) * sc + ofv;
                }
                if (rrow) {
                    float2 rv = *(const float2*)(rrow + col);
                    v.x += rv.x; v.y += rv.y;
                }
                *(float2*)(crow + col) = v;
            }
        }
}

// ===========================================================================
// hconv_tap: conv KSxKS (pad KS/2) as per-tap shifted GEMMs, Kcore=128/tap.
// k-chunk 128 (one segment per chunk), 2-stage, row stride 272B.
// ===========================================================================
template <int KS, int MT>
__global__ void __launch_bounds__(256) hconv_tap(
    const __nv_bfloat16* __restrict__ W2t, const __nv_bfloat16* __restrict__ Bsplit,
    float* __restrict__ out,
    const float* __restrict__ bias, const float* __restrict__ scale,
    const float* __restrict__ off, long long out_bstride)
{
    constexpr int P    = KS / 2;
    constexpr int TAPS = KS * KS;
    constexpr int NC   = TAPS * 3;
    constexpr int WM_N = MT / 32;
    constexpr int WN_N = 8 / WM_N;
    constexpr int NJ   = 128 / (WN_N * 8);
    constexpr int ASTG = MT * 272;
    extern __shared__ __align__(16) char smbuf[];
    const uint32_t sA = smem_u32(smbuf);
    const uint32_t sB = sA + 2 * ASTG;
    const int t = threadIdx.x, lane = t & 31, wid = t >> 5;
    const int wm = wid % WM_N, wn = wid / WM_N;
    const int b  = blockIdx.z;
    const int n0 = blockIdx.x * 128;
    const __nv_bfloat16* Bb = Bsplit + (long long)b * (4096LL * 256);

    float acc[2][NJ][4];
#pragma unroll
    for (int i = 0; i < 2; i++)
#pragma unroll
        for (int j = 0; j < NJ; j++)
#pragma unroll
            for (int r = 0; r < 4; r++) acc[i][j][r] = 0.f;

    auto ldch = [&](int gc) {
        const int tap = gc / 3;
        const int seg = gc - tap * 3;
        const int aco = (seg == 1 ? 128 : 0);
        const int bco = (seg == 2 ? 128 : 0);
        const int dy  = tap / KS - P, dx = tap - (tap / KS) * KS - P;
        const int shift = dy * 64 + dx;
        const uint32_t ao = sA + (gc & 1) * ASTG;
        const uint32_t bo = sB + (gc & 1) * 34816;
#pragma unroll
        for (int r = 0; r < MT / 16; r++) {
            int f = t + 256 * r, row = f >> 4, kq = f & 15;
            CP_ASYNC(ao + (uint32_t)(row * 272 + kq * 16),
                     W2t + (long long)tap * (MT * 256) + (long long)row * 256
                         + aco + kq * 8);
        }
#pragma unroll
        for (int r = 0; r < 8; r++) {
            int f = t + 256 * r, row = f >> 4, kq = f & 15;
            int gpix = n0 + row;
            int y = gpix >> 6, x = gpix & 63;
            bool ok = ((unsigned)(y + dy) < 64u) && ((unsigned)(x + dx) < 64u);
            int spix = ok ? (gpix + shift) : 0;
            uint32_t sz = ok ? 16u : 0u;
            CP_ASYNC_Z(bo + (uint32_t)(row * 272 + kq * 16),
                       Bb + (long long)spix * 256 + bco + kq * 8, sz);
        }
        CP_COMMIT();
    };

    ldch(0);
    for (int gc = 0; gc < NC; gc++) {
        CP_WAIT0();
        __syncthreads();
        if (gc + 1 < NC) ldch(gc + 1);
        const uint32_t ao = sA + (gc & 1) * ASTG;
        const uint32_t bo = sB + (gc & 1) * 34816;
#pragma unroll
        for (int ks = 0; ks < 8; ks++) {
            const int kb = ks * 16;
            uint32_t af[2][4];
#pragma unroll
            for (int i = 0; i < 2; i++) {
                int row = wm * 32 + i * 16 + (lane & 7) + ((lane >> 3) & 1) * 8;
                int col = kb + ((lane >> 4) & 1) * 8;
                LDM_X4(af[i][0], af[i][1], af[i][2], af[i][3],
                       ao + (uint32_t)(row * 272 + col * 2));
            }
            uint32_t bfr[NJ][2];
#pragma unroll
            for (int jp = 0; jp < NJ / 2; jp++) {
                int n = wn * (NJ * 8) + jp * 16 + (lane & 7) + ((lane >> 4) & 1) * 8;
                int k = kb + ((lane >> 3) & 1) * 8;
                LDM_X4(bfr[2 * jp][0], bfr[2 * jp][1],
                       bfr[2 * jp + 1][0], bfr[2 * jp + 1][1],
                       bo + (uint32_t)(n * 272 + k * 2));
            }
#pragma unroll
            for (int i = 0; i < 2; i++)
#pragma unroll
                for (int j = 0; j < NJ; j++)
                    MMA16816(acc[i][j], af[i], bfr[j]);
        }
    }

    float* Ob = out + (long long)b * out_bstride;
#pragma unroll
    for (int i = 0; i < 2; i++)
#pragma unroll
        for (int h = 0; h < 2; h++) {
            int m = wm * 32 + i * 16 + (lane >> 2) + h * 8;
            float bi = bias[m];
            float sc = scale ? scale[m] : 1.f;
            float ofv = off ? off[m] : 0.f;
            float* crow = Ob + (long long)m * 4096;
#pragma unroll
            for (int j = 0; j < NJ; j++) {
                int col = n0 + wn * (NJ * 8) + j * 8 + (lane & 3) * 2;
                float2 v = make_float2(acc[i][j][h * 2 + 0] + bi,
                                       acc[i][j][h * 2 + 1] + bi);
                if (scale) {
                    v.x = fmaxf(v.x, 0.f) * sc + ofv;
                    v.y = fmaxf(v.y, 0.f) * sc + ofv;
                }
                *(float2*)(crow + col) = v;
            }
        }
}

// ===========================================================================
// prep kernels (2-segment [hi|lo])
// ===========================================================================
__global__ void wsplit5_k(const float* s0, const float* s1, const float* s2,
                          const float* s3, const float* s4,
                          __nv_bfloat16* d0, __nv_bfloat16* d1, __nv_bfloat16* d2,
                          __nv_bfloat16* d3, __nv_bfloat16* d4)
{
    const int seg = blockIdx.y;
    const float* src; __nv_bfloat16* dst; int K, total;
    switch (seg) {
        case 0: src = s0; dst = d0; K = 256; total = 32768; break;
        case 1: src = s1; dst = d1; K = 256; total = 32768; break;
        case 2: src = s2; dst = d2; K = 256; total = 32768; break;
        case 3: src = s3; dst = d3; K = 256; total = 32768; break;
        default: src = s4; dst = d4; K = 128; total = 16384; break;
    }
    int i = blockIdx.x * 256 + threadIdx.x;
    if (i >= total) return;
    int m = i / K, k = i - m * K;
    __nv_bfloat16 h, l; bsplit(src[i], h, l);
    __nv_bfloat16* o = dst + (long long)m * 2 * K + k;
    o[0] = h; o[K] = l;
}

__global__ void wsplit_tap4_k(const float* w0, const float* w1,
                              const float* w2, const float* w3,
                              __nv_bfloat16* d0, __nv_bfloat16* d1,
                              __nv_bfloat16* d2, __nv_bfloat16* d3)
{
    const int seg = blockIdx.y;
    const float* src; __nv_bfloat16* dst; int Cout, KS2, total;
    switch (seg) {
        case 0: src = w0; dst = d0; Cout = 64;  KS2 = 9;  total = 73728;  break;
        case 1: src = w1; dst = d1; Cout = 64;  KS2 = 25; total = 204800; break;
        case 2: src = w2; dst = d2; Cout = 128; KS2 = 9;  total = 147456; break;
        default: src = w3; dst = d3; Cout = 128; KS2 = 25; total = 409600; break;
    }
    int i = blockIdx.x * 256 + threadIdx.x;
    if (i >= total) return;
    int co = i / (128 * KS2);
    int rem = i - co * 128 * KS2;
    int ci = rem / KS2;
    int tap = rem - ci * KS2;
    __nv_bfloat16 h, l; bsplit(src[i], h, l);
    __nv_bfloat16* o = dst + (long long)tap * Cout * 256 + (long long)co * 256 + ci;
    o[0] = h; o[128] = l;
}

// transpose+split: in [Z,R,Ncol] f32 -> out [Z,Ncol,2R] bf16 (hi|lo), z direct
__global__ void tsplit2_k(const float* __restrict__ in, __nv_bfloat16* __restrict__ out,
                          int R, int Ncol)
{
    __shared__ float tile[32][33];
    const int b = blockIdx.z, r0 = blockIdx.y * 32, n0 = blockIdx.x * 32;
    const int tx = threadIdx.x & 31, ty = threadIdx.x >> 5;
    const float* ib = in + (long long)b * R * Ncol;
#pragma unroll
    for (int p = 0; p < 4; p++)
        tile[ty + 8 * p][tx] = ib[(long long)(r0 + ty + 8 * p) * Ncol + n0 + tx];
    __syncthreads();
    __nv_bfloat16* ob = out + (long long)b * Ncol * 2 * R;
#pragma unroll
    for (int p = 0; p < 4; p++) {
        int n = n0 + ty + 8 * p, r = r0 + tx;
        float x = tile[tx][ty + 8 * p];
        __nv_bfloat16 h, l; bsplit(x, h, l);
        __nv_bfloat16* o = ob + (long long)n * 2 * R;
        o[r] = h; o[R + r] = l;
    }
}

__global__ void split2row_k(const float* __restrict__ in, __nv_bfloat16* __restrict__ out)
{
    int i = blockIdx.x * 256 + threadIdx.x;
    float x = in[i];
    __nv_bfloat16 h, l; bsplit(x, h, l);
    long long row = i >> 7; int c = i & 127;
    __nv_bfloat16* o = out + row * 256 + c;
    o[0] = h; o[128] = l;
}

// fused difsim: absd f32 AND difcat split operand [B,4096,512] (hi(256)|lo(256))
__global__ void difsim_split_k(const float* __restrict__ r1, const float* __restrict__ r2,
                               const float* __restrict__ sim,
                               __nv_bfloat16* __restrict__ dsplit,
                               float* __restrict__ absd)
{
    __shared__ float f1s[32][33], f2s[32][33], d1s[32][33], d2s[32][33], ss[32];
    const int b  = blockIdx.z;
    const int c0 = blockIdx.y * 32;
    const int n0 = blockIdx.x * 32;
    const int t  = threadIdx.x;
    const int tx = t & 31, ty = t >> 5;
    const long long BS = 524288;
    const float* r1b = r1 + (long long)b * BS;
    const float* r2b = r2 + (long long)b * BS;
#pragma unroll
    for (int r = 0; r < 4; r++) {
        int n = ty + 8 * r;
        f1s[n][tx] = r1b[(long long)(n0 + n) * 128 + c0 + tx];
        f2s[n][tx] = r2b[(long long)(n0 + n) * 128 + c0 + tx];
    }
    if (t < 32) ss[t] = sim[b * 4096 + n0 + t];
    __syncthreads();
#pragma unroll
    for (int r = 0; r < 4; r++) {
        int cl = ty + 8 * r;
        int c = c0 + cl;
        int n = n0 + tx;
        float rv1 = r1b[(long long)c * 4096 + n];
        float rv2 = r2b[(long long)c * 4096 + n];
        float s  = ss[tx];
        float f1 = f1s[tx][cl];
        float f2 = f2s[tx][cl];
        float omns = 1.f - s;
        d1s[cl][tx] = f1 * omns + rv1;
        d2s[cl][tx] = f2 * omns + rv2;
        absd[(long long)b * BS + (long long)c * 4096 + n] =
            fabsf((f1 - f2) * s + rv1 - rv2);
    }
    __syncthreads();
#pragma unroll
    for (int p = 0; p < 4; p++) {
        int nl = ty + 8 * p;
        float d1 = d1s[tx][nl];
        float d2 = d2s[tx][nl];
        __nv_bfloat16 h1, l1, h2, l2;
        bsplit(d1, h1, l1);
        bsplit(d2, h2, l2);
        __nv_bfloat16* orow = dsplit + (long long)b * (4096LL * 512)
                            + (long long)(n0 + nl) * 512;
        orow[c0 + tx]       = h1;
        orow[128 + c0 + tx] = h2;
        orow[256 + c0 + tx] = l1;
        orow[384 + c0 + tx] = l2;
    }
}

// fused column softmax over logitsT [Z,4096,1024] -> aT2 [Z,4096,2048] (hi|lo)
// grid (16, Z), block 1024
__global__ void colsoftmax_k(const float* __restrict__ lt,
                             __nv_bfloat16* __restrict__ out)
{
    __shared__ float smx[16][65], ssm[16][65];
    __shared__ float cmx[64], csi[64];
    const int z = blockIdx.y;
    const int c = threadIdx.x & 63, g = threadIdx.x >> 6;
    const int col = blockIdx.x * 64 + c;
    const float* p = lt + (long long)z * 4194304 + col;
    float mx = -1e30f, sm = 0.f;
    for (int m = g; m < 4096; m += 16) {
        float x = p[(long long)m * 1024];
        float nm = fmaxf(mx, x);
        sm = sm * __expf(mx - nm) + __expf(x - nm);
        mx = nm;
    }
    smx[g][c] = mx; ssm[g][c] = sm;
    __syncthreads();
    if (g == 0) {
        float MX = smx[0][c], SM = ssm[0][c];
#pragma unroll
        for (int k = 1; k < 16; k++) {
            float m2 = smx[k][c], s2 = ssm[k][c];
            float nm = fmaxf(MX, m2);
            SM = SM * __expf(MX - nm) + s2 * __expf(m2 - nm);
            MX = nm;
        }
        cmx[c] = MX;
        csi[c] = 1.f / SM;
    }
    __syncthreads();
    const float MX = cmx[c], SI = csi[c];
    __nv_bfloat16* ob = out + (long long)z * (4096LL * 2048) + col;
    for (int m = g; m < 4096; m += 16) {
        float e = __expf(p[(long long)m * 1024] - MX) * SI;
        __nv_bfloat16 h, l; bsplit(e, h, l);
        ob[(long long)m * 2048]        = h;
        ob[(long long)m * 2048 + 1024] = l;
    }
}

// ===========================================================================
// scalar auxiliary kernels
// ===========================================================================
__global__ void cos_k(const float* __restrict__ r1, const float* __restrict__ r2,
                      float* __restrict__ sim)
{
    int gid  = blockIdx.x * blockDim.x + threadIdx.x;
    int wid  = gid >> 5;
    int lane = gid & 31;
    if (wid >= 4 * 4096) return;
    const float* a = r1 + (long long)wid * 128;
    const float* c = r2 + (long long)wid * 128;
    float dot = 0.f, na = 0.f, nb = 0.f;
#pragma unroll
    for (int i = 0; i < 4; i++) {
        float x = a[lane + 32 * i], y = c[lane + 32 * i];
        dot += x * y; na += x * x; nb += y * y;
    }
#pragma unroll
    for (int o = 16; o; o >>= 1) {
        dot += __shfl_xor_sync(0xffffffffu, dot, o);
        na  += __shfl_xor_sync(0xffffffffu, na,  o);
        nb  += __shfl_xor_sync(0xffffffffu, nb,  o);
    }
    if (lane == 0)
        sim[wid] = dot / fmaxf(sqrtf(na) * sqrtf(nb), 1e-8f);
}

__global__ void pool_k(const float* __restrict__ absd, float* __restrict__ simp)
{
    int i = blockIdx.x * 256 + threadIdx.x;
    if (i >= 524288) return;
    int wp = i & 31, hp = (i >> 5) & 31, bc = i >> 10;
    const float* a = absd + (long long)bc * 4096 + (hp * 2) * 64 + wp * 2;
    simp[i] = 0.25f * (a[0] + a[1] + a[64] + a[65]);
}

__global__ void resize_k(const float* __restrict__ in, float* __restrict__ out)
{
    long long i = (long long)blockIdx.x * 256 + threadIdx.x;
    if (i >= 8388608LL) return;
    int x = (int)(i & 127), y = (int)((i >> 7) & 127);
    long long bc = i >> 14;
    float sx = (x + 0.5f) * 0.5f - 0.5f;
    float sy = (y + 0.5f) * 0.5f - 0.5f;
    int x0 = (int)floorf(sx), y0 = (int)floorf(sy);
    float fx = sx - x0, fy = sy - y0;
    int x1 = min(x0 + 1, 63), y1 = min(y0 + 1, 63);
    x0 = max(x0, 0); y0 = max(y0, 0);
    const float* p = in + bc * 4096;
    float v = (1.f - fy) * ((1.f - fx) * p[y0 * 64 + x0] + fx * p[y0 * 64 + x1])
            +        fy  * ((1.f - fx) * p[y1 * 64 + x0] + fx * p[y1 * 64 + x1]);
    out[i] = v;
}

// ---------------------------------------------------------------------------
extern "C" void kernel_launch(void* const* d_in, const int* in_sizes, int n_in,
                              void* d_out, int out_size)
{
    (void)in_sizes; (void)n_in; (void)out_size;
    const float* t1      = (const float*)d_in[0];
    const float* t2      = (const float*)d_in[1];
    const float* t1_w    = (const float*)d_in[2];
    const float* t1_b    = (const float*)d_in[3];
    const float* t2_w    = (const float*)d_in[4];
    const float* t2_b    = (const float*)d_in[5];
    const float* df_res_w = (const float*)d_in[6];
    const float* df_res_b = (const float*)d_in[7];
    const float* df_res_s = (const float*)d_in[8];
    const float* df_res_o = (const float*)d_in[9];
    const float* df_b0_w = (const float*)d_in[10];
    const float* df_b0_b = (const float*)d_in[11];
    const float* df_b0_s = (const float*)d_in[12];
    const float* df_b0_o = (const float*)d_in[13];
    const float* df_b1_w = (const float*)d_in[14];
    const float* df_b1_b = (const float*)d_in[15];
    const float* df_b1_s = (const float*)d_in[16];
    const float* df_b1_o = (const float*)d_in[17];
    const float* df_fu_w = (const float*)d_in[18];
    const float* df_fu_b = (const float*)d_in[19];
    const float* df_fu_s = (const float*)d_in[20];
    const float* df_fu_o = (const float*)d_in[21];
    const float* br1_w   = (const float*)d_in[22];
    const float* br1_b   = (const float*)d_in[23];
    const float* br2_w   = (const float*)d_in[24];
    const float* br2_b   = (const float*)d_in[25];
    const float* fu_w    = (const float*)d_in[26];
    const float* fu_b    = (const float*)d_in[27];
    const float* fu_s    = (const float*)d_in[28];
    const float* fu_o    = (const float*)d_in[29];
    float* out = (float*)d_out;

    float* S;
    cudaGetSymbolAddress((void**)&S, g_scratch);
    __nv_bfloat16* G;
    cudaGetSymbolAddress((void**)&G, g_bf);

    cudaFuncSetAttribute(hmma_gemm, cudaFuncAttributeMaxDynamicSharedMemorySize, 110592);
    cudaFuncSetAttribute(hconv_tap<3, 64>,  cudaFuncAttributeMaxDynamicSharedMemorySize, 104448);
    cudaFuncSetAttribute(hconv_tap<5, 64>,  cudaFuncAttributeMaxDynamicSharedMemorySize, 104448);
    cudaFuncSetAttribute(hconv_tap<3, 128>, cudaFuncAttributeMaxDynamicSharedMemorySize, 139264);
    cudaFuncSetAttribute(hconv_tap<5, 128>, cudaFuncAttributeMaxDynamicSharedMemorySize, 139264);

    float* res1    = S + F_RES1;
    float* res2    = S + F_RES2;
    float* sim     = S + F_SIM;
    float* absd    = S + F_ABSD;
    float* simp    = S + F_SIMP;
    float* rbuf    = S + F_R;
    float* b0b1    = S + F_B0B1;
    float* dif     = S + F_DIF;
    float* inc     = S + F_INC;     // [8][128*4096], z = b*2 + br
    float* logitsT = S + F_LOG;     // [8][4096*1024]
    float* acat    = S + F_ACAT;
    float* fuse    = S + F_FUSE;

    const long long S128 = 128LL * 4096;

    // weight splits (merged)
    wsplit5_k<<<dim3(128, 5), 256>>>(t1_w, t2_w, df_res_w, fu_w, df_fu_w,
                                     G + W_T1W2, G + W_T2W2, G + W_RESW2,
                                     G + W_FUW2, G + W_DFUW2);
    wsplit_tap4_k<<<dim3(1600, 4), 256>>>(df_b0_w, df_b1_w, br1_w, br2_w,
                                          G + W_B0T, G + W_B1T,
                                          G + W_BR1T, G + W_BR2T);
    // input splits
    tsplit2_k<<<dim3(128, 8, 4), 256>>>(t1, G + G_T3A, 256, 4096);
    tsplit2_k<<<dim3(128, 8, 4), 256>>>(t2, G + G_T3B, 256, 4096);
    // 1. res1/res2 = 1x1 (256->128) + bias
    hmma_gemm<<<dim3(32, 1, 4), 256, 110592>>>(G + W_T1W2, G + G_T3A, res1,
                                               t1_b, nullptr, nullptr, nullptr,
                                               256, 4096, 0, 4096LL * 512, S128, 0, 0, 0);
    hmma_gemm<<<dim3(32, 1, 4), 256, 110592>>>(G + W_T2W2, G + G_T3B, res2,
                                               t2_b, nullptr, nullptr, nullptr,
                                               256, 4096, 0, 4096LL * 512, S128, 0, 0, 0);
    // 2-4. cosine, fused dif-split (into G_T3A), avgpool, attn operands
    cos_k<<<2048, 256>>>(res1, res2, sim);
    difsim_split_k<<<dim3(128, 4, 4), 256>>>(res1, res2, sim, G + G_T3A, absd);
    pool_k<<<2048, 256>>>(absd, simp);
    split2row_k<<<2048, 256>>>(simp, G + G_ATTN2);
    tsplit2_k<<<dim3(4, 32, 4), 256>>>(simp, G + G_ATTNT2, 1024, 128);
    // 5. r = stdconv 1x1 (256->128)
    hmma_gemm<<<dim3(32, 1, 4), 256, 110592>>>(G + W_RESW2, G + G_T3A, rbuf,
                                               df_res_b, df_res_s, df_res_o, nullptr,
                                               256, 4096, 0, 4096LL * 512, S128, 0, 0, 0);
    // 6/7. inception branches over shared rbuf-split
    tsplit2_k<<<dim3(128, 4, 4), 256>>>(rbuf, G + G_RB2, 128, 4096);
    hconv_tap<3, 64><<<dim3(32, 1, 4), 256, 104448>>>(
        G + W_B0T, G + G_RB2, b0b1, df_b0_b, df_b0_s, df_b0_o, S128);
    hconv_tap<5, 64><<<dim3(32, 1, 4), 256, 104448>>>(
        G + W_B1T, G + G_RB2, b0b1 + 64LL * 4096, df_b1_b, df_b1_s, df_b1_o, S128);
    // 8. dif = stdconv 1x1 (128->128) + r
    tsplit2_k<<<dim3(128, 4, 4), 256>>>(b0b1, G + G_BB2, 128, 4096);
    hmma_gemm<<<dim3(32, 1, 4), 256, 110592>>>(G + W_DFUW2, G + G_BB2, dif,
                                               df_fu_b, df_fu_s, df_fu_o, rbuf,
                                               128, 4096, 0, 4096LL * 256, S128, S128, 0, 0);
    tsplit2_k<<<dim3(128, 4, 4), 256>>>(dif, G + G_DIF2, 128, 4096);
    // --- attention, branch-merged: z = b*2 + br ---
    // both convs write inc[z]: br0 -> z even, br1 -> z odd
    hconv_tap<3, 128><<<dim3(32, 1, 4), 256, 139264>>>(
        G + W_BR1T, G + G_DIF2, inc, br1_b, nullptr, nullptr, 2 * S128);
    hconv_tap<5, 128><<<dim3(32, 1, 4), 256, 139264>>>(
        G + W_BR2T, G + G_DIF2, inc + S128, br2_b, nullptr, nullptr, 2 * S128);
    // merged transpose-split of inc (z = 8)
    tsplit2_k<<<dim3(128, 4, 8), 256>>>(inc, G + G_INCT2, 128, 4096);
    // merged logit GEMM: A = incT2 (z), B = attn2 (z>>1)
    hmma_gemm<<<dim3(8, 32, 8), 256, 110592>>>(G + G_INCT2, G + G_ATTN2, logitsT,
                                               nullptr, nullptr, nullptr, nullptr,
                                               128, 1024,
                                               4096LL * 256, 1024LL * 256,
                                               4096LL * 1024, 0, 0, 1);
    // merged column softmax (z = 8)
    colsoftmax_k<<<dim3(16, 8), 1024>>>(logitsT, G + G_AT2);
    // merged AV GEMM: A = attnT2 (z>>1), B = aT2 (z), C = acat + z*S128, resid inc[z]
    hmma_gemm<<<dim3(32, 1, 8), 256, 110592>>>(G + G_ATTNT2, G + G_AT2, acat,
                                               nullptr, nullptr, nullptr, inc,
                                               1024, 4096,
                                               128LL * 2048, 4096LL * 2048,
                                               S128, S128, 1, 0);
    // 14. fused = stdconv 1x1 (256->128) + dif
    tsplit2_k<<<dim3(128, 8, 4), 256>>>(acat, G + G_T3A, 256, 4096);
    hmma_gemm<<<dim3(32, 1, 4), 256, 110592>>>(G + W_FUW2, G + G_T3A, fuse,
                                               fu_b, fu_s, fu_o, dif,
                                               256, 4096, 0, 4096LL * 512, S128, S128, 0, 0);
    // 15. bilinear x2 upsample
    resize_k<<<32768, 256>>>(fuse, out);
}

// round 16
// speedup vs baseline: 1.5475x; 1.0103x over previous
#include <cuda_runtime.h>
#include <cuda_bf16.h>
#include <cstdint>

// ===========================================================================
// B=4, C_IN=256, C=128, H=W=64, HW=4096. out [4,128,128,128] f32.
// ALL dense ops on mma.sync bf16 HMMA, 2-term split (storage [hi|lo],
// 3-segment schedule). Convs = per-tap shifted GEMMs, k-chunk 128, 2-stage.
// Round 16: res GEMMs merged (z=8), t1/t2 splits merged, pool emits attn2.
// ===========================================================================

#define F_RES1 0LL
#define F_RES2 (F_RES1 + 2097152)
#define F_SIM  (F_RES2 + 2097152)
#define F_ABSD (F_SIM  + 16384)
#define F_SIMP (F_ABSD + 2097152)
#define F_R    (F_SIMP + 524288)
#define F_B0B1 (F_R    + 2097152)
#define F_DIF  (F_B0B1 + 2097152)
#define F_INC  (F_DIF  + 2097152)      /* [8][128*4096] z = b*2+br */
#define F_LOG  (F_INC  + 4194304)      /* [8][4096][1024]          */
#define F_ACAT (F_LOG  + 33554432)
#define F_FUSE (F_ACAT + 4194304)
#define F_BCAT (F_FUSE + 2097152)      /* concat bias [256]        */
#define F_TOTAL (F_BCAT + 256)

__device__ float g_scratch[F_TOTAL];

// bf16 scratch element offsets (2-segment layouts)
#define W_T1W2   0LL          /* [128,512]  (T1W2 || T2W2 contiguous) */
#define W_T2W2   65536LL
#define W_RESW2  131072LL
#define W_FUW2   196608LL
#define W_DFUW2  262144LL     /* [128,256]        */
#define W_B0T    294912LL     /* [9][64][256]     */
#define W_B1T    442368LL     /* [25][64][256]    */
#define W_BR1T   851968LL     /* [9][128][256]    */
#define W_BR2T   1146880LL    /* [25][128][256]   */
#define G_ATTN2  1966080LL    /* [4,1024,256]     */
#define G_INCT2  3014656LL    /* [8,4096,256]     */
#define G_ATTNT2 11403264LL   /* [4,128,2048]     */
#define G_AT2    12451840LL   /* [8,4096,2048]    */
#define G_T3A    79560704LL   /* [4,4096,512]  (T3A || T3B contiguous) */
#define G_T3B    87949312LL   /* [4,4096,512]     */
#define G_RB2    96337920LL   /* [4,4096,256]     */
#define G_DIF2   100532224LL  /* [4,4096,256]     */
#define G_BB2    104726528LL  /* [4,4096,256]     */
#define G_TOTAL  108920832LL

__device__ __align__(256) __nv_bfloat16 g_bf[G_TOTAL];

// ------------------------------ helpers ------------------------------------
__device__ __forceinline__ uint32_t smem_u32(const void* p) {
    uint32_t a;
    asm("{ .reg .u64 t; cvta.to.shared.u64 t, %1; cvt.u32.u64 %0, t; }"
        : "=r"(a) : "l"(p));
    return a;
}
__device__ __forceinline__ void bsplit(float x, __nv_bfloat16& h, __nv_bfloat16& l) {
    h = __float2bfloat16(x);
    l = __float2bfloat16(x - __bfloat162float(h));
}
#define CP_ASYNC(dst, src) asm volatile( \
    "cp.async.cg.shared.global [%0], [%1], 16;" :: "r"(dst), "l"(src))
#define CP_ASYNC_Z(dst, src, sz) asm volatile( \
    "cp.async.cg.shared.global [%0], [%1], 16, %2;" :: "r"(dst), "l"(src), "r"(sz))
#define CP_COMMIT() asm volatile("cp.async.commit_group;" ::: "memory")
#define CP_WAIT1()  asm volatile("cp.async.wait_group 1;" ::: "memory")
#define CP_WAIT0()  asm volatile("cp.async.wait_group 0;" ::: "memory")
#define LDM_X4(r0, r1, r2, r3, a) asm volatile( \
    "ldmatrix.sync.aligned.m8n8.x4.shared.b16 {%0,%1,%2,%3}, [%4];" \
    : "=r"(r0), "=r"(r1), "=r"(r2), "=r"(r3) : "r"(a))
#define MMA16816(d, a, bfr) asm volatile( \
    "mma.sync.aligned.m16n8k16.row.col.f32.bf16.bf16.f32 " \
    "{%0,%1,%2,%3}, {%4,%5,%6,%7}, {%8,%9}, {%0,%1,%2,%3};" \
    : "+f"((d)[0]), "+f"((d)[1]), "+f"((d)[2]), "+f"((d)[3]) \
    : "r"((a)[0]), "r"((a)[1]), "r"((a)[2]), "r"((a)[3]), \
      "r"((bfr)[0]), "r"((bfr)[1]))

// ===========================================================================
// hmma_gemm: 128x128 tile, 8 warps (32m x 64n), chunk k=64, 3-stage cp.async.
// A batch = z >> azshift; B batch = z >> bzshift; C/resid use z directly.
// bias index = (z >> azshift) * biasstride + m.
// Row stride 144B. dyn smem = 110592.
// ===========================================================================
__global__ void __launch_bounds__(256) hmma_gemm(
    const __nv_bfloat16* __restrict__ A2, const __nv_bfloat16* __restrict__ B2,
    float* __restrict__ C,
    const float* __restrict__ bias, const float* __restrict__ scale,
    const float* __restrict__ off, const float* __restrict__ resid,
    int Kcore, int Ncols,
    long long Abs, long long Bbs, long long Cbs, long long Rbs,
    int azshift, int bzshift, int biasstride)
{
    extern __shared__ __align__(16) char smbuf[];
    const uint32_t sA = smem_u32(smbuf);          // 3 stages x 18432
    const uint32_t sB = sA + 55296;               // 3 stages x 18432
    const int t = threadIdx.x, lane = t & 31, wid = t >> 5;
    const int wm = wid & 3, wn = wid >> 2;
    const int z  = blockIdx.z;
    const int m0 = blockIdx.y * 128;
    const int n0 = blockIdx.x * 128;
    const int Kp = 2 * Kcore;
    const __nv_bfloat16* Ab = A2 + (long long)(z >> azshift) * Abs + (long long)m0 * Kp;
    const __nv_bfloat16* Bb = B2 + (long long)(z >> bzshift) * Bbs + (long long)n0 * Kp;
    const int boff = (z >> azshift) * biasstride;

    float acc[2][8][4];
#pragma unroll
    for (int i = 0; i < 2; i++)
#pragma unroll
        for (int j = 0; j < 8; j++)
#pragma unroll
            for (int r = 0; r < 4; r++) acc[i][j][r] = 0.f;

    const int nchseg = Kcore >> 6;
    auto ldch = [&](int gc) {
        const int seg = (gc >= nchseg) + (gc >= 2 * nchseg);
        const int cc  = gc - seg * nchseg;
        const int aco = (seg == 1 ? Kcore : 0) + cc * 64;
        const int bco = (seg == 2 ? Kcore : 0) + cc * 64;
        const uint32_t ao = sA + (gc % 3) * 18432;
        const uint32_t bo = sB + (gc % 3) * 18432;
#pragma unroll
        for (int r = 0; r < 4; r++) {
            int f = t + 256 * r, row = f >> 3, kq = f & 7;
            CP_ASYNC(ao + (uint32_t)(row * 144 + kq * 16),
                     Ab + (long long)row * Kp + aco + kq * 8);
            CP_ASYNC(bo + (uint32_t)(row * 144 + kq * 16),
                     Bb + (long long)row * Kp + bco + kq * 8);
        }
        CP_COMMIT();
    };

    const int NC = 3 * nchseg;
    ldch(0);
    ldch(1);
    for (int gc = 0; gc < NC; gc++) {
        if (gc + 1 < NC) CP_WAIT1(); else CP_WAIT0();
        __syncthreads();
        if (gc + 2 < NC) ldch(gc + 2);
        const uint32_t ao = sA + (gc % 3) * 18432;
        const uint32_t bo = sB + (gc % 3) * 18432;
#pragma unroll
        for (int ks = 0; ks < 4; ks++) {
            const int kb = ks * 16;
            uint32_t af[2][4];
#pragma unroll
            for (int i = 0; i < 2; i++) {
                int row = wm * 32 + i * 16 + (lane & 7) + ((lane >> 3) & 1) * 8;
                int col = kb + ((lane >> 4) & 1) * 8;
                LDM_X4(af[i][0], af[i][1], af[i][2], af[i][3],
                       ao + (uint32_t)(row * 144 + col * 2));
            }
            uint32_t bfr[8][2];
#pragma unroll
            for (int jp = 0; jp < 4; jp++) {
                int n = wn * 64 + jp * 16 + (lane & 7) + ((lane >> 4) & 1) * 8;
                int k = kb + ((lane >> 3) & 1) * 8;
                LDM_X4(bfr[2 * jp][0], bfr[2 * jp][1],
                       bfr[2 * jp + 1][0], bfr[2 * jp + 1][1],
                       bo + (uint32_t)(n * 144 + k * 2));
            }
#pragma unroll
            for (int i = 0; i < 2; i++)
#pragma unroll
                for (int j = 0; j < 8; j++)
                    MMA16816(acc[i][j], af[i], bfr[j]);
        }
    }

    float* Cb = C + (long long)z * Cbs;
    const float* Rb = resid ? resid + (long long)z * Rbs : nullptr;
#pragma unroll
    for (int i = 0; i < 2; i++)
#pragma unroll
        for (int h = 0; h < 2; h++) {
            int m = m0 + wm * 32 + i * 16 + (lane >> 2) + h * 8;
            float bi = bias  ? bias[boff + m] : 0.f;
            float sc = scale ? scale[m] : 1.f;
            float ofv = off  ? off[m]   : 0.f;
            float* crow = Cb + (long long)m * Ncols;
            const float* rrow = Rb ? Rb + (long long)m * Ncols : nullptr;
#pragma unroll
            for (int j = 0; j < 8; j++) {
                int col = n0 + wn * 64 + j * 8 + (lane & 3) * 2;
                float2 v = make_float2(acc[i][j][h * 2 + 0] + bi,
                                       acc[i][j][h * 2 + 1] + bi);
                if (scale) {
                    v.x = fmaxf(v.x, 0.f) * sc + ofv;
                    v.y = fmaxf(v.y, 0.f) * sc + ofv;
                }
                if (rrow) {
                    float2 rv = *(const float2*)(rrow + col);
                    v.x += rv.x; v.y += rv.y;
                }
                *(float2*)(crow + col) = v;
            }
        }
}

// ===========================================================================
// hconv_tap: conv KSxKS (pad KS/2) as per-tap shifted GEMMs, Kcore=128/tap.
// k-chunk 128 (one segment per chunk), 2-stage, row stride 272B.
// ===========================================================================
template <int KS, int MT>
__global__ void __launch_bounds__(256) hconv_tap(
    const __nv_bfloat16* __restrict__ W2t, const __nv_bfloat16* __restrict__ Bsplit,
    float* __restrict__ out,
    const float* __restrict__ bias, const float* __restrict__ scale,
    const float* __restrict__ off, long long out_bstride)
{
    constexpr int P    = KS / 2;
    constexpr int TAPS = KS * KS;
    constexpr int NC   = TAPS * 3;
    constexpr int WM_N = MT / 32;
    constexpr int WN_N = 8 / WM_N;
    constexpr int NJ   = 128 / (WN_N * 8);
    constexpr int ASTG = MT * 272;
    extern __shared__ __align__(16) char smbuf[];
    const uint32_t sA = smem_u32(smbuf);
    const uint32_t sB = sA + 2 * ASTG;
    const int t = threadIdx.x, lane = t & 31, wid = t >> 5;
    const int wm = wid % WM_N, wn = wid / WM_N;
    const int b  = blockIdx.z;
    const int n0 = blockIdx.x * 128;
    const __nv_bfloat16* Bb = Bsplit + (long long)b * (4096LL * 256);

    float acc[2][NJ][4];
#pragma unroll
    for (int i = 0; i < 2; i++)
#pragma unroll
        for (int j = 0; j < NJ; j++)
#pragma unroll
            for (int r = 0; r < 4; r++) acc[i][j][r] = 0.f;

    auto ldch = [&](int gc) {
        const int tap = gc / 3;
        const int seg = gc - tap * 3;
        const int aco = (seg == 1 ? 128 : 0);
        const int bco = (seg == 2 ? 128 : 0);
        const int dy  = tap / KS - P, dx = tap - (tap / KS) * KS - P;
        const int shift = dy * 64 + dx;
        const uint32_t ao = sA + (gc & 1) * ASTG;
        const uint32_t bo = sB + (gc & 1) * 34816;
#pragma unroll
        for (int r = 0; r < MT / 16; r++) {
            int f = t + 256 * r, row = f >> 4, kq = f & 15;
            CP_ASYNC(ao + (uint32_t)(row * 272 + kq * 16),
                     W2t + (long long)tap * (MT * 256) + (long long)row * 256
                         + aco + kq * 8);
        }
#pragma unroll
        for (int r = 0; r < 8; r++) {
            int f = t + 256 * r, row = f >> 4, kq = f & 15;
            int gpix = n0 + row;
            int y = gpix >> 6, x = gpix & 63;
            bool ok = ((unsigned)(y + dy) < 64u) && ((unsigned)(x + dx) < 64u);
            int spix = ok ? (gpix + shift) : 0;
            uint32_t sz = ok ? 16u : 0u;
            CP_ASYNC_Z(bo + (uint32_t)(row * 272 + kq * 16),
                       Bb + (long long)spix * 256 + bco + kq * 8, sz);
        }
        CP_COMMIT();
    };

    ldch(0);
    for (int gc = 0; gc < NC; gc++) {
        CP_WAIT0();
        __syncthreads();
        if (gc + 1 < NC) ldch(gc + 1);
        const uint32_t ao = sA + (gc & 1) * ASTG;
        const uint32_t bo = sB + (gc & 1) * 34816;
#pragma unroll
        for (int ks = 0; ks < 8; ks++) {
            const int kb = ks * 16;
            uint32_t af[2][4];
#pragma unroll
            for (int i = 0; i < 2; i++) {
                int row = wm * 32 + i * 16 + (lane & 7) + ((lane >> 3) & 1) * 8;
                int col = kb + ((lane >> 4) & 1) * 8;
                LDM_X4(af[i][0], af[i][1], af[i][2], af[i][3],
                       ao + (uint32_t)(row * 272 + col * 2));
            }
            uint32_t bfr[NJ][2];
#pragma unroll
            for (int jp = 0; jp < NJ / 2; jp++) {
                int n = wn * (NJ * 8) + jp * 16 + (lane & 7) + ((lane >> 4) & 1) * 8;
                int k = kb + ((lane >> 3) & 1) * 8;
                LDM_X4(bfr[2 * jp][0], bfr[2 * jp][1],
                       bfr[2 * jp + 1][0], bfr[2 * jp + 1][1],
                       bo + (uint32_t)(n * 272 + k * 2));
            }
#pragma unroll
            for (int i = 0; i < 2; i++)
#pragma unroll
                for (int j = 0; j < NJ; j++)
                    MMA16816(acc[i][j], af[i], bfr[j]);
        }
    }

    float* Ob = out + (long long)b * out_bstride;
#pragma unroll
    for (int i = 0; i < 2; i++)
#pragma unroll
        for (int h = 0; h < 2; h++) {
            int m = wm * 32 + i * 16 + (lane >> 2) + h * 8;
            float bi = bias[m];
            float sc = scale ? scale[m] : 1.f;
            float ofv = off ? off[m] : 0.f;
            float* crow = Ob + (long long)m * 4096;
#pragma unroll
            for (int j = 0; j < NJ; j++) {
                int col = n0 + wn * (NJ * 8) + j * 8 + (lane & 3) * 2;
                float2 v = make_float2(acc[i][j][h * 2 + 0] + bi,
                                       acc[i][j][h * 2 + 1] + bi);
                if (scale) {
                    v.x = fmaxf(v.x, 0.f) * sc + ofv;
                    v.y = fmaxf(v.y, 0.f) * sc + ofv;
                }
                *(float2*)(crow + col) = v;
            }
        }
}

// ===========================================================================
// prep kernels (2-segment [hi|lo])
// ===========================================================================
// five 1x1 weight splits + bias concat. grid (128, 6).
__global__ void wsplit5_k(const float* s0, const float* s1, const float* s2,
                          const float* s3, const float* s4,
                          __nv_bfloat16* d0, __nv_bfloat16* d1, __nv_bfloat16* d2,
                          __nv_bfloat16* d3, __nv_bfloat16* d4,
                          const float* tb1, const float* tb2, float* bcat)
{
    const int seg = blockIdx.y;
    if (seg == 5) {
        int i = blockIdx.x * 256 + threadIdx.x;
        if (i < 256) bcat[i] = (i < 128) ? tb1[i] : tb2[i - 128];
        return;
    }
    const float* src; __nv_bfloat16* dst; int K, total;
    switch (seg) {
        case 0: src = s0; dst = d0; K = 256; total = 32768; break;
        case 1: src = s1; dst = d1; K = 256; total = 32768; break;
        case 2: src = s2; dst = d2; K = 256; total = 32768; break;
        case 3: src = s3; dst = d3; K = 256; total = 32768; break;
        default: src = s4; dst = d4; K = 128; total = 16384; break;
    }
    int i = blockIdx.x * 256 + threadIdx.x;
    if (i >= total) return;
    int m = i / K, k = i - m * K;
    __nv_bfloat16 h, l; bsplit(src[i], h, l);
    __nv_bfloat16* o = dst + (long long)m * 2 * K + k;
    o[0] = h; o[K] = l;
}

__global__ void wsplit_tap4_k(const float* w0, const float* w1,
                              const float* w2, const float* w3,
                              __nv_bfloat16* d0, __nv_bfloat16* d1,
                              __nv_bfloat16* d2, __nv_bfloat16* d3)
{
    const int seg = blockIdx.y;
    const float* src; __nv_bfloat16* dst; int Cout, KS2, total;
    switch (seg) {
        case 0: src = w0; dst = d0; Cout = 64;  KS2 = 9;  total = 73728;  break;
        case 1: src = w1; dst = d1; Cout = 64;  KS2 = 25; total = 204800; break;
        case 2: src = w2; dst = d2; Cout = 128; KS2 = 9;  total = 147456; break;
        default: src = w3; dst = d3; Cout = 128; KS2 = 25; total = 409600; break;
    }
    int i = blockIdx.x * 256 + threadIdx.x;
    if (i >= total) return;
    int co = i / (128 * KS2);
    int rem = i - co * 128 * KS2;
    int ci = rem / KS2;
    int tap = rem - ci * KS2;
    __nv_bfloat16 h, l; bsplit(src[i], h, l);
    __nv_bfloat16* o = dst + (long long)tap * Cout * 256 + (long long)co * 256 + ci;
    o[0] = h; o[128] = l;
}

// transpose+split: in [Z,R,Ncol] f32 -> out [Z,Ncol,2R] bf16 (hi|lo)
__global__ void tsplit2_k(const float* __restrict__ in, __nv_bfloat16* __restrict__ out,
                          int R, int Ncol)
{
    __shared__ float tile[32][33];
    const int b = blockIdx.z, r0 = blockIdx.y * 32, n0 = blockIdx.x * 32;
    const int tx = threadIdx.x & 31, ty = threadIdx.x >> 5;
    const float* ib = in + (long long)b * R * Ncol;
#pragma unroll
    for (int p = 0; p < 4; p++)
        tile[ty + 8 * p][tx] = ib[(long long)(r0 + ty + 8 * p) * Ncol + n0 + tx];
    __syncthreads();
    __nv_bfloat16* ob = out + (long long)b * Ncol * 2 * R;
#pragma unroll
    for (int p = 0; p < 4; p++) {
        int n = n0 + ty + 8 * p, r = r0 + tx;
        float x = tile[tx][ty + 8 * p];
        __nv_bfloat16 h, l; bsplit(x, h, l);
        __nv_bfloat16* o = ob + (long long)n * 2 * R;
        o[r] = h; o[R + r] = l;
    }
}

// merged t1/t2 transpose+split: z=0..7, src = z<4 ? s0(batch z) : s1(batch z-4)
__global__ void tsplit2b_k(const float* __restrict__ s0, const float* __restrict__ s1,
                           __nv_bfloat16* __restrict__ out, int R, int Ncol)
{
    __shared__ float tile[32][33];
    const int zz = blockIdx.z;
    const int b = zz & 3;
    const float* in = (zz < 4) ? s0 : s1;
    const int r0 = blockIdx.y * 32, n0 = blockIdx.x * 32;
    const int tx = threadIdx.x & 31, ty = threadIdx.x >> 5;
    const float* ib = in + (long long)b * R * Ncol;
#pragma unroll
    for (int p = 0; p < 4; p++)
        tile[ty + 8 * p][tx] = ib[(long long)(r0 + ty + 8 * p) * Ncol + n0 + tx];
    __syncthreads();
    __nv_bfloat16* ob = out + (long long)zz * Ncol * 2 * R;
#pragma unroll
    for (int p = 0; p < 4; p++) {
        int n = n0 + ty + 8 * p, r = r0 + tx;
        float x = tile[tx][ty + 8 * p];
        __nv_bfloat16 h, l; bsplit(x, h, l);
        __nv_bfloat16* o = ob + (long long)n * 2 * R;
        o[r] = h; o[R + r] = l;
    }
}

// fused difsim: absd f32 AND difcat split operand [B,4096,512] (hi(256)|lo(256))
__global__ void difsim_split_k(const float* __restrict__ r1, const float* __restrict__ r2,
                               const float* __restrict__ sim,
                               __nv_bfloat16* __restrict__ dsplit,
                               float* __restrict__ absd)
{
    __shared__ float f1s[32][33], f2s[32][33], d1s[32][33], d2s[32][33], ss[32];
    const int b  = blockIdx.z;
    const int c0 = blockIdx.y * 32;
    const int n0 = blockIdx.x * 32;
    const int t  = threadIdx.x;
    const int tx = t & 31, ty = t >> 5;
    const long long BS = 524288;
    const float* r1b = r1 + (long long)b * BS;
    const float* r2b = r2 + (long long)b * BS;
#pragma unroll
    for (int r = 0; r < 4; r++) {
        int n = ty + 8 * r;
        f1s[n][tx] = r1b[(long long)(n0 + n) * 128 + c0 + tx];
        f2s[n][tx] = r2b[(long long)(n0 + n) * 128 + c0 + tx];
    }
    if (t < 32) ss[t] = sim[b * 4096 + n0 + t];
    __syncthreads();
#pragma unroll
    for (int r = 0; r < 4; r++) {
        int cl = ty + 8 * r;
        int c = c0 + cl;
        int n = n0 + tx;
        float rv1 = r1b[(long long)c * 4096 + n];
        float rv2 = r2b[(long long)c * 4096 + n];
        float s  = ss[tx];
        float f1 = f1s[tx][cl];
        float f2 = f2s[tx][cl];
        float omns = 1.f - s;
        d1s[cl][tx] = f1 * omns + rv1;
        d2s[cl][tx] = f2 * omns + rv2;
        absd[(long long)b * BS + (long long)c * 4096 + n] =
            fabsf((f1 - f2) * s + rv1 - rv2);
    }
    __syncthreads();
#pragma unroll
    for (int p = 0; p < 4; p++) {
        int nl = ty + 8 * p;
        float d1 = d1s[tx][nl];
        float d2 = d2s[tx][nl];
        __nv_bfloat16 h1, l1, h2, l2;
        bsplit(d1, h1, l1);
        bsplit(d2, h2, l2);
        __nv_bfloat16* orow = dsplit + (long long)b * (4096LL * 512)
                            + (long long)(n0 + nl) * 512;
        orow[c0 + tx]       = h1;
        orow[128 + c0 + tx] = h2;
        orow[256 + c0 + tx] = l1;
        orow[384 + c0 + tx] = l2;
    }
}

// fused column softmax over logitsT [Z,4096,1024] -> aT2 [Z,4096,2048] (hi|lo)
__global__ void colsoftmax_k(const float* __restrict__ lt,
                             __nv_bfloat16* __restrict__ out)
{
    __shared__ float smx[16][65], ssm[16][65];
    __shared__ float cmx[64], csi[64];
    const int z = blockIdx.y;
    const int c = threadIdx.x & 63, g = threadIdx.x >> 6;
    const int col = blockIdx.x * 64 + c;
    const float* p = lt + (long long)z * 4194304 + col;
    float mx = -1e30f, sm = 0.f;
    for (int m = g; m < 4096; m += 16) {
        float x = p[(long long)m * 1024];
        float nm = fmaxf(mx, x);
        sm = sm * __expf(mx - nm) + __expf(x - nm);
        mx = nm;
    }
    smx[g][c] = mx; ssm[g][c] = sm;
    __syncthreads();
    if (g == 0) {
        float MX = smx[0][c], SM = ssm[0][c];
#pragma unroll
        for (int k = 1; k < 16; k++) {
            float m2 = smx[k][c], s2 = ssm[k][c];
            float nm = fmaxf(MX, m2);
            SM = SM * __expf(MX - nm) + s2 * __expf(m2 - nm);
            MX = nm;
        }
        cmx[c] = MX;
        csi[c] = 1.f / SM;
    }
    __syncthreads();
    const float MX = cmx[c], SI = csi[c];
    __nv_bfloat16* ob = out + (long long)z * (4096LL * 2048) + col;
    for (int m = g; m < 4096; m += 16) {
        float e = __expf(p[(long long)m * 1024] - MX) * SI;
        __nv_bfloat16 h, l; bsplit(e, h, l);
        ob[(long long)m * 2048]        = h;
        ob[(long long)m * 2048 + 1024] = l;
    }
}

// ===========================================================================
// scalar auxiliary kernels
// ===========================================================================
__global__ void cos_k(const float* __restrict__ r1, const float* __restrict__ r2,
                      float* __restrict__ sim)
{
    int gid  = blockIdx.x * blockDim.x + threadIdx.x;
    int wid  = gid >> 5;
    int lane = gid & 31;
    if (wid >= 4 * 4096) return;
    const float* a = r1 + (long long)wid * 128;
    const float* c = r2 + (long long)wid * 128;
    float dot = 0.f, na = 0.f, nb = 0.f;
#pragma unroll
    for (int i = 0; i < 4; i++) {
        float x = a[lane + 32 * i], y = c[lane + 32 * i];
        dot += x * y; na += x * x; nb += y * y;
    }
#pragma unroll
    for (int o = 16; o; o >>= 1) {
        dot += __shfl_xor_sync(0xffffffffu, dot, o);
        na  += __shfl_xor_sync(0xffffffffu, na,  o);
        nb  += __shfl_xor_sync(0xffffffffu, nb,  o);
    }
    if (lane == 0)
        sim[wid] = dot / fmaxf(sqrtf(na) * sqrtf(nb), 1e-8f);
}

// avgpool + attn2 row split (pool output element i == split2row input i)
__global__ void pool_k(const float* __restrict__ absd, float* __restrict__ simp,
                       __nv_bfloat16* __restrict__ attn2)
{
    int i = blockIdx.x * 256 + threadIdx.x;
    if (i >= 524288) return;
    int wp = i & 31, hp = (i >> 5) & 31, bc = i >> 10;
    const float* a = absd + (long long)bc * 4096 + (hp * 2) * 64 + wp * 2;
    float v = 0.25f * (a[0] + a[1] + a[64] + a[65]);
    simp[i] = v;
    __nv_bfloat16 h, l; bsplit(v, h, l);
    long long row = i >> 7; int c = i & 127;
    __nv_bfloat16* o = attn2 + row * 256 + c;
    o[0] = h; o[128] = l;
}

__global__ void resize_k(const float* __restrict__ in, float* __restrict__ out)
{
    long long i = (long long)blockIdx.x * 256 + threadIdx.x;
    if (i >= 8388608LL) return;
    int x = (int)(i & 127), y = (int)((i >> 7) & 127);
    long long bc = i >> 14;
    float sx = (x + 0.5f) * 0.5f - 0.5f;
    float sy = (y + 0.5f) * 0.5f - 0.5f;
    int x0 = (int)floorf(sx), y0 = (int)floorf(sy);
    float fx = sx - x0, fy = sy - y0;
    int x1 = min(x0 + 1, 63), y1 = min(y0 + 1, 63);
    x0 = max(x0, 0); y0 = max(y0, 0);
    const float* p = in + bc * 4096;
    float v = (1.f - fy) * ((1.f - fx) * p[y0 * 64 + x0] + fx * p[y0 * 64 + x1])
            +        fy  * ((1.f - fx) * p[y1 * 64 + x0] + fx * p[y1 * 64 + x1]);
    out[i] = v;
}

// ---------------------------------------------------------------------------
extern "C" void kernel_launch(void* const* d_in, const int* in_sizes, int n_in,
                              void* d_out, int out_size)
{
    (void)in_sizes; (void)n_in; (void)out_size;
    const float* t1      = (const float*)d_in[0];
    const float* t2      = (const float*)d_in[1];
    const float* t1_w    = (const float*)d_in[2];
    const float* t1_b    = (const float*)d_in[3];
    const float* t2_w    = (const float*)d_in[4];
    const float* t2_b    = (const float*)d_in[5];
    const float* df_res_w = (const float*)d_in[6];
    const float* df_res_b = (const float*)d_in[7];
    const float* df_res_s = (const float*)d_in[8];
    const float* df_res_o = (const float*)d_in[9];
    const float* df_b0_w = (const float*)d_in[10];
    const float* df_b0_b = (const float*)d_in[11];
    const float* df_b0_s = (const float*)d_in[12];
    const float* df_b0_o = (const float*)d_in[13];
    const float* df_b1_w = (const float*)d_in[14];
    const float* df_b1_b = (const float*)d_in[15];
    const float* df_b1_s = (const float*)d_in[16];
    const float* df_b1_o = (const float*)d_in[17];
    const float* df_fu_w = (const float*)d_in[18];
    const float* df_fu_b = (const float*)d_in[19];
    const float* df_fu_s = (const float*)d_in[20];
    const float* df_fu_o = (const float*)d_in[21];
    const float* br1_w   = (const float*)d_in[22];
    const float* br1_b   = (const float*)d_in[23];
    const float* br2_w   = (const float*)d_in[24];
    const float* br2_b   = (const float*)d_in[25];
    const float* fu_w    = (const float*)d_in[26];
    const float* fu_b    = (const float*)d_in[27];
    const float* fu_s    = (const float*)d_in[28];
    const float* fu_o    = (const float*)d_in[29];
    float* out = (float*)d_out;

    float* S;
    cudaGetSymbolAddress((void**)&S, g_scratch);
    __nv_bfloat16* G;
    cudaGetSymbolAddress((void**)&G, g_bf);

    cudaFuncSetAttribute(hmma_gemm, cudaFuncAttributeMaxDynamicSharedMemorySize, 110592);
    cudaFuncSetAttribute(hconv_tap<3, 64>,  cudaFuncAttributeMaxDynamicSharedMemorySize, 104448);
    cudaFuncSetAttribute(hconv_tap<5, 64>,  cudaFuncAttributeMaxDynamicSharedMemorySize, 104448);
    cudaFuncSetAttribute(hconv_tap<3, 128>, cudaFuncAttributeMaxDynamicSharedMemorySize, 139264);
    cudaFuncSetAttribute(hconv_tap<5, 128>, cudaFuncAttributeMaxDynamicSharedMemorySize, 139264);

    float* res1    = S + F_RES1;
    float* res2    = S + F_RES2;
    float* sim     = S + F_SIM;
    float* absd    = S + F_ABSD;
    float* simp    = S + F_SIMP;
    float* rbuf    = S + F_R;
    float* b0b1    = S + F_B0B1;
    float* dif     = S + F_DIF;
    float* inc     = S + F_INC;     // [8][128*4096], z = b*2 + br
    float* logitsT = S + F_LOG;     // [8][4096*1024]
    float* acat    = S + F_ACAT;
    float* fuse    = S + F_FUSE;
    float* bcat    = S + F_BCAT;

    const long long S128 = 128LL * 4096;

    // weight splits + bias concat (merged)
    wsplit5_k<<<dim3(128, 6), 256>>>(t1_w, t2_w, df_res_w, fu_w, df_fu_w,
                                     G + W_T1W2, G + W_T2W2, G + W_RESW2,
                                     G + W_FUW2, G + W_DFUW2,
                                     t1_b, t2_b, bcat);
    wsplit_tap4_k<<<dim3(1600, 4), 256>>>(df_b0_w, df_b1_w, br1_w, br2_w,
                                          G + W_B0T, G + W_B1T,
                                          G + W_BR1T, G + W_BR2T);
    // merged t1/t2 input splits (z = 8, outputs contiguous T3A||T3B)
    tsplit2b_k<<<dim3(128, 8, 8), 256>>>(t1, t2, G + G_T3A, 256, 4096);
    // 1. merged res1/res2 GEMM (z = 8): A = z>>2 weight block, B = z input block
    hmma_gemm<<<dim3(32, 1, 8), 256, 110592>>>(G + W_T1W2, G + G_T3A, res1,
                                               bcat, nullptr, nullptr, nullptr,
                                               256, 4096, 65536LL, 4096LL * 512,
                                               S128, 0, 2, 0, 128);
    // 2-4. cosine, fused dif-split (into G_T3A), pool (+attn2 split)
    cos_k<<<2048, 256>>>(res1, res2, sim);
    difsim_split_k<<<dim3(128, 4, 4), 256>>>(res1, res2, sim, G + G_T3A, absd);
    pool_k<<<2048, 256>>>(absd, simp, G + G_ATTN2);
    tsplit2_k<<<dim3(4, 32, 4), 256>>>(simp, G + G_ATTNT2, 1024, 128);
    // 5. r = stdconv 1x1 (256->128)
    hmma_gemm<<<dim3(32, 1, 4), 256, 110592>>>(G + W_RESW2, G + G_T3A, rbuf,
                                               df_res_b, df_res_s, df_res_o, nullptr,
                                               256, 4096, 0, 4096LL * 512, S128, 0, 0, 0, 0);
    // 6/7. inception branches over shared rbuf-split
    tsplit2_k<<<dim3(128, 4, 4), 256>>>(rbuf, G + G_RB2, 128, 4096);
    hconv_tap<3, 64><<<dim3(32, 1, 4), 256, 104448>>>(
        G + W_B0T, G + G_RB2, b0b1, df_b0_b, df_b0_s, df_b0_o, S128);
    hconv_tap<5, 64><<<dim3(32, 1, 4), 256, 104448>>>(
        G + W_B1T, G + G_RB2, b0b1 + 64LL * 4096, df_b1_b, df_b1_s, df_b1_o, S128);
    // 8. dif = stdconv 1x1 (128->128) + r
    tsplit2_k<<<dim3(128, 4, 4), 256>>>(b0b1, G + G_BB2, 128, 4096);
    hmma_gemm<<<dim3(32, 1, 4), 256, 110592>>>(G + W_DFUW2, G + G_BB2, dif,
                                               df_fu_b, df_fu_s, df_fu_o, rbuf,
                                               128, 4096, 0, 4096LL * 256, S128, S128, 0, 0, 0);
    tsplit2_k<<<dim3(128, 4, 4), 256>>>(dif, G + G_DIF2, 128, 4096);
    // --- attention, branch-merged: z = b*2 + br ---
    hconv_tap<3, 128><<<dim3(32, 1, 4), 256, 139264>>>(
        G + W_BR1T, G + G_DIF2, inc, br1_b, nullptr, nullptr, 2 * S128);
    hconv_tap<5, 128><<<dim3(32, 1, 4), 256, 139264>>>(
        G + W_BR2T, G + G_DIF2, inc + S128, br2_b, nullptr, nullptr, 2 * S128);
    tsplit2_k<<<dim3(128, 4, 8), 256>>>(inc, G + G_INCT2, 128, 4096);
    // merged logit GEMM: A = incT2 (z), B = attn2 (z>>1)
    hmma_gemm<<<dim3(8, 32, 8), 256, 110592>>>(G + G_INCT2, G + G_ATTN2, logitsT,
                                               nullptr, nullptr, nullptr, nullptr,
                                               128, 1024,
                                               4096LL * 256, 1024LL * 256,
                                               4096LL * 1024, 0, 0, 1, 0);
    colsoftmax_k<<<dim3(16, 8), 1024>>>(logitsT, G + G_AT2);
    // merged AV GEMM: A = attnT2 (z>>1), B = aT2 (z), C = acat + z*S128, resid inc[z]
    hmma_gemm<<<dim3(32, 1, 8), 256, 110592>>>(G + G_ATTNT2, G + G_AT2, acat,
                                               nullptr, nullptr, nullptr, inc,
                                               1024, 4096,
                                               128LL * 2048, 4096LL * 2048,
                                               S128, S128, 1, 0, 0);
    // 14. fused = stdconv 1x1 (256->128) + dif
    tsplit2_k<<<dim3(128, 8, 4), 256>>>(acat, G + G_T3A, 256, 4096);
    hmma_gemm<<<dim3(32, 1, 4), 256, 110592>>>(G + W_FUW2, G + G_T3A, fuse,
                                               fu_b, fu_s, fu_o, dif,
                                               256, 4096, 0, 4096LL * 512, S128, S128, 0, 0, 0);
    // 15. bilinear x2 upsample
    resize_k<<<32768, 256>>>(fuse, out);
}

// round 17
// speedup vs baseline: 1.6034x; 1.0361x over previous
#include <cuda_runtime.h>
#include <cuda_bf16.h>
#include <cstdint>

// ===========================================================================
// B=4, C_IN=256, C=128, H=W=64, HW=4096. out [4,128,128,128] f32.
// ALL dense ops on mma.sync bf16 HMMA, 2-term split (storage [hi|lo],
// 3-segment schedule). Convs = per-tap shifted GEMMs, k-chunk 128, 2-stage.
// Round 17: 2 CTAs/SM on all dense kernels (launch_bounds(256,2); conv N-tile 64).
// ===========================================================================

#define F_RES1 0LL
#define F_RES2 (F_RES1 + 2097152)
#define F_SIM  (F_RES2 + 2097152)
#define F_ABSD (F_SIM  + 16384)
#define F_SIMP (F_ABSD + 2097152)
#define F_R    (F_SIMP + 524288)
#define F_B0B1 (F_R    + 2097152)
#define F_DIF  (F_B0B1 + 2097152)
#define F_INC  (F_DIF  + 2097152)      /* [8][128*4096] z = b*2+br */
#define F_LOG  (F_INC  + 4194304)      /* [8][4096][1024]          */
#define F_ACAT (F_LOG  + 33554432)
#define F_FUSE (F_ACAT + 4194304)
#define F_BCAT (F_FUSE + 2097152)      /* concat bias [256]        */
#define F_TOTAL (F_BCAT + 256)

__device__ float g_scratch[F_TOTAL];

// bf16 scratch element offsets (2-segment layouts)
#define W_T1W2   0LL          /* [128,512]  (T1W2 || T2W2 contiguous) */
#define W_T2W2   65536LL
#define W_RESW2  131072LL
#define W_FUW2   196608LL
#define W_DFUW2  262144LL     /* [128,256]        */
#define W_B0T    294912LL     /* [9][64][256]     */
#define W_B1T    442368LL     /* [25][64][256]    */
#define W_BR1T   851968LL     /* [9][128][256]    */
#define W_BR2T   1146880LL    /* [25][128][256]   */
#define G_ATTN2  1966080LL    /* [4,1024,256]     */
#define G_INCT2  3014656LL    /* [8,4096,256]     */
#define G_ATTNT2 11403264LL   /* [4,128,2048]     */
#define G_AT2    12451840LL   /* [8,4096,2048]    */
#define G_T3A    79560704LL   /* [4,4096,512]  (T3A || T3B contiguous) */
#define G_T3B    87949312LL   /* [4,4096,512]     */
#define G_RB2    96337920LL   /* [4,4096,256]     */
#define G_DIF2   100532224LL  /* [4,4096,256]     */
#define G_BB2    104726528LL  /* [4,4096,256]     */
#define G_TOTAL  108920832LL

__device__ __align__(256) __nv_bfloat16 g_bf[G_TOTAL];

// ------------------------------ helpers ------------------------------------
__device__ __forceinline__ uint32_t smem_u32(const void* p) {
    uint32_t a;
    asm("{ .reg .u64 t; cvta.to.shared.u64 t, %1; cvt.u32.u64 %0, t; }"
        : "=r"(a) : "l"(p));
    return a;
}
__device__ __forceinline__ void bsplit(float x, __nv_bfloat16& h, __nv_bfloat16& l) {
    h = __float2bfloat16(x);
    l = __float2bfloat16(x - __bfloat162float(h));
}
#define CP_ASYNC(dst, src) asm volatile( \
    "cp.async.cg.shared.global [%0], [%1], 16;" :: "r"(dst), "l"(src))
#define CP_ASYNC_Z(dst, src, sz) asm volatile( \
    "cp.async.cg.shared.global [%0], [%1], 16, %2;" :: "r"(dst), "l"(src), "r"(sz))
#define CP_COMMIT() asm volatile("cp.async.commit_group;" ::: "memory")
#define CP_WAIT1()  asm volatile("cp.async.wait_group 1;" ::: "memory")
#define CP_WAIT0()  asm volatile("cp.async.wait_group 0;" ::: "memory")
#define LDM_X4(r0, r1, r2, r3, a) asm volatile( \
    "ldmatrix.sync.aligned.m8n8.x4.shared.b16 {%0,%1,%2,%3}, [%4];" \
    : "=r"(r0), "=r"(r1), "=r"(r2), "=r"(r3) : "r"(a))
#define MMA16816(d, a, bfr) asm volatile( \
    "mma.sync.aligned.m16n8k16.row.col.f32.bf16.bf16.f32 " \
    "{%0,%1,%2,%3}, {%4,%5,%6,%7}, {%8,%9}, {%0,%1,%2,%3};" \
    : "+f"((d)[0]), "+f"((d)[1]), "+f"((d)[2]), "+f"((d)[3]) \
    : "r"((a)[0]), "r"((a)[1]), "r"((a)[2]), "r"((a)[3]), \
      "r"((bfr)[0]), "r"((bfr)[1]))

// ===========================================================================
// hmma_gemm: 128x128 tile, 8 warps (32m x 64n), chunk k=64, 3-stage cp.async.
// launch_bounds(256,2) -> <=128 regs -> 2 CTAs/SM (smem 110592*2 fits 228KB).
// A batch = z >> azshift; B batch = z >> bzshift; bias idx = (z>>azshift)*bs+m.
// ===========================================================================
__global__ void __launch_bounds__(256, 2) hmma_gemm(
    const __nv_bfloat16* __restrict__ A2, const __nv_bfloat16* __restrict__ B2,
    float* __restrict__ C,
    const float* __restrict__ bias, const float* __restrict__ scale,
    const float* __restrict__ off, const float* __restrict__ resid,
    int Kcore, int Ncols,
    long long Abs, long long Bbs, long long Cbs, long long Rbs,
    int azshift, int bzshift, int biasstride)
{
    extern __shared__ __align__(16) char smbuf[];
    const uint32_t sA = smem_u32(smbuf);          // 3 stages x 18432
    const uint32_t sB = sA + 55296;               // 3 stages x 18432
    const int t = threadIdx.x, lane = t & 31, wid = t >> 5;
    const int wm = wid & 3, wn = wid >> 2;
    const int z  = blockIdx.z;
    const int m0 = blockIdx.y * 128;
    const int n0 = blockIdx.x * 128;
    const int Kp = 2 * Kcore;
    const __nv_bfloat16* Ab = A2 + (long long)(z >> azshift) * Abs + (long long)m0 * Kp;
    const __nv_bfloat16* Bb = B2 + (long long)(z >> bzshift) * Bbs + (long long)n0 * Kp;
    const int boff = (z >> azshift) * biasstride;

    float acc[2][8][4];
#pragma unroll
    for (int i = 0; i < 2; i++)
#pragma unroll
        for (int j = 0; j < 8; j++)
#pragma unroll
            for (int r = 0; r < 4; r++) acc[i][j][r] = 0.f;

    const int nchseg = Kcore >> 6;
    auto ldch = [&](int gc) {
        const int seg = (gc >= nchseg) + (gc >= 2 * nchseg);
        const int cc  = gc - seg * nchseg;
        const int aco = (seg == 1 ? Kcore : 0) + cc * 64;
        const int bco = (seg == 2 ? Kcore : 0) + cc * 64;
        const uint32_t ao = sA + (gc % 3) * 18432;
        const uint32_t bo = sB + (gc % 3) * 18432;
#pragma unroll
        for (int r = 0; r < 4; r++) {
            int f = t + 256 * r, row = f >> 3, kq = f & 7;
            CP_ASYNC(ao + (uint32_t)(row * 144 + kq * 16),
                     Ab + (long long)row * Kp + aco + kq * 8);
            CP_ASYNC(bo + (uint32_t)(row * 144 + kq * 16),
                     Bb + (long long)row * Kp + bco + kq * 8);
        }
        CP_COMMIT();
    };

    const int NC = 3 * nchseg;
    ldch(0);
    ldch(1);
    for (int gc = 0; gc < NC; gc++) {
        if (gc + 1 < NC) CP_WAIT1(); else CP_WAIT0();
        __syncthreads();
        if (gc + 2 < NC) ldch(gc + 2);
        const uint32_t ao = sA + (gc % 3) * 18432;
        const uint32_t bo = sB + (gc % 3) * 18432;
#pragma unroll
        for (int ks = 0; ks < 4; ks++) {
            const int kb = ks * 16;
            uint32_t af[2][4];
#pragma unroll
            for (int i = 0; i < 2; i++) {
                int row = wm * 32 + i * 16 + (lane & 7) + ((lane >> 3) & 1) * 8;
                int col = kb + ((lane >> 4) & 1) * 8;
                LDM_X4(af[i][0], af[i][1], af[i][2], af[i][3],
                       ao + (uint32_t)(row * 144 + col * 2));
            }
            uint32_t bfr[8][2];
#pragma unroll
            for (int jp = 0; jp < 4; jp++) {
                int n = wn * 64 + jp * 16 + (lane & 7) + ((lane >> 4) & 1) * 8;
                int k = kb + ((lane >> 3) & 1) * 8;
                LDM_X4(bfr[2 * jp][0], bfr[2 * jp][1],
                       bfr[2 * jp + 1][0], bfr[2 * jp + 1][1],
                       bo + (uint32_t)(n * 144 + k * 2));
            }
#pragma unroll
            for (int i = 0; i < 2; i++)
#pragma unroll
                for (int j = 0; j < 8; j++)
                    MMA16816(acc[i][j], af[i], bfr[j]);
        }
    }

    float* Cb = C + (long long)z * Cbs;
    const float* Rb = resid ? resid + (long long)z * Rbs : nullptr;
#pragma unroll
    for (int i = 0; i < 2; i++)
#pragma unroll
        for (int h = 0; h < 2; h++) {
            int m = m0 + wm * 32 + i * 16 + (lane >> 2) + h * 8;
            float bi = bias  ? bias[boff + m] : 0.f;
            float sc = scale ? scale[m] : 1.f;
            float ofv = off  ? off[m]   : 0.f;
            float* crow = Cb + (long long)m * Ncols;
            const float* rrow = Rb ? Rb + (long long)m * Ncols : nullptr;
#pragma unroll
            for (int j = 0; j < 8; j++) {
                int col = n0 + wn * 64 + j * 8 + (lane & 3) * 2;
                float2 v = make_float2(acc[i][j][h * 2 + 0] + bi,
                                       acc[i][j][h * 2 + 1] + bi);
                if (scale) {
                    v.x = fmaxf(v.x, 0.f) * sc + ofv;
                    v.y = fmaxf(v.y, 0.f) * sc + ofv;
                }
                if (rrow) {
                    float2 rv = *(const float2*)(rrow + col);
                    v.x += rv.x; v.y += rv.y;
                }
                *(float2*)(crow + col) = v;
            }
        }
}

// ===========================================================================
// hconv_tap: conv KSxKS (pad KS/2) as per-tap shifted GEMMs, Kcore=128/tap.
// Tile MT x NT (NT=64 -> grid 256 CTAs, 2 CTAs/SM). k-chunk 128, 2-stage.
// Row stride 272B. dyn smem = 2*(MT+NT)*272.
// ===========================================================================
template <int KS, int MT, int NT>
__global__ void __launch_bounds__(256, 2) hconv_tap(
    const __nv_bfloat16* __restrict__ W2t, const __nv_bfloat16* __restrict__ Bsplit,
    float* __restrict__ out,
    const float* __restrict__ bias, const float* __restrict__ scale,
    const float* __restrict__ off, long long out_bstride)
{
    constexpr int P    = KS / 2;
    constexpr int TAPS = KS * KS;
    constexpr int NC   = TAPS * 3;
    constexpr int WM_N = MT / 32;
    constexpr int WN_N = 8 / WM_N;
    constexpr int NJ   = NT / (WN_N * 8);
    constexpr int ASTG = MT * 272;
    constexpr int BSTG = NT * 272;
    extern __shared__ __align__(16) char smbuf[];
    const uint32_t sA = smem_u32(smbuf);
    const uint32_t sB = sA + 2 * ASTG;
    const int t = threadIdx.x, lane = t & 31, wid = t >> 5;
    const int wm = wid % WM_N, wn = wid / WM_N;
    const int b  = blockIdx.z;
    const int n0 = blockIdx.x * NT;
    const __nv_bfloat16* Bb = Bsplit + (long long)b * (4096LL * 256);

    float acc[2][NJ][4];
#pragma unroll
    for (int i = 0; i < 2; i++)
#pragma unroll
        for (int j = 0; j < NJ; j++)
#pragma unroll
            for (int r = 0; r < 4; r++) acc[i][j][r] = 0.f;

    auto ldch = [&](int gc) {
        const int tap = gc / 3;
        const int seg = gc - tap * 3;
        const int aco = (seg == 1 ? 128 : 0);
        const int bco = (seg == 2 ? 128 : 0);
        const int dy  = tap / KS - P, dx = tap - (tap / KS) * KS - P;
        const int shift = dy * 64 + dx;
        const uint32_t ao = sA + (gc & 1) * ASTG;
        const uint32_t bo = sB + (gc & 1) * BSTG;
#pragma unroll
        for (int r = 0; r < MT / 16; r++) {
            int f = t + 256 * r, row = f >> 4, kq = f & 15;
            CP_ASYNC(ao + (uint32_t)(row * 272 + kq * 16),
                     W2t + (long long)tap * (MT * 256) + (long long)row * 256
                         + aco + kq * 8);
        }
#pragma unroll
        for (int r = 0; r < NT / 16; r++) {
            int f = t + 256 * r, row = f >> 4, kq = f & 15;
            int gpix = n0 + row;
            int y = gpix >> 6, x = gpix & 63;
            bool ok = ((unsigned)(y + dy) < 64u) && ((unsigned)(x + dx) < 64u);
            int spix = ok ? (gpix + shift) : 0;
            uint32_t sz = ok ? 16u : 0u;
            CP_ASYNC_Z(bo + (uint32_t)(row * 272 + kq * 16),
                       Bb + (long long)spix * 256 + bco + kq * 8, sz);
        }
        CP_COMMIT();
    };

    ldch(0);
    for (int gc = 0; gc < NC; gc++) {
        CP_WAIT0();
        __syncthreads();
        if (gc + 1 < NC) ldch(gc + 1);
        const uint32_t ao = sA + (gc & 1) * ASTG;
        const uint32_t bo = sB + (gc & 1) * BSTG;
#pragma unroll
        for (int ks = 0; ks < 8; ks++) {
            const int kb = ks * 16;
            uint32_t af[2][4];
#pragma unroll
            for (int i = 0; i < 2; i++) {
                int row = wm * 32 + i * 16 + (lane & 7) + ((lane >> 3) & 1) * 8;
                int col = kb + ((lane >> 4) & 1) * 8;
                LDM_X4(af[i][0], af[i][1], af[i][2], af[i][3],
                       ao + (uint32_t)(row * 272 + col * 2));
            }
            uint32_t bfr[NJ][2];
#pragma unroll
            for (int jp = 0; jp < NJ / 2; jp++) {
                int n = wn * (NJ * 8) + jp * 16 + (lane & 7) + ((lane >> 4) & 1) * 8;
                int k = kb + ((lane >> 3) & 1) * 8;
                LDM_X4(bfr[2 * jp][0], bfr[2 * jp][1],
                       bfr[2 * jp + 1][0], bfr[2 * jp + 1][1],
                       bo + (uint32_t)(n * 272 + k * 2));
            }
#pragma unroll
            for (int i = 0; i < 2; i++)
#pragma unroll
                for (int j = 0; j < NJ; j++)
                    MMA16816(acc[i][j], af[i], bfr[j]);
        }
    }

    float* Ob = out + (long long)b * out_bstride;
#pragma unroll
    for (int i = 0; i < 2; i++)
#pragma unroll
        for (int h = 0; h < 2; h++) {
            int m = wm * 32 + i * 16 + (lane >> 2) + h * 8;
            float bi = bias[m];
            float sc = scale ? scale[m] : 1.f;
            float ofv = off ? off[m] : 0.f;
            float* crow = Ob + (long long)m * 4096;
#pragma unroll
            for (int j = 0; j < NJ; j++) {
                int col = n0 + wn * (NJ * 8) + j * 8 + (lane & 3) * 2;
                float2 v = make_float2(acc[i][j][h * 2 + 0] + bi,
                                       acc[i][j][h * 2 + 1] + bi);
                if (scale) {
                    v.x = fmaxf(v.x, 0.f) * sc + ofv;
                    v.y = fmaxf(v.y, 0.f) * sc + ofv;
                }
                *(float2*)(crow + col) = v;
            }
        }
}

// ===========================================================================
// prep kernels (2-segment [hi|lo])
// ===========================================================================
__global__ void wsplit5_k(const float* s0, const float* s1, const float* s2,
                          const float* s3, const float* s4,
                          __nv_bfloat16* d0, __nv_bfloat16* d1, __nv_bfloat16* d2,
                          __nv_bfloat16* d3, __nv_bfloat16* d4,
                          const float* tb1, const float* tb2, float* bcat)
{
    const int seg = blockIdx.y;
    if (seg == 5) {
        int i = blockIdx.x * 256 + threadIdx.x;
        if (i < 256) bcat[i] = (i < 128) ? tb1[i] : tb2[i - 128];
        return;
    }
    const float* src; __nv_bfloat16* dst; int K, total;
    switch (seg) {
        case 0: src = s0; dst = d0; K = 256; total = 32768; break;
        case 1: src = s1; dst = d1; K = 256; total = 32768; break;
        case 2: src = s2; dst = d2; K = 256; total = 32768; break;
        case 3: src = s3; dst = d3; K = 256; total = 32768; break;
        default: src = s4; dst = d4; K = 128; total = 16384; break;
    }
    int i = blockIdx.x * 256 + threadIdx.x;
    if (i >= total) return;
    int m = i / K, k = i - m * K;
    __nv_bfloat16 h, l; bsplit(src[i], h, l);
    __nv_bfloat16* o = dst + (long long)m * 2 * K + k;
    o[0] = h; o[K] = l;
}

__global__ void wsplit_tap4_k(const float* w0, const float* w1,
                              const float* w2, const float* w3,
                              __nv_bfloat16* d0, __nv_bfloat16* d1,
                              __nv_bfloat16* d2, __nv_bfloat16* d3)
{
    const int seg = blockIdx.y;
    const float* src; __nv_bfloat16* dst; int Cout, KS2, total;
    switch (seg) {
        case 0: src = w0; dst = d0; Cout = 64;  KS2 = 9;  total = 73728;  break;
        case 1: src = w1; dst = d1; Cout = 64;  KS2 = 25; total = 204800; break;
        case 2: src = w2; dst = d2; Cout = 128; KS2 = 9;  total = 147456; break;
        default: src = w3; dst = d3; Cout = 128; KS2 = 25; total = 409600; break;
    }
    int i = blockIdx.x * 256 + threadIdx.x;
    if (i >= total) return;
    int co = i / (128 * KS2);
    int rem = i - co * 128 * KS2;
    int ci = rem / KS2;
    int tap = rem - ci * KS2;
    __nv_bfloat16 h, l; bsplit(src[i], h, l);
    __nv_bfloat16* o = dst + (long long)tap * Cout * 256 + (long long)co * 256 + ci;
    o[0] = h; o[128] = l;
}

__global__ void tsplit2_k(const float* __restrict__ in, __nv_bfloat16* __restrict__ out,
                          int R, int Ncol)
{
    __shared__ float tile[32][33];
    const int b = blockIdx.z, r0 = blockIdx.y * 32, n0 = blockIdx.x * 32;
    const int tx = threadIdx.x & 31, ty = threadIdx.x >> 5;
    const float* ib = in + (long long)b * R * Ncol;
#pragma unroll
    for (int p = 0; p < 4; p++)
        tile[ty + 8 * p][tx] = ib[(long long)(r0 + ty + 8 * p) * Ncol + n0 + tx];
    __syncthreads();
    __nv_bfloat16* ob = out + (long long)b * Ncol * 2 * R;
#pragma unroll
    for (int p = 0; p < 4; p++) {
        int n = n0 + ty + 8 * p, r = r0 + tx;
        float x = tile[tx][ty + 8 * p];
        __nv_bfloat16 h, l; bsplit(x, h, l);
        __nv_bfloat16* o = ob + (long long)n * 2 * R;
        o[r] = h; o[R + r] = l;
    }
}

__global__ void tsplit2b_k(const float* __restrict__ s0, const float* __restrict__ s1,
                           __nv_bfloat16* __restrict__ out, int R, int Ncol)
{
    __shared__ float tile[32][33];
    const int zz = blockIdx.z;
    const int b = zz & 3;
    const float* in = (zz < 4) ? s0 : s1;
    const int r0 = blockIdx.y * 32, n0 = blockIdx.x * 32;
    const int tx = threadIdx.x & 31, ty = threadIdx.x >> 5;
    const float* ib = in + (long long)b * R * Ncol;
#pragma unroll
    for (int p = 0; p < 4; p++)
        tile[ty + 8 * p][tx] = ib[(long long)(r0 + ty + 8 * p) * Ncol + n0 + tx];
    __syncthreads();
    __nv_bfloat16* ob = out + (long long)zz * Ncol * 2 * R;
#pragma unroll
    for (int p = 0; p < 4; p++) {
        int n = n0 + ty + 8 * p, r = r0 + tx;
        float x = tile[tx][ty + 8 * p];
        __nv_bfloat16 h, l; bsplit(x, h, l);
        __nv_bfloat16* o = ob + (long long)n * 2 * R;
        o[r] = h; o[R + r] = l;
    }
}

__global__ void difsim_split_k(const float* __restrict__ r1, const float* __restrict__ r2,
                               const float* __restrict__ sim,
                               __nv_bfloat16* __restrict__ dsplit,
                               float* __restrict__ absd)
{
    __shared__ float f1s[32][33], f2s[32][33], d1s[32][33], d2s[32][33], ss[32];
    const int b  = blockIdx.z;
    const int c0 = blockIdx.y * 32;
    const int n0 = blockIdx.x * 32;
    const int t  = threadIdx.x;
    const int tx = t & 31, ty = t >> 5;
    const long long BS = 524288;
    const float* r1b = r1 + (long long)b * BS;
    const float* r2b = r2 + (long long)b * BS;
#pragma unroll
    for (int r = 0; r < 4; r++) {
        int n = ty + 8 * r;
        f1s[n][tx] = r1b[(long long)(n0 + n) * 128 + c0 + tx];
        f2s[n][tx] = r2b[(long long)(n0 + n) * 128 + c0 + tx];
    }
    if (t < 32) ss[t] = sim[b * 4096 + n0 + t];
    __syncthreads();
#pragma unroll
    for (int r = 0; r < 4; r++) {
        int cl = ty + 8 * r;
        int c = c0 + cl;
        int n = n0 + tx;
        float rv1 = r1b[(long long)c * 4096 + n];
        float rv2 = r2b[(long long)c * 4096 + n];
        float s  = ss[tx];
        float f1 = f1s[tx][cl];
        float f2 = f2s[tx][cl];
        float omns = 1.f - s;
        d1s[cl][tx] = f1 * omns + rv1;
        d2s[cl][tx] = f2 * omns + rv2;
        absd[(long long)b * BS + (long long)c * 4096 + n] =
            fabsf((f1 - f2) * s + rv1 - rv2);
    }
    __syncthreads();
#pragma unroll
    for (int p = 0; p < 4; p++) {
        int nl = ty + 8 * p;
        float d1 = d1s[tx][nl];
        float d2 = d2s[tx][nl];
        __nv_bfloat16 h1, l1, h2, l2;
        bsplit(d1, h1, l1);
        bsplit(d2, h2, l2);
        __nv_bfloat16* orow = dsplit + (long long)b * (4096LL * 512)
                            + (long long)(n0 + nl) * 512;
        orow[c0 + tx]       = h1;
        orow[128 + c0 + tx] = h2;
        orow[256 + c0 + tx] = l1;
        orow[384 + c0 + tx] = l2;
    }
}

__global__ void colsoftmax_k(const float* __restrict__ lt,
                             __nv_bfloat16* __restrict__ out)
{
    __shared__ float smx[16][65], ssm[16][65];
    __shared__ float cmx[64], csi[64];
    const int z = blockIdx.y;
    const int c = threadIdx.x & 63, g = threadIdx.x >> 6;
    const int col = blockIdx.x * 64 + c;
    const float* p = lt + (long long)z * 4194304 + col;
    float mx = -1e30f, sm = 0.f;
    for (int m = g; m < 4096; m += 16) {
        float x = p[(long long)m * 1024];
        float nm = fmaxf(mx, x);
        sm = sm * __expf(mx - nm) + __expf(x - nm);
        mx = nm;
    }
    smx[g][c] = mx; ssm[g][c] = sm;
    __syncthreads();
    if (g == 0) {
        float MX = smx[0][c], SM = ssm[0][c];
#pragma unroll
        for (int k = 1; k < 16; k++) {
            float m2 = smx[k][c], s2 = ssm[k][c];
            float nm = fmaxf(MX, m2);
            SM = SM * __expf(MX - nm) + s2 * __expf(m2 - nm);
            MX = nm;
        }
        cmx[c] = MX;
        csi[c] = 1.f / SM;
    }
    __syncthreads();
    const float MX = cmx[c], SI = csi[c];
    __nv_bfloat16* ob = out + (long long)z * (4096LL * 2048) + col;
    for (int m = g; m < 4096; m += 16) {
        float e = __expf(p[(long long)m * 1024] - MX) * SI;
        __nv_bfloat16 h, l; bsplit(e, h, l);
        ob[(long long)m * 2048]        = h;
        ob[(long long)m * 2048 + 1024] = l;
    }
}

// ===========================================================================
// scalar auxiliary kernels
// ===========================================================================
__global__ void cos_k(const float* __restrict__ r1, const float* __restrict__ r2,
                      float* __restrict__ sim)
{
    int gid  = blockIdx.x * blockDim.x + threadIdx.x;
    int wid  = gid >> 5;
    int lane = gid & 31;
    if (wid >= 4 * 4096) return;
    const float* a = r1 + (long long)wid * 128;
    const float* c = r2 + (long long)wid * 128;
    float dot = 0.f, na = 0.f, nb = 0.f;
#pragma unroll
    for (int i = 0; i < 4; i++) {
        float x = a[lane + 32 * i], y = c[lane + 32 * i];
        dot += x * y; na += x * x; nb += y * y;
    }
#pragma unroll
    for (int o = 16; o; o >>= 1) {
        dot += __shfl_xor_sync(0xffffffffu, dot, o);
        na  += __shfl_xor_sync(0xffffffffu, na,  o);
        nb  += __shfl_xor_sync(0xffffffffu, nb,  o);
    }
    if (lane == 0)
        sim[wid] = dot / fmaxf(sqrtf(na) * sqrtf(nb), 1e-8f);
}

__global__ void pool_k(const float* __restrict__ absd, float* __restrict__ simp,
                       __nv_bfloat16* __restrict__ attn2)
{
    int i = blockIdx.x * 256 + threadIdx.x;
    if (i >= 524288) return;
    int wp = i & 31, hp = (i >> 5) & 31, bc = i >> 10;
    const float* a = absd + (long long)bc * 4096 + (hp * 2) * 64 + wp * 2;
    float v = 0.25f * (a[0] + a[1] + a[64] + a[65]);
    simp[i] = v;
    __nv_bfloat16 h, l; bsplit(v, h, l);
    long long row = i >> 7; int c = i & 127;
    __nv_bfloat16* o = attn2 + row * 256 + c;
    o[0] = h; o[128] = l;
}

__global__ void resize_k(const float* __restrict__ in, float* __restrict__ out)
{
    long long i = (long long)blockIdx.x * 256 + threadIdx.x;
    if (i >= 8388608LL) return;
    int x = (int)(i & 127), y = (int)((i >> 7) & 127);
    long long bc = i >> 14;
    float sx = (x + 0.5f) * 0.5f - 0.5f;
    float sy = (y + 0.5f) * 0.5f - 0.5f;
    int x0 = (int)floorf(sx), y0 = (int)floorf(sy);
    float fx = sx - x0, fy = sy - y0;
    int x1 = min(x0 + 1, 63), y1 = min(y0 + 1, 63);
    x0 = max(x0, 0); y0 = max(y0, 0);
    const float* p = in + bc * 4096;
    float v = (1.f - fy) * ((1.f - fx) * p[y0 * 64 + x0] + fx * p[y0 * 64 + x1])
            +        fy  * ((1.f - fx) * p[y1 * 64 + x0] + fx * p[y1 * 64 + x1]);
    out[i] = v;
}

// ---------------------------------------------------------------------------
extern "C" void kernel_launch(void* const* d_in, const int* in_sizes, int n_in,
                              void* d_out, int out_size)
{
    (void)in_sizes; (void)n_in; (void)out_size;
    const float* t1      = (const float*)d_in[0];
    const float* t2      = (const float*)d_in[1];
    const float* t1_w    = (const float*)d_in[2];
    const float* t1_b    = (const float*)d_in[3];
    const float* t2_w    = (const float*)d_in[4];
    const float* t2_b    = (const float*)d_in[5];
    const float* df_res_w = (const float*)d_in[6];
    const float* df_res_b = (const float*)d_in[7];
    const float* df_res_s = (const float*)d_in[8];
    const float* df_res_o = (const float*)d_in[9];
    const float* df_b0_w = (const float*)d_in[10];
    const float* df_b0_b = (const float*)d_in[11];
    const float* df_b0_s = (const float*)d_in[12];
    const float* df_b0_o = (const float*)d_in[13];
    const float* df_b1_w = (const float*)d_in[14];
    const float* df_b1_b = (const float*)d_in[15];
    const float* df_b1_s = (const float*)d_in[16];
    const float* df_b1_o = (const float*)d_in[17];
    const float* df_fu_w = (const float*)d_in[18];
    const float* df_fu_b = (const float*)d_in[19];
    const float* df_fu_s = (const float*)d_in[20];
    const float* df_fu_o = (const float*)d_in[21];
    const float* br1_w   = (const float*)d_in[22];
    const float* br1_b   = (const float*)d_in[23];
    const float* br2_w   = (const float*)d_in[24];
    const float* br2_b   = (const float*)d_in[25];
    const float* fu_w    = (const float*)d_in[26];
    const float* fu_b    = (const float*)d_in[27];
    const float* fu_s    = (const float*)d_in[28];
    const float* fu_o    = (const float*)d_in[29];
    float* out = (float*)d_out;

    float* S;
    cudaGetSymbolAddress((void**)&S, g_scratch);
    __nv_bfloat16* G;
    cudaGetSymbolAddress((void**)&G, g_bf);

    cudaFuncSetAttribute(hmma_gemm, cudaFuncAttributeMaxDynamicSharedMemorySize, 110592);
    cudaFuncSetAttribute(hconv_tap<3, 64, 64>,  cudaFuncAttributeMaxDynamicSharedMemorySize, 69632);
    cudaFuncSetAttribute(hconv_tap<5, 64, 64>,  cudaFuncAttributeMaxDynamicSharedMemorySize, 69632);
    cudaFuncSetAttribute(hconv_tap<3, 128, 64>, cudaFuncAttributeMaxDynamicSharedMemorySize, 104448);
    cudaFuncSetAttribute(hconv_tap<5, 128, 64>, cudaFuncAttributeMaxDynamicSharedMemorySize, 104448);

    float* res1    = S + F_RES1;
    float* res2    = S + F_RES2;
    float* sim     = S + F_SIM;
    float* absd    = S + F_ABSD;
    float* simp    = S + F_SIMP;
    float* rbuf    = S + F_R;
    float* b0b1    = S + F_B0B1;
    float* dif     = S + F_DIF;
    float* inc     = S + F_INC;     // [8][128*4096], z = b*2 + br
    float* logitsT = S + F_LOG;     // [8][4096*1024]
    float* acat    = S + F_ACAT;
    float* fuse    = S + F_FUSE;
    float* bcat    = S + F_BCAT;

    const long long S128 = 128LL * 4096;

    // weight splits + bias concat (merged)
    wsplit5_k<<<dim3(128, 6), 256>>>(t1_w, t2_w, df_res_w, fu_w, df_fu_w,
                                     G + W_T1W2, G + W_T2W2, G + W_RESW2,
                                     G + W_FUW2, G + W_DFUW2,
                                     t1_b, t2_b, bcat);
    wsplit_tap4_k<<<dim3(1600, 4), 256>>>(df_b0_w, df_b1_w, br1_w, br2_w,
                                          G + W_B0T, G + W_B1T,
                                          G + W_BR1T, G + W_BR2T);
    // merged t1/t2 input splits (z = 8)
    tsplit2b_k<<<dim3(128, 8, 8), 256>>>(t1, t2, G + G_T3A, 256, 4096);
    // 1. merged res1/res2 GEMM (z = 8)
    hmma_gemm<<<dim3(32, 1, 8), 256, 110592>>>(G + W_T1W2, G + G_T3A, res1,
                                               bcat, nullptr, nullptr, nullptr,
                                               256, 4096, 65536LL, 4096LL * 512,
                                               S128, 0, 2, 0, 128);
    // 2-4. cosine, fused dif-split (into G_T3A), pool (+attn2 split)
    cos_k<<<2048, 256>>>(res1, res2, sim);
    difsim_split_k<<<dim3(128, 4, 4), 256>>>(res1, res2, sim, G + G_T3A, absd);
    pool_k<<<2048, 256>>>(absd, simp, G + G_ATTN2);
    tsplit2_k<<<dim3(4, 32, 4), 256>>>(simp, G + G_ATTNT2, 1024, 128);
    // 5. r = stdconv 1x1 (256->128)
    hmma_gemm<<<dim3(32, 1, 4), 256, 110592>>>(G + W_RESW2, G + G_T3A, rbuf,
                                               df_res_b, df_res_s, df_res_o, nullptr,
                                               256, 4096, 0, 4096LL * 512, S128, 0, 0, 0, 0);
    // 6/7. inception branches over shared rbuf-split (NT=64 -> 256 CTAs)
    tsplit2_k<<<dim3(128, 4, 4), 256>>>(rbuf, G + G_RB2, 128, 4096);
    hconv_tap<3, 64, 64><<<dim3(64, 1, 4), 256, 69632>>>(
        G + W_B0T, G + G_RB2, b0b1, df_b0_b, df_b0_s, df_b0_o, S128);
    hconv_tap<5, 64, 64><<<dim3(64, 1, 4), 256, 69632>>>(
        G + W_B1T, G + G_RB2, b0b1 + 64LL * 4096, df_b1_b, df_b1_s, df_b1_o, S128);
    // 8. dif = stdconv 1x1 (128->128) + r
    tsplit2_k<<<dim3(128, 4, 4), 256>>>(b0b1, G + G_BB2, 128, 4096);
    hmma_gemm<<<dim3(32, 1, 4), 256, 110592>>>(G + W_DFUW2, G + G_BB2, dif,
                                               df_fu_b, df_fu_s, df_fu_o, rbuf,
                                               128, 4096, 0, 4096LL * 256, S128, S128, 0, 0, 0);
    tsplit2_k<<<dim3(128, 4, 4), 256>>>(dif, G + G_DIF2, 128, 4096);
    // --- attention, branch-merged: z = b*2 + br ---
    hconv_tap<3, 128, 64><<<dim3(64, 1, 4), 256, 104448>>>(
        G + W_BR1T, G + G_DIF2, inc, br1_b, nullptr, nullptr, 2 * S128);
    hconv_tap<5, 128, 64><<<dim3(64, 1, 4), 256, 104448>>>(
        G + W_BR2T, G + G_DIF2, inc + S128, br2_b, nullptr, nullptr, 2 * S128);
    tsplit2_k<<<dim3(128, 4, 8), 256>>>(inc, G + G_INCT2, 128, 4096);
    // merged logit GEMM: A = incT2 (z), B = attn2 (z>>1)
    hmma_gemm<<<dim3(8, 32, 8), 256, 110592>>>(G + G_INCT2, G + G_ATTN2, logitsT,
                                               nullptr, nullptr, nullptr, nullptr,
                                               128, 1024,
                                               4096LL * 256, 1024LL * 256,
                                               4096LL * 1024, 0, 0, 1, 0);
    colsoftmax_k<<<dim3(16, 8), 1024>>>(logitsT, G + G_AT2);
    // merged AV GEMM: A = attnT2 (z>>1), B = aT2 (z), C = acat + z*S128, resid inc[z]
    hmma_gemm<<<dim3(32, 1, 8), 256, 110592>>>(G + G_ATTNT2, G + G_AT2, acat,
                                               nullptr, nullptr, nullptr, inc,
                                               1024, 4096,
                                               128LL * 2048, 4096LL * 2048,
                                               S128, S128, 1, 0, 0);
    // 14. fused = stdconv 1x1 (256->128) + dif
    tsplit2_k<<<dim3(128, 8, 4), 256>>>(acat, G + G_T3A, 256, 4096);
    hmma_gemm<<<dim3(32, 1, 4), 256, 110592>>>(G + W_FUW2, G + G_T3A, fuse,
                                               fu_b, fu_s, fu_o, dif,
                                               256, 4096, 0, 4096LL * 512, S128, S128, 0, 0, 0);
    // 15. bilinear x2 upsample
    resize_k<<<32768, 256>>>(fuse, out);
}